// round 7
// baseline (speedup 1.0000x reference)
#include <cuda_runtime.h>
#include <cuda_bf16.h>
#include <stdint.h>
#include <math.h>

#define B_ 8
#define M_ 2048
#define HD_ 512
#define BM_ (B_*M_)
#define SCALE_ 22.62741699796952f   // reference divides by HEAD_DIM**-0.5

typedef __nv_bfloat16 bf16;
typedef __nv_bfloat162 bf162;

// ---------------- device scratch (allocation-free rule) ----------------
__device__ __align__(16) bf16 g_Xh[(size_t)BM_*HD_], g_Xl[(size_t)BM_*HD_];
__device__ __align__(16) bf16 g_Qh[(size_t)BM_*HD_], g_Ql[(size_t)BM_*HD_];
__device__ __align__(16) bf16 g_Kh[(size_t)BM_*HD_], g_Kl[(size_t)BM_*HD_];
__device__ __align__(16) bf16 g_Vh[(size_t)BM_*HD_], g_Vl[(size_t)BM_*HD_];
__device__ __align__(16) bf16 g_Ch[(size_t)BM_*HD_], g_Cl[(size_t)BM_*HD_];
__device__ __align__(16) bf16 g_Wh[4][512*512], g_Wl[4][512*512];   // W^T: [n][k]

// ---------------- helpers ----------------
__device__ __forceinline__ uint32_t smem_u32(const void* p) {
    uint32_t a;
    asm("{ .reg .u64 t; cvta.to.shared.u64 t, %1; cvt.u32.u64 %0, t; }" : "=r"(a) : "l"(p));
    return a;
}
#define SWZ(x) ((uint32_t)(x) ^ ((((uint32_t)(x)) >> 3) & 0x70))

__device__ __forceinline__ void ldm4(uint32_t (&r)[4], uint32_t a) {
    asm volatile("ldmatrix.sync.aligned.m8n8.x4.shared.b16 {%0,%1,%2,%3}, [%4];"
                 : "=r"(r[0]), "=r"(r[1]), "=r"(r[2]), "=r"(r[3]) : "r"(a));
}
__device__ __forceinline__ void ldm4t(uint32_t (&r)[4], uint32_t a) {
    asm volatile("ldmatrix.sync.aligned.m8n8.x4.trans.shared.b16 {%0,%1,%2,%3}, [%4];"
                 : "=r"(r[0]), "=r"(r[1]), "=r"(r[2]), "=r"(r[3]) : "r"(a));
}
__device__ __forceinline__ void mma_bf(float (&d)[4], const uint32_t (&a)[4],
                                       uint32_t b0, uint32_t b1) {
    asm volatile("mma.sync.aligned.m16n8k16.row.col.f32.bf16.bf16.f32 "
                 "{%0,%1,%2,%3}, {%4,%5,%6,%7}, {%8,%9}, {%0,%1,%2,%3};"
                 : "+f"(d[0]), "+f"(d[1]), "+f"(d[2]), "+f"(d[3])
                 : "r"(a[0]), "r"(a[1]), "r"(a[2]), "r"(a[3]), "r"(b0), "r"(b1));
}
__device__ __forceinline__ void splitf(float x, bf16& h, bf16& l) {
    h = __float2bfloat16(x);
    l = __float2bfloat16(x - __bfloat162float(h));
}
__device__ __forceinline__ void cpa16(uint32_t dst, const void* src) {
    asm volatile("cp.async.cg.shared.global [%0], [%1], 16;" :: "r"(dst), "l"(src));
}
#define CP_COMMIT() asm volatile("cp.async.commit_group;" ::: "memory")
#define CP_WAIT0()  asm volatile("cp.async.wait_group 0;" ::: "memory")

// ---------------- prep kernels ----------------
__global__ void __launch_bounds__(512) prep_x(const float4* __restrict__ x,
                                              bf16* __restrict__ xh, bf16* __restrict__ xl) {
    size_t i = (size_t)blockIdx.x * 512 + threadIdx.x;
    float4 v = x[i];
    bf16 h0, l0, h1, l1, h2, l2, h3, l3;
    splitf(v.x, h0, l0); splitf(v.y, h1, l1);
    splitf(v.z, h2, l2); splitf(v.w, h3, l3);
    bf162 a, b, c, d;
    a.x = h0; a.y = h1; b.x = h2; b.y = h3;
    c.x = l0; c.y = l1; d.x = l2; d.y = l3;
    *(bf162*)(xh + i * 4) = a; *(bf162*)(xh + i * 4 + 2) = b;
    *(bf162*)(xl + i * 4) = c; *(bf162*)(xl + i * 4 + 2) = d;
}

// coalesced tile-transpose for all 4 weights: W[k][n] -> W^T[n][k] hi/lo
__global__ void __launch_bounds__(256) prep_w4(
    const float* __restrict__ W0, const float* __restrict__ W1,
    const float* __restrict__ W2, const float* __restrict__ W3,
    bf16* __restrict__ th, bf16* __restrict__ tl) {
    __shared__ float t[32][33];
    const int w = blockIdx.z;
    const float* W = (w == 0) ? W0 : (w == 1) ? W1 : (w == 2) ? W2 : W3;
    bf16* thw = th + (size_t)w * 262144;
    bf16* tlw = tl + (size_t)w * 262144;
    const int bx = blockIdx.x * 32;   // n-block
    const int by = blockIdx.y * 32;   // k-block
    const int tx = threadIdx.x, ty = threadIdx.y;
#pragma unroll
    for (int j = ty; j < 32; j += 8)
        t[j][tx] = W[(size_t)(by + j) * 512 + bx + tx];
    __syncthreads();
#pragma unroll
    for (int j = ty; j < 32; j += 8) {
        float v = t[tx][j];
        bf16 h, l; splitf(v, h, l);
        thw[(size_t)(bx + j) * 512 + by + tx] = h;
        tlw[(size_t)(bx + j) * 512 + by + tx] = l;
    }
}

// ===========================================================================
// GEMM via mma.sync, cp.async double-buffered.
// CTA 128x128, 8 warps (2x4), warp tile 64x32, split-bf16 3-pass.
// MODE 0 (fused QKV): blockIdx.x selects W/output. MODE 2: fp32 + bias.
// ===========================================================================
#define GS(c)   ((c) * 65536)
#define G_AH(c) (GS(c) + 0)
#define G_AL(c) (GS(c) + 16384)
#define G_BH(c) (GS(c) + 32768)
#define G_BL(c) (GS(c) + 49152)
#define G_SZ    131072

template <int MODE>
__global__ void __launch_bounds__(256, 1) gemm_mma(
    const bf16* __restrict__ Ah_, const bf16* __restrict__ Al_,
    const bf16* __restrict__ WhB, const bf16* __restrict__ WlB,
    const float* __restrict__ bias, float* __restrict__ out32,
    bf16* __restrict__ oh0, bf16* __restrict__ ol0,
    bf16* __restrict__ oh1, bf16* __restrict__ ol1,
    bf16* __restrict__ oh2, bf16* __restrict__ ol2)
{
    extern __shared__ char sm[];
    const uint32_t sb = smem_u32(sm);
    const int tid = threadIdx.x, warp = tid >> 5, lane = tid & 31;
    const int wm = warp >> 2, wn = warp & 3;
    const int lr = lane & 7, g = lane >> 3;
    const int offAr = (g & 1) * 8 + lr, offAc = (g >> 1) * 8;
    const int offBr = (g >> 1) * 8 + lr, offBc = (g & 1) * 8;

    const int widx = (MODE == 0) ? (blockIdx.x >> 2) : 0;    // which W / output
    const int n0 = (MODE == 0) ? ((blockIdx.x & 3) * 128) : (blockIdx.x * 128);
    const int m0 = blockIdx.y * 128;
    const bf16* Bh_ = WhB + (size_t)widx * 262144;
    const bf16* Bl_ = WlB + (size_t)widx * 262144;

    // prologue: chunk 0
#pragma unroll
    for (int i = 0; i < 4; i++) {
        int t = i * 256 + tid, row = t >> 3, cb = (t & 7) * 16;
        uint32_t dsw = SWZ(row * 128 + cb);
        size_t abyte = ((size_t)(m0 + row) * 512) * 2 + cb;
        size_t bbyte = ((size_t)(n0 + row) * 512) * 2 + cb;
        cpa16(sb + G_AH(0) + dsw, (const char*)Ah_ + abyte);
        cpa16(sb + G_AL(0) + dsw, (const char*)Al_ + abyte);
        cpa16(sb + G_BH(0) + dsw, (const char*)Bh_ + bbyte);
        cpa16(sb + G_BL(0) + dsw, (const char*)Bl_ + bbyte);
    }
    CP_COMMIT();

    float acc[4][4][4];
#pragma unroll
    for (int a = 0; a < 4; a++)
#pragma unroll
        for (int b = 0; b < 4; b++)
#pragma unroll
            for (int c = 0; c < 4; c++) acc[a][b][c] = 0.0f;

    for (int ch = 0; ch < 8; ch++) {
        const int c = ch & 1;
        CP_WAIT0();
        __syncthreads();          // buf c ready; all warps done with buf c^1

        if (ch < 7) {             // prefetch ch+1 into buf c^1
#pragma unroll
            for (int i = 0; i < 4; i++) {
                int t = i * 256 + tid, row = t >> 3, cb = (t & 7) * 16;
                uint32_t dsw = SWZ(row * 128 + cb);
                size_t abyte = ((size_t)(m0 + row) * 512 + (ch + 1) * 64) * 2 + cb;
                size_t bbyte = ((size_t)(n0 + row) * 512 + (ch + 1) * 64) * 2 + cb;
                cpa16(sb + G_AH(c ^ 1) + dsw, (const char*)Ah_ + abyte);
                cpa16(sb + G_AL(c ^ 1) + dsw, (const char*)Al_ + abyte);
                cpa16(sb + G_BH(c ^ 1) + dsw, (const char*)Bh_ + bbyte);
                cpa16(sb + G_BL(c ^ 1) + dsw, (const char*)Bl_ + bbyte);
            }
            CP_COMMIT();
        }

#pragma unroll
        for (int ks = 0; ks < 4; ks++) {
            uint32_t bhF[2][4], blF[2][4];
#pragma unroll
            for (int np = 0; np < 2; np++) {
                uint32_t boff = SWZ((wn * 32 + np * 16 + offBr) * 128 + (ks * 16 + offBc) * 2);
                ldm4(bhF[np], sb + G_BH(c) + boff);
                ldm4(blF[np], sb + G_BL(c) + boff);
            }
#pragma unroll
            for (int mf = 0; mf < 4; mf++) {
                uint32_t aoff = SWZ((wm * 64 + mf * 16 + offAr) * 128 + (ks * 16 + offAc) * 2);
                uint32_t ah2[4], al2[4];
                ldm4(ah2, sb + G_AH(c) + aoff);
                ldm4(al2, sb + G_AL(c) + aoff);
#pragma unroll
                for (int nf = 0; nf < 4; nf++) {
                    int np = nf >> 1, hh = nf & 1;
                    uint32_t b0h = bhF[np][hh * 2], b1h = bhF[np][hh * 2 + 1];
                    uint32_t b0l = blF[np][hh * 2], b1l = blF[np][hh * 2 + 1];
                    mma_bf(acc[mf][nf], ah2, b0h, b1h);
                    mma_bf(acc[mf][nf], ah2, b0l, b1l);
                    mma_bf(acc[mf][nf], al2, b0h, b1h);
                }
            }
        }
    }

    bf16* oh = (MODE == 0) ? ((widx == 0) ? oh0 : (widx == 1) ? oh1 : oh2) : oh0;
    bf16* ol = (MODE == 0) ? ((widx == 0) ? ol0 : (widx == 1) ? ol1 : ol2) : ol0;

#pragma unroll
    for (int mf = 0; mf < 4; mf++) {
        int rlo = m0 + wm * 64 + mf * 16 + (lane >> 2);
        int rhi = rlo + 8;
#pragma unroll
        for (int nf = 0; nf < 4; nf++) {
            int n = n0 + wn * 32 + nf * 8 + (lane & 3) * 2;
            if (MODE == 2) {
                float2 v0, v1;
                v0.x = acc[mf][nf][0] + bias[n]; v0.y = acc[mf][nf][1] + bias[n + 1];
                v1.x = acc[mf][nf][2] + bias[n]; v1.y = acc[mf][nf][3] + bias[n + 1];
                *(float2*)(out32 + (size_t)rlo * 512 + n) = v0;
                *(float2*)(out32 + (size_t)rhi * 512 + n) = v1;
            } else {
                int h = n >> 6, d = n & 63;
                {
                    int b = rlo >> 11, mm = rlo & 2047;
                    size_t base = ((size_t)(b * 8 + h) * 2048 + mm) * 64 + d;
                    bf16 h0, l0, h1, l1;
                    splitf(acc[mf][nf][0], h0, l0); splitf(acc[mf][nf][1], h1, l1);
                    bf162 t, u; t.x = h0; t.y = h1; u.x = l0; u.y = l1;
                    *(bf162*)(oh + base) = t; *(bf162*)(ol + base) = u;
                }
                {
                    int b = rhi >> 11, mm = rhi & 2047;
                    size_t base = ((size_t)(b * 8 + h) * 2048 + mm) * 64 + d;
                    bf16 h0, l0, h1, l1;
                    splitf(acc[mf][nf][2], h0, l0); splitf(acc[mf][nf][3], h1, l1);
                    bf162 t, u; t.x = h0; t.y = h1; u.x = l0; u.y = l1;
                    *(bf162*)(oh + base) = t; *(bf162*)(ol + base) = u;
                }
            }
        }
    }
}

// ===========================================================================
// Flash attention via mma.sync, 64-key tiles, cp.async double-buffered K/V.
// CTA = (128-q tile, b*h). 512 threads, 16 warps (4 wm x 4 wn), warp tile 32x16.
// PV is 2-pass (Ph*Vh + Ph*Vl): p_max = 1.0 is exact in bf16 and softmax is
// near-one-hot (logit sigma ~180), so P's lo-half is numerically negligible.
// l (denominator) kept as per-thread partials, reduced once at the end.
// ===========================================================================
#define AQH 0
#define AQL 16384
#define AKH(c) (32768 + (c)*32768)
#define AKL(c) (32768 + (c)*32768 + 8192)
#define AVH(c) (32768 + (c)*32768 + 16384)
#define AVL(c) (32768 + (c)*32768 + 24576)
#define APH 98304
#define AWMX 114688
#define ALRD 116736
#define ASZ  118784

__global__ void __launch_bounds__(512, 1) attn_mma(
    const bf16* __restrict__ Qh, const bf16* __restrict__ Ql,
    const bf16* __restrict__ Kh, const bf16* __restrict__ Kl,
    const bf16* __restrict__ Vh, const bf16* __restrict__ Vl,
    bf16* __restrict__ Ch, bf16* __restrict__ Cl)
{
    extern __shared__ char sm[];
    const uint32_t sb = smem_u32(sm);
    float* wmax = (float*)(sm + AWMX);   // [4][128]
    float* lred = (float*)(sm + ALRD);   // [4][128]

    const int tid = threadIdx.x, warp = tid >> 5, lane = tid & 31;
    const int wm = warp >> 2, wn = warp & 3;
    const int lr = lane & 7, g = lane >> 3;
    const int offAr = (g & 1) * 8 + lr, offAc = (g >> 1) * 8;
    const int offBr = (g >> 1) * 8 + lr, offBc = (g & 1) * 8;
    const int bh = blockIdx.y, q0 = blockIdx.x * 128;

    const char* khb = (const char*)Kh + ((size_t)bh * 2048) * 128;
    const char* klb = (const char*)Kl + ((size_t)bh * 2048) * 128;
    const char* vhb = (const char*)Vh + ((size_t)bh * 2048) * 128;
    const char* vlb = (const char*)Vl + ((size_t)bh * 2048) * 128;

    // Q tiles (hi/lo), 128x64
    {
        const char* qhp = (const char*)Qh + ((size_t)bh * 2048 + q0) * 128;
        const char* qlp = (const char*)Ql + ((size_t)bh * 2048 + q0) * 128;
#pragma unroll
        for (int i = 0; i < 2; i++) {
            int t = i * 512 + tid, row = t >> 3, cb = (t & 7) * 16;
            uint32_t dsw = SWZ(row * 128 + cb);
            *(uint4*)(sm + AQH + dsw) = *(const uint4*)(qhp + row * 128 + cb);
            *(uint4*)(sm + AQL + dsw) = *(const uint4*)(qlp + row * 128 + cb);
        }
    }

    // prologue: issue kt=0 loads into buf 0
    {
        int row = tid >> 3, cb = (tid & 7) * 16;
        uint32_t dsw = SWZ(row * 128 + cb);
        size_t go = (size_t)row * 128 + cb;
        cpa16(sb + AKH(0) + dsw, khb + go);
        cpa16(sb + AKL(0) + dsw, klb + go);
        cpa16(sb + AVH(0) + dsw, vhb + go);
        cpa16(sb + AVL(0) + dsw, vlb + go);
        CP_COMMIT();
    }

    float oacc[2][2][4];
#pragma unroll
    for (int a = 0; a < 2; a++)
#pragma unroll
        for (int b = 0; b < 2; b++)
#pragma unroll
            for (int c = 0; c < 4; c++) oacc[a][b][c] = 0.0f;
    float m_prev[4], l_part[4];
#pragma unroll
    for (int r = 0; r < 4; r++) { m_prev[r] = -INFINITY; l_part[r] = 0.0f; }

    for (int kt = 0; kt < 32; kt++) {
        const int c = kt & 1;
        CP_WAIT0();
        __syncthreads();   // buf c ready + all threads done with iter kt-1

        if (kt < 31) {     // prefetch kt+1 into buf c^1
            size_t tb = (size_t)(kt + 1) * 64 * 128;
            int row = tid >> 3, cb = (tid & 7) * 16;
            uint32_t dsw = SWZ(row * 128 + cb);
            size_t go = tb + (size_t)row * 128 + cb;
            cpa16(sb + AKH(c ^ 1) + dsw, khb + go);
            cpa16(sb + AKL(c ^ 1) + dsw, klb + go);
            cpa16(sb + AVH(c ^ 1) + dsw, vhb + go);
            cpa16(sb + AVL(c ^ 1) + dsw, vlb + go);
            CP_COMMIT();
        }

        // ---- S = Q K^T (warp tile 32x16) ----
        float sacc[2][2][4];
#pragma unroll
        for (int a = 0; a < 2; a++)
#pragma unroll
            for (int b = 0; b < 2; b++)
#pragma unroll
                for (int e = 0; e < 4; e++) sacc[a][b][e] = 0.0f;

#pragma unroll
        for (int ks = 0; ks < 4; ks++) {
            uint32_t kh2[4], kl2[4];
            uint32_t boff = SWZ((wn * 16 + offBr) * 128 + (ks * 16 + offBc) * 2);
            ldm4(kh2, sb + AKH(c) + boff);
            ldm4(kl2, sb + AKL(c) + boff);
#pragma unroll
            for (int mf = 0; mf < 2; mf++) {
                uint32_t aoff = SWZ((wm * 32 + mf * 16 + offAr) * 128 + (ks * 16 + offAc) * 2);
                uint32_t qh2[4], ql2[4];
                ldm4(qh2, sb + AQH + aoff);
                ldm4(ql2, sb + AQL + aoff);
#pragma unroll
                for (int nf = 0; nf < 2; nf++) {
                    mma_bf(sacc[mf][nf], qh2, kh2[nf * 2], kh2[nf * 2 + 1]);
                    mma_bf(sacc[mf][nf], qh2, kl2[nf * 2], kl2[nf * 2 + 1]);
                    mma_bf(sacc[mf][nf], ql2, kh2[nf * 2], kh2[nf * 2 + 1]);
                }
            }
        }

        // ---- scale + warp-chunk row max ----
#pragma unroll
        for (int mf = 0; mf < 2; mf++) {
            float mlo = -INFINITY, mhi = -INFINITY;
#pragma unroll
            for (int nf = 0; nf < 2; nf++) {
#pragma unroll
                for (int e = 0; e < 4; e++) sacc[mf][nf][e] *= SCALE_;
                mlo = fmaxf(mlo, fmaxf(sacc[mf][nf][0], sacc[mf][nf][1]));
                mhi = fmaxf(mhi, fmaxf(sacc[mf][nf][2], sacc[mf][nf][3]));
            }
            mlo = fmaxf(mlo, __shfl_xor_sync(0xffffffffu, mlo, 1));
            mlo = fmaxf(mlo, __shfl_xor_sync(0xffffffffu, mlo, 2));
            mhi = fmaxf(mhi, __shfl_xor_sync(0xffffffffu, mhi, 1));
            mhi = fmaxf(mhi, __shfl_xor_sync(0xffffffffu, mhi, 2));
            if ((lane & 3) == 0) {
                int rl = wm * 32 + mf * 16 + (lane >> 2);
                wmax[wn * 128 + rl] = mlo;
                wmax[wn * 128 + rl + 8] = mhi;
            }
        }
        __syncthreads();

        // ---- exp + P store (hi only) + per-thread l update + O rescale ----
#pragma unroll
        for (int mf = 0; mf < 2; mf++) {
            int rl = wm * 32 + mf * 16 + (lane >> 2), rh = rl + 8;
            float ml = m_prev[mf * 2], mh2 = m_prev[mf * 2 + 1];
#pragma unroll
            for (int w = 0; w < 4; w++) {
                ml = fmaxf(ml, wmax[w * 128 + rl]);
                mh2 = fmaxf(mh2, wmax[w * 128 + rh]);
            }
            float slo = 0.0f, shi = 0.0f;
#pragma unroll
            for (int nf = 0; nf < 2; nf++) {
                float p0 = __expf(sacc[mf][nf][0] - ml);
                float p1 = __expf(sacc[mf][nf][1] - ml);
                float p2 = __expf(sacc[mf][nf][2] - mh2);
                float p3 = __expf(sacc[mf][nf][3] - mh2);
                slo += p0 + p1; shi += p2 + p3;
                int col = wn * 16 + nf * 8 + (lane & 3) * 2;
                bf162 t;
                t.x = __float2bfloat16(p0); t.y = __float2bfloat16(p1);
                *(bf162*)(sm + APH + SWZ(rl * 128 + col * 2)) = t;
                t.x = __float2bfloat16(p2); t.y = __float2bfloat16(p3);
                *(bf162*)(sm + APH + SWZ(rh * 128 + col * 2)) = t;
            }
            float cl_ = __expf(m_prev[mf * 2] - ml);
            float ch_ = __expf(m_prev[mf * 2 + 1] - mh2);
            l_part[mf * 2]     = l_part[mf * 2] * cl_ + slo;
            l_part[mf * 2 + 1] = l_part[mf * 2 + 1] * ch_ + shi;
            m_prev[mf * 2] = ml; m_prev[mf * 2 + 1] = mh2;
#pragma unroll
            for (int nf = 0; nf < 2; nf++) {
                oacc[mf][nf][0] *= cl_; oacc[mf][nf][1] *= cl_;
                oacc[mf][nf][2] *= ch_; oacc[mf][nf][3] *= ch_;
            }
        }
        __syncthreads();

        // ---- PV, 2-pass (O warp tile 32x16) ----
#pragma unroll
        for (int ks = 0; ks < 4; ks++) {
            uint32_t voff = SWZ((ks * 16 + offAr) * 128 + (wn * 16 + offAc) * 2);
            uint32_t vh2[4], vl2[4];
            ldm4t(vh2, sb + AVH(c) + voff);
            ldm4t(vl2, sb + AVL(c) + voff);
#pragma unroll
            for (int mf = 0; mf < 2; mf++) {
                uint32_t poff = SWZ((wm * 32 + mf * 16 + offAr) * 128 + (ks * 16 + offAc) * 2);
                uint32_t ph2[4];
                ldm4(ph2, sb + APH + poff);
#pragma unroll
                for (int nf = 0; nf < 2; nf++) {
                    mma_bf(oacc[mf][nf], ph2, vh2[nf * 2], vh2[nf * 2 + 1]);
                    mma_bf(oacc[mf][nf], ph2, vl2[nf * 2], vl2[nf * 2 + 1]);
                }
            }
        }
    }

    // ---- final l reduction: quad shuffles -> smem across wn warps ----
#pragma unroll
    for (int mf = 0; mf < 2; mf++) {
        float slo = l_part[mf * 2], shi = l_part[mf * 2 + 1];
        slo += __shfl_xor_sync(0xffffffffu, slo, 1);
        slo += __shfl_xor_sync(0xffffffffu, slo, 2);
        shi += __shfl_xor_sync(0xffffffffu, shi, 1);
        shi += __shfl_xor_sync(0xffffffffu, shi, 2);
        if ((lane & 3) == 0) {
            int rl = wm * 32 + mf * 16 + (lane >> 2);
            lred[wn * 128 + rl] = slo;
            lred[wn * 128 + rl + 8] = shi;
        }
    }
    __syncthreads();

    // ---- epilogue: O /= l, write merged context hi/lo [B*M, 512] ----
    const int b = bh >> 3, h = bh & 7;
#pragma unroll
    for (int mf = 0; mf < 2; mf++) {
        int rl = wm * 32 + mf * 16 + (lane >> 2), rh = rl + 8;
        float ll = lred[rl] + lred[128 + rl] + lred[256 + rl] + lred[384 + rl];
        float lh = lred[rh] + lred[128 + rh] + lred[256 + rh] + lred[384 + rh];
        float il = 1.0f / ll, ih = 1.0f / lh;
#pragma unroll
        for (int nf = 0; nf < 2; nf++) {
            int col = wn * 16 + nf * 8 + (lane & 3) * 2;
            size_t blo = ((size_t)b * 2048 + q0 + rl) * 512 + h * 64 + col;
            size_t bhi = ((size_t)b * 2048 + q0 + rh) * 512 + h * 64 + col;
            bf16 x0, y0, x1, y1;
            splitf(oacc[mf][nf][0] * il, x0, y0);
            splitf(oacc[mf][nf][1] * il, x1, y1);
            bf162 t, u; t.x = x0; t.y = x1; u.x = y0; u.y = y1;
            *(bf162*)(Ch + blo) = t; *(bf162*)(Cl + blo) = u;
            splitf(oacc[mf][nf][2] * ih, x0, y0);
            splitf(oacc[mf][nf][3] * ih, x1, y1);
            t.x = x0; t.y = x1; u.x = y0; u.y = y1;
            *(bf162*)(Ch + bhi) = t; *(bf162*)(Cl + bhi) = u;
        }
    }
}

// ---------------------------------------------------------------------------
extern "C" void kernel_launch(void* const* d_in, const int* in_sizes, int n_in,
                              void* d_out, int out_size)
{
    const float* x  = (const float*)d_in[0];
    const float* Wq = (const float*)d_in[1];
    const float* Wk = (const float*)d_in[2];
    const float* Wv = (const float*)d_in[3];
    const float* Wo = (const float*)d_in[4];
    const float* bo = (const float*)d_in[5];
    float* out = (float*)d_out;

    bf16 *Xh, *Xl, *Qh, *Ql, *Kh, *Kl, *Vh, *Vl, *Chp, *Clp, *Whp, *Wlp;
    cudaGetSymbolAddress((void**)&Xh, g_Xh);  cudaGetSymbolAddress((void**)&Xl, g_Xl);
    cudaGetSymbolAddress((void**)&Qh, g_Qh);  cudaGetSymbolAddress((void**)&Ql, g_Ql);
    cudaGetSymbolAddress((void**)&Kh, g_Kh);  cudaGetSymbolAddress((void**)&Kl, g_Kl);
    cudaGetSymbolAddress((void**)&Vh, g_Vh);  cudaGetSymbolAddress((void**)&Vl, g_Vl);
    cudaGetSymbolAddress((void**)&Chp, g_Ch); cudaGetSymbolAddress((void**)&Clp, g_Cl);
    cudaGetSymbolAddress((void**)&Whp, g_Wh); cudaGetSymbolAddress((void**)&Wlp, g_Wl);

    cudaFuncSetAttribute(gemm_mma<0>, cudaFuncAttributeMaxDynamicSharedMemorySize, G_SZ);
    cudaFuncSetAttribute(gemm_mma<2>, cudaFuncAttributeMaxDynamicSharedMemorySize, G_SZ);
    cudaFuncSetAttribute(attn_mma, cudaFuncAttributeMaxDynamicSharedMemorySize, ASZ);

    // prep
    prep_x<<<(BM_ * HD_ / 4) / 512, 512>>>((const float4*)x, Xh, Xl);
    dim3 wblk(32, 8), wgrd(16, 16, 4);
    prep_w4<<<wgrd, wblk>>>(Wq, Wk, Wv, Wo, Whp, Wlp);

    // fused QKV projections -> [b,h,m,d] hi/lo
    gemm_mma<0><<<dim3(12, 128), 256, G_SZ>>>(Xh, Xl, Whp, Wlp,
                                              nullptr, nullptr,
                                              Qh, Ql, Kh, Kl, Vh, Vl);

    // attention
    attn_mma<<<dim3(16, 64), 512, ASZ>>>(Qh, Ql, Kh, Kl, Vh, Vl, Chp, Clp);

    // output projection + bias
    gemm_mma<2><<<dim3(4, 128), 256, G_SZ>>>(Chp, Clp, Whp + 3 * 262144, Wlp + 3 * 262144,
                                             bo, out, nullptr, nullptr,
                                             nullptr, nullptr, nullptr, nullptr);
}

// round 8
// speedup vs baseline: 1.6809x; 1.6809x over previous
#include <cuda_runtime.h>
#include <cuda_bf16.h>
#include <stdint.h>
#include <math.h>

#define B_ 8
#define M_ 2048
#define HD_ 512
#define BM_ (B_*M_)
#define SCALE_ 22.62741699796952f   // reference divides by HEAD_DIM**-0.5

typedef __nv_bfloat16 bf16;
typedef __nv_bfloat162 bf162;

// ---------------- device scratch (allocation-free rule) ----------------
__device__ __align__(16) bf16 g_Xh[(size_t)BM_*HD_], g_Xl[(size_t)BM_*HD_];
__device__ __align__(16) bf16 g_Qh[(size_t)BM_*HD_], g_Ql[(size_t)BM_*HD_];
__device__ __align__(16) bf16 g_Kh[(size_t)BM_*HD_], g_Kl[(size_t)BM_*HD_];
__device__ __align__(16) bf16 g_Vh[(size_t)BM_*HD_], g_Vl[(size_t)BM_*HD_];
__device__ __align__(16) bf16 g_Ch[(size_t)BM_*HD_], g_Cl[(size_t)BM_*HD_];
__device__ __align__(16) bf16 g_Wh[4][512*512], g_Wl[4][512*512];   // W^T: [n][k]

// ---------------- helpers ----------------
__device__ __forceinline__ uint32_t smem_u32(const void* p) {
    uint32_t a;
    asm("{ .reg .u64 t; cvta.to.shared.u64 t, %1; cvt.u32.u64 %0, t; }" : "=r"(a) : "l"(p));
    return a;
}
#define SWZ(x) ((uint32_t)(x) ^ ((((uint32_t)(x)) >> 3) & 0x70))

__device__ __forceinline__ void ldm4(uint32_t (&r)[4], uint32_t a) {
    asm volatile("ldmatrix.sync.aligned.m8n8.x4.shared.b16 {%0,%1,%2,%3}, [%4];"
                 : "=r"(r[0]), "=r"(r[1]), "=r"(r[2]), "=r"(r[3]) : "r"(a));
}
__device__ __forceinline__ void ldm4t(uint32_t (&r)[4], uint32_t a) {
    asm volatile("ldmatrix.sync.aligned.m8n8.x4.trans.shared.b16 {%0,%1,%2,%3}, [%4];"
                 : "=r"(r[0]), "=r"(r[1]), "=r"(r[2]), "=r"(r[3]) : "r"(a));
}
__device__ __forceinline__ void mma_bf(float (&d)[4], const uint32_t (&a)[4],
                                       uint32_t b0, uint32_t b1) {
    asm volatile("mma.sync.aligned.m16n8k16.row.col.f32.bf16.bf16.f32 "
                 "{%0,%1,%2,%3}, {%4,%5,%6,%7}, {%8,%9}, {%0,%1,%2,%3};"
                 : "+f"(d[0]), "+f"(d[1]), "+f"(d[2]), "+f"(d[3])
                 : "r"(a[0]), "r"(a[1]), "r"(a[2]), "r"(a[3]), "r"(b0), "r"(b1));
}
__device__ __forceinline__ void splitf(float x, bf16& h, bf16& l) {
    h = __float2bfloat16(x);
    l = __float2bfloat16(x - __bfloat162float(h));
}
__device__ __forceinline__ uint32_t packbf(float a, float b) {
    bf162 t; t.x = __float2bfloat16(a); t.y = __float2bfloat16(b);
    return *(uint32_t*)&t;
}
__device__ __forceinline__ void cpa16(uint32_t dst, const void* src) {
    asm volatile("cp.async.cg.shared.global [%0], [%1], 16;" :: "r"(dst), "l"(src));
}
#define CP_COMMIT() asm volatile("cp.async.commit_group;" ::: "memory")
#define CP_WAIT0()  asm volatile("cp.async.wait_group 0;" ::: "memory")

// ---------------- prep kernels ----------------
__global__ void __launch_bounds__(512) prep_x(const float4* __restrict__ x,
                                              bf16* __restrict__ xh, bf16* __restrict__ xl) {
    size_t i = (size_t)blockIdx.x * 512 + threadIdx.x;
    float4 v = x[i];
    bf16 h0, l0, h1, l1, h2, l2, h3, l3;
    splitf(v.x, h0, l0); splitf(v.y, h1, l1);
    splitf(v.z, h2, l2); splitf(v.w, h3, l3);
    bf162 a, b, c, d;
    a.x = h0; a.y = h1; b.x = h2; b.y = h3;
    c.x = l0; c.y = l1; d.x = l2; d.y = l3;
    *(bf162*)(xh + i * 4) = a; *(bf162*)(xh + i * 4 + 2) = b;
    *(bf162*)(xl + i * 4) = c; *(bf162*)(xl + i * 4 + 2) = d;
}

// coalesced tile-transpose for all 4 weights: W[k][n] -> W^T[n][k] hi/lo
__global__ void __launch_bounds__(256) prep_w4(
    const float* __restrict__ W0, const float* __restrict__ W1,
    const float* __restrict__ W2, const float* __restrict__ W3,
    bf16* __restrict__ th, bf16* __restrict__ tl) {
    __shared__ float t[32][33];
    const int w = blockIdx.z;
    const float* W = (w == 0) ? W0 : (w == 1) ? W1 : (w == 2) ? W2 : W3;
    bf16* thw = th + (size_t)w * 262144;
    bf16* tlw = tl + (size_t)w * 262144;
    const int bx = blockIdx.x * 32;   // n-block
    const int by = blockIdx.y * 32;   // k-block
    const int tx = threadIdx.x, ty = threadIdx.y;
#pragma unroll
    for (int j = ty; j < 32; j += 8)
        t[j][tx] = W[(size_t)(by + j) * 512 + bx + tx];
    __syncthreads();
#pragma unroll
    for (int j = ty; j < 32; j += 8) {
        float v = t[tx][j];
        bf16 h, l; splitf(v, h, l);
        thw[(size_t)(bx + j) * 512 + by + tx] = h;
        tlw[(size_t)(bx + j) * 512 + by + tx] = l;
    }
}

// ===========================================================================
// GEMM via mma.sync, cp.async double-buffered.
// CTA 128x128, 8 warps (2x4), warp tile 64x32, split-bf16 3-pass.
// MODE 0 (fused QKV): blockIdx.x selects W/output. MODE 2: fp32 + bias.
// ===========================================================================
#define GS(c)   ((c) * 65536)
#define G_AH(c) (GS(c) + 0)
#define G_AL(c) (GS(c) + 16384)
#define G_BH(c) (GS(c) + 32768)
#define G_BL(c) (GS(c) + 49152)
#define G_SZ    131072

template <int MODE>
__global__ void __launch_bounds__(256, 1) gemm_mma(
    const bf16* __restrict__ Ah_, const bf16* __restrict__ Al_,
    const bf16* __restrict__ WhB, const bf16* __restrict__ WlB,
    const float* __restrict__ bias, float* __restrict__ out32,
    bf16* __restrict__ oh0, bf16* __restrict__ ol0,
    bf16* __restrict__ oh1, bf16* __restrict__ ol1,
    bf16* __restrict__ oh2, bf16* __restrict__ ol2)
{
    extern __shared__ char sm[];
    const uint32_t sb = smem_u32(sm);
    const int tid = threadIdx.x, warp = tid >> 5, lane = tid & 31;
    const int wm = warp >> 2, wn = warp & 3;
    const int lr = lane & 7, g = lane >> 3;
    const int offAr = (g & 1) * 8 + lr, offAc = (g >> 1) * 8;
    const int offBr = (g >> 1) * 8 + lr, offBc = (g & 1) * 8;

    const int widx = (MODE == 0) ? (blockIdx.x >> 2) : 0;    // which W / output
    const int n0 = (MODE == 0) ? ((blockIdx.x & 3) * 128) : (blockIdx.x * 128);
    const int m0 = blockIdx.y * 128;
    const bf16* Bh_ = WhB + (size_t)widx * 262144;
    const bf16* Bl_ = WlB + (size_t)widx * 262144;

    // prologue: chunk 0
#pragma unroll
    for (int i = 0; i < 4; i++) {
        int t = i * 256 + tid, row = t >> 3, cb = (t & 7) * 16;
        uint32_t dsw = SWZ(row * 128 + cb);
        size_t abyte = ((size_t)(m0 + row) * 512) * 2 + cb;
        size_t bbyte = ((size_t)(n0 + row) * 512) * 2 + cb;
        cpa16(sb + G_AH(0) + dsw, (const char*)Ah_ + abyte);
        cpa16(sb + G_AL(0) + dsw, (const char*)Al_ + abyte);
        cpa16(sb + G_BH(0) + dsw, (const char*)Bh_ + bbyte);
        cpa16(sb + G_BL(0) + dsw, (const char*)Bl_ + bbyte);
    }
    CP_COMMIT();

    float acc[4][4][4];
#pragma unroll
    for (int a = 0; a < 4; a++)
#pragma unroll
        for (int b = 0; b < 4; b++)
#pragma unroll
            for (int c = 0; c < 4; c++) acc[a][b][c] = 0.0f;

    for (int ch = 0; ch < 8; ch++) {
        const int c = ch & 1;
        CP_WAIT0();
        __syncthreads();          // buf c ready; all warps done with buf c^1

        if (ch < 7) {             // prefetch ch+1 into buf c^1
#pragma unroll
            for (int i = 0; i < 4; i++) {
                int t = i * 256 + tid, row = t >> 3, cb = (t & 7) * 16;
                uint32_t dsw = SWZ(row * 128 + cb);
                size_t abyte = ((size_t)(m0 + row) * 512 + (ch + 1) * 64) * 2 + cb;
                size_t bbyte = ((size_t)(n0 + row) * 512 + (ch + 1) * 64) * 2 + cb;
                cpa16(sb + G_AH(c ^ 1) + dsw, (const char*)Ah_ + abyte);
                cpa16(sb + G_AL(c ^ 1) + dsw, (const char*)Al_ + abyte);
                cpa16(sb + G_BH(c ^ 1) + dsw, (const char*)Bh_ + bbyte);
                cpa16(sb + G_BL(c ^ 1) + dsw, (const char*)Bl_ + bbyte);
            }
            CP_COMMIT();
        }

#pragma unroll
        for (int ks = 0; ks < 4; ks++) {
            uint32_t bhF[2][4], blF[2][4];
#pragma unroll
            for (int np = 0; np < 2; np++) {
                uint32_t boff = SWZ((wn * 32 + np * 16 + offBr) * 128 + (ks * 16 + offBc) * 2);
                ldm4(bhF[np], sb + G_BH(c) + boff);
                ldm4(blF[np], sb + G_BL(c) + boff);
            }
#pragma unroll
            for (int mf = 0; mf < 4; mf++) {
                uint32_t aoff = SWZ((wm * 64 + mf * 16 + offAr) * 128 + (ks * 16 + offAc) * 2);
                uint32_t ah2[4], al2[4];
                ldm4(ah2, sb + G_AH(c) + aoff);
                ldm4(al2, sb + G_AL(c) + aoff);
#pragma unroll
                for (int nf = 0; nf < 4; nf++) {
                    int np = nf >> 1, hh = nf & 1;
                    uint32_t b0h = bhF[np][hh * 2], b1h = bhF[np][hh * 2 + 1];
                    uint32_t b0l = blF[np][hh * 2], b1l = blF[np][hh * 2 + 1];
                    mma_bf(acc[mf][nf], ah2, b0h, b1h);
                    mma_bf(acc[mf][nf], ah2, b0l, b1l);
                    mma_bf(acc[mf][nf], al2, b0h, b1h);
                }
            }
        }
    }

    bf16* oh = (MODE == 0) ? ((widx == 0) ? oh0 : (widx == 1) ? oh1 : oh2) : oh0;
    bf16* ol = (MODE == 0) ? ((widx == 0) ? ol0 : (widx == 1) ? ol1 : ol2) : ol0;

#pragma unroll
    for (int mf = 0; mf < 4; mf++) {
        int rlo = m0 + wm * 64 + mf * 16 + (lane >> 2);
        int rhi = rlo + 8;
#pragma unroll
        for (int nf = 0; nf < 4; nf++) {
            int n = n0 + wn * 32 + nf * 8 + (lane & 3) * 2;
            if (MODE == 2) {
                float2 v0, v1;
                v0.x = acc[mf][nf][0] + bias[n]; v0.y = acc[mf][nf][1] + bias[n + 1];
                v1.x = acc[mf][nf][2] + bias[n]; v1.y = acc[mf][nf][3] + bias[n + 1];
                *(float2*)(out32 + (size_t)rlo * 512 + n) = v0;
                *(float2*)(out32 + (size_t)rhi * 512 + n) = v1;
            } else {
                int h = n >> 6, d = n & 63;
                {
                    int b = rlo >> 11, mm = rlo & 2047;
                    size_t base = ((size_t)(b * 8 + h) * 2048 + mm) * 64 + d;
                    bf16 h0, l0, h1, l1;
                    splitf(acc[mf][nf][0], h0, l0); splitf(acc[mf][nf][1], h1, l1);
                    bf162 t, u; t.x = h0; t.y = h1; u.x = l0; u.y = l1;
                    *(bf162*)(oh + base) = t; *(bf162*)(ol + base) = u;
                }
                {
                    int b = rhi >> 11, mm = rhi & 2047;
                    size_t base = ((size_t)(b * 8 + h) * 2048 + mm) * 64 + d;
                    bf16 h0, l0, h1, l1;
                    splitf(acc[mf][nf][2], h0, l0); splitf(acc[mf][nf][3], h1, l1);
                    bf162 t, u; t.x = h0; t.y = h1; u.x = l0; u.y = l1;
                    *(bf162*)(oh + base) = t; *(bf162*)(ol + base) = u;
                }
            }
        }
    }
}

// ===========================================================================
// Flash attention, FA2-style register-resident P. 256 threads, 8 warps:
// wm = warp>>1 (4 row-groups of 32), wn = warp&1 (2 key-chunks of 32).
// S accumulator frags are repacked in-register as PV A-operand frags
// (split-k over wn); partial O summed across wn once at the end.
// PV 2-pass (Ph*Vh + Ph*Vl). 2 barriers per iter. No P smem traffic.
// ===========================================================================
#define AQH 0
#define AQL 16384
#define AKH(c) (32768 + (c)*32768)
#define AKL(c) (32768 + (c)*32768 + 8192)
#define AVH(c) (32768 + (c)*32768 + 16384)
#define AVL(c) (32768 + (c)*32768 + 24576)
#define AOB  98304             // O-reduce buffer: 128 rows x 66 f32 = 33792 B
#define AWMX 132096            // [2][128] f32
#define ALRD 133120            // [2][128] f32
#define ASZ  134144

__global__ void __launch_bounds__(256, 1) attn_mma(
    const bf16* __restrict__ Qh, const bf16* __restrict__ Ql,
    const bf16* __restrict__ Kh, const bf16* __restrict__ Kl,
    const bf16* __restrict__ Vh, const bf16* __restrict__ Vl,
    bf16* __restrict__ Ch, bf16* __restrict__ Cl)
{
    extern __shared__ char sm[];
    const uint32_t sb = smem_u32(sm);
    float* wmax = (float*)(sm + AWMX);   // [2][128]
    float* lred = (float*)(sm + ALRD);   // [2][128]
    float* obuf = (float*)(sm + AOB);    // [128][66]

    const int tid = threadIdx.x, warp = tid >> 5, lane = tid & 31;
    const int wm = warp >> 1, wn = warp & 1;
    const int lr = lane & 7, g = lane >> 3;
    const int offAr = (g & 1) * 8 + lr, offAc = (g >> 1) * 8;
    const int offBr = (g >> 1) * 8 + lr, offBc = (g & 1) * 8;
    const int bh = blockIdx.y, q0 = blockIdx.x * 128;

    const char* khb = (const char*)Kh + ((size_t)bh * 2048) * 128;
    const char* klb = (const char*)Kl + ((size_t)bh * 2048) * 128;
    const char* vhb = (const char*)Vh + ((size_t)bh * 2048) * 128;
    const char* vlb = (const char*)Vl + ((size_t)bh * 2048) * 128;

    // Q tiles (hi/lo), 128x64 into smem
    {
        const char* qhp = (const char*)Qh + ((size_t)bh * 2048 + q0) * 128;
        const char* qlp = (const char*)Ql + ((size_t)bh * 2048 + q0) * 128;
#pragma unroll
        for (int i = 0; i < 4; i++) {
            int t = i * 256 + tid, row = t >> 3, cb = (t & 7) * 16;
            uint32_t dsw = SWZ(row * 128 + cb);
            *(uint4*)(sm + AQH + dsw) = *(const uint4*)(qhp + row * 128 + cb);
            *(uint4*)(sm + AQL + dsw) = *(const uint4*)(qlp + row * 128 + cb);
        }
    }

    // prologue: kt=0 loads into buf 0 (each thread: 2x16B per array)
#pragma unroll
    for (int i = 0; i < 2; i++) {
        int t = i * 256 + tid, row = t >> 3, cb = (t & 7) * 16;
        uint32_t dsw = SWZ(row * 128 + cb);
        size_t go = (size_t)row * 128 + cb;
        cpa16(sb + AKH(0) + dsw, khb + go);
        cpa16(sb + AKL(0) + dsw, klb + go);
        cpa16(sb + AVH(0) + dsw, vhb + go);
        cpa16(sb + AVL(0) + dsw, vlb + go);
    }
    CP_COMMIT();
    __syncthreads();   // Q smem visible

    // hoist Q-hi fragments (loop-invariant): [ks][mf][4] = 32 regs
    uint32_t qfh[4][2][4];
#pragma unroll
    for (int ks = 0; ks < 4; ks++)
#pragma unroll
        for (int mf = 0; mf < 2; mf++) {
            uint32_t aoff = SWZ((wm * 32 + mf * 16 + offAr) * 128 + (ks * 16 + offAc) * 2);
            ldm4(qfh[ks][mf], sb + AQH + aoff);
        }

    float oacc[2][8][4];
#pragma unroll
    for (int a = 0; a < 2; a++)
#pragma unroll
        for (int b = 0; b < 8; b++)
#pragma unroll
            for (int c = 0; c < 4; c++) oacc[a][b][c] = 0.0f;
    float m_prev[4], l_part[4];
#pragma unroll
    for (int r = 0; r < 4; r++) { m_prev[r] = -INFINITY; l_part[r] = 0.0f; }

    for (int kt = 0; kt < 32; kt++) {
        const int c = kt & 1;
        CP_WAIT0();
        __syncthreads();   // buf c ready + all warps done with iter kt-1

        if (kt < 31) {     // prefetch kt+1 into buf c^1
            size_t tb = (size_t)(kt + 1) * 64 * 128;
#pragma unroll
            for (int i = 0; i < 2; i++) {
                int t = i * 256 + tid, row = t >> 3, cb = (t & 7) * 16;
                uint32_t dsw = SWZ(row * 128 + cb);
                size_t go = tb + (size_t)row * 128 + cb;
                cpa16(sb + AKH(c ^ 1) + dsw, khb + go);
                cpa16(sb + AKL(c ^ 1) + dsw, klb + go);
                cpa16(sb + AVH(c ^ 1) + dsw, vhb + go);
                cpa16(sb + AVL(c ^ 1) + dsw, vlb + go);
            }
            CP_COMMIT();
        }

        // ---- S = Q K^T : warp computes S[32 rows x 32 own keys] ----
        float sacc[2][4][4];
#pragma unroll
        for (int a = 0; a < 2; a++)
#pragma unroll
            for (int b = 0; b < 4; b++)
#pragma unroll
                for (int e = 0; e < 4; e++) sacc[a][b][e] = 0.0f;

#pragma unroll
        for (int ks = 0; ks < 4; ks++) {
            uint32_t kh2[2][4], kl2[2][4];
#pragma unroll
            for (int kg = 0; kg < 2; kg++) {
                uint32_t boff = SWZ((wn * 32 + kg * 16 + offBr) * 128 + (ks * 16 + offBc) * 2);
                ldm4(kh2[kg], sb + AKH(c) + boff);
                ldm4(kl2[kg], sb + AKL(c) + boff);
            }
#pragma unroll
            for (int mf = 0; mf < 2; mf++) {
                uint32_t aoff = SWZ((wm * 32 + mf * 16 + offAr) * 128 + (ks * 16 + offAc) * 2);
                uint32_t ql2[4];
                ldm4(ql2, sb + AQL + aoff);
#pragma unroll
                for (int nf = 0; nf < 4; nf++) {
                    int kg = nf >> 1, hh = nf & 1;
                    mma_bf(sacc[mf][nf], qfh[ks][mf], kh2[kg][hh * 2], kh2[kg][hh * 2 + 1]);
                    mma_bf(sacc[mf][nf], qfh[ks][mf], kl2[kg][hh * 2], kl2[kg][hh * 2 + 1]);
                    mma_bf(sacc[mf][nf], ql2,         kh2[kg][hh * 2], kh2[kg][hh * 2 + 1]);
                }
            }
        }

        // ---- scale + warp-chunk row max ----
#pragma unroll
        for (int mf = 0; mf < 2; mf++) {
            float mlo = -INFINITY, mhi = -INFINITY;
#pragma unroll
            for (int nf = 0; nf < 4; nf++) {
#pragma unroll
                for (int e = 0; e < 4; e++) sacc[mf][nf][e] *= SCALE_;
                mlo = fmaxf(mlo, fmaxf(sacc[mf][nf][0], sacc[mf][nf][1]));
                mhi = fmaxf(mhi, fmaxf(sacc[mf][nf][2], sacc[mf][nf][3]));
            }
            mlo = fmaxf(mlo, __shfl_xor_sync(0xffffffffu, mlo, 1));
            mlo = fmaxf(mlo, __shfl_xor_sync(0xffffffffu, mlo, 2));
            mhi = fmaxf(mhi, __shfl_xor_sync(0xffffffffu, mhi, 1));
            mhi = fmaxf(mhi, __shfl_xor_sync(0xffffffffu, mhi, 2));
            if ((lane & 3) == 0) {
                int rl = wm * 32 + mf * 16 + (lane >> 2);
                wmax[wn * 128 + rl] = mlo;
                wmax[wn * 128 + rl + 8] = mhi;
            }
        }
        __syncthreads();

        // ---- exp in regs -> PV A-frags; l partials; O rescale ----
        uint32_t pa[2][2][4];
#pragma unroll
        for (int mf = 0; mf < 2; mf++) {
            int rl = wm * 32 + mf * 16 + (lane >> 2), rh = rl + 8;
            float ml = fmaxf(m_prev[mf * 2], fmaxf(wmax[rl], wmax[128 + rl]));
            float mh2 = fmaxf(m_prev[mf * 2 + 1], fmaxf(wmax[rh], wmax[128 + rh]));
            float slo = 0.0f, shi = 0.0f;
            float pv[4][4];
#pragma unroll
            for (int nf = 0; nf < 4; nf++) {
                pv[nf][0] = __expf(sacc[mf][nf][0] - ml);
                pv[nf][1] = __expf(sacc[mf][nf][1] - ml);
                pv[nf][2] = __expf(sacc[mf][nf][2] - mh2);
                pv[nf][3] = __expf(sacc[mf][nf][3] - mh2);
                slo += pv[nf][0] + pv[nf][1];
                shi += pv[nf][2] + pv[nf][3];
            }
#pragma unroll
            for (int k2 = 0; k2 < 2; k2++) {
                pa[mf][k2][0] = packbf(pv[2 * k2][0], pv[2 * k2][1]);
                pa[mf][k2][1] = packbf(pv[2 * k2][2], pv[2 * k2][3]);
                pa[mf][k2][2] = packbf(pv[2 * k2 + 1][0], pv[2 * k2 + 1][1]);
                pa[mf][k2][3] = packbf(pv[2 * k2 + 1][2], pv[2 * k2 + 1][3]);
            }
            float cl_ = __expf(m_prev[mf * 2] - ml);
            float ch_ = __expf(m_prev[mf * 2 + 1] - mh2);
            l_part[mf * 2]     = l_part[mf * 2] * cl_ + slo;
            l_part[mf * 2 + 1] = l_part[mf * 2 + 1] * ch_ + shi;
            m_prev[mf * 2] = ml; m_prev[mf * 2 + 1] = mh2;
#pragma unroll
            for (int nj = 0; nj < 8; nj++) {
                oacc[mf][nj][0] *= cl_; oacc[mf][nj][1] *= cl_;
                oacc[mf][nj][2] *= ch_; oacc[mf][nj][3] *= ch_;
            }
        }

        // ---- PV: O_partial[32x64] += P(regs) * V(own 32 keys) ----
#pragma unroll
        for (int k2 = 0; k2 < 2; k2++) {
            uint32_t vh[4][4], vl[4][4];
#pragma unroll
            for (int j = 0; j < 4; j++) {
                uint32_t voff = SWZ((wn * 32 + k2 * 16 + offAr) * 128 + (j * 16 + offAc) * 2);
                ldm4t(vh[j], sb + AVH(c) + voff);
                ldm4t(vl[j], sb + AVL(c) + voff);
            }
#pragma unroll
            for (int mf = 0; mf < 2; mf++) {
#pragma unroll
                for (int j = 0; j < 4; j++) {
#pragma unroll
                    for (int hh = 0; hh < 2; hh++) {
                        int nj = j * 2 + hh;
                        mma_bf(oacc[mf][nj], pa[mf][k2], vh[j][hh * 2], vh[j][hh * 2 + 1]);
                        mma_bf(oacc[mf][nj], pa[mf][k2], vl[j][hh * 2], vl[j][hh * 2 + 1]);
                    }
                }
            }
        }
    }

    // ---- final reductions: l across wn; O partial from wn==1 staged ----
#pragma unroll
    for (int mf = 0; mf < 2; mf++) {
        float slo = l_part[mf * 2], shi = l_part[mf * 2 + 1];
        slo += __shfl_xor_sync(0xffffffffu, slo, 1);
        slo += __shfl_xor_sync(0xffffffffu, slo, 2);
        shi += __shfl_xor_sync(0xffffffffu, shi, 1);
        shi += __shfl_xor_sync(0xffffffffu, shi, 2);
        if ((lane & 3) == 0) {
            int rl = wm * 32 + mf * 16 + (lane >> 2);
            lred[wn * 128 + rl] = slo;
            lred[wn * 128 + rl + 8] = shi;
        }
    }
    if (wn == 1) {
#pragma unroll
        for (int mf = 0; mf < 2; mf++) {
            int rl = wm * 32 + mf * 16 + (lane >> 2), rh = rl + 8;
#pragma unroll
            for (int nj = 0; nj < 8; nj++) {
                int col = nj * 8 + (lane & 3) * 2;
                *(float2*)(obuf + rl * 66 + col) = make_float2(oacc[mf][nj][0], oacc[mf][nj][1]);
                *(float2*)(obuf + rh * 66 + col) = make_float2(oacc[mf][nj][2], oacc[mf][nj][3]);
            }
        }
    }
    __syncthreads();

    // ---- epilogue (wn==0 warps): O = mine + staged, /= l, write hi/lo ----
    if (wn == 0) {
        const int b = bh >> 3, h = bh & 7;
#pragma unroll
        for (int mf = 0; mf < 2; mf++) {
            int rl = wm * 32 + mf * 16 + (lane >> 2), rh = rl + 8;
            float il = 1.0f / (lred[rl] + lred[128 + rl]);
            float ih = 1.0f / (lred[rh] + lred[128 + rh]);
#pragma unroll
            for (int nj = 0; nj < 8; nj++) {
                int col = nj * 8 + (lane & 3) * 2;
                float2 s0 = *(float2*)(obuf + rl * 66 + col);
                float2 s1 = *(float2*)(obuf + rh * 66 + col);
                float v0 = (oacc[mf][nj][0] + s0.x) * il;
                float v1 = (oacc[mf][nj][1] + s0.y) * il;
                float v2 = (oacc[mf][nj][2] + s1.x) * ih;
                float v3 = (oacc[mf][nj][3] + s1.y) * ih;
                size_t blo = ((size_t)b * 2048 + q0 + rl) * 512 + h * 64 + col;
                size_t bhi = ((size_t)b * 2048 + q0 + rh) * 512 + h * 64 + col;
                bf16 x0, y0, x1, y1;
                splitf(v0, x0, y0); splitf(v1, x1, y1);
                bf162 t, u; t.x = x0; t.y = x1; u.x = y0; u.y = y1;
                *(bf162*)(Ch + blo) = t; *(bf162*)(Cl + blo) = u;
                splitf(v2, x0, y0); splitf(v3, x1, y1);
                t.x = x0; t.y = x1; u.x = y0; u.y = y1;
                *(bf162*)(Ch + bhi) = t; *(bf162*)(Cl + bhi) = u;
            }
        }
    }
}

// ---------------------------------------------------------------------------
extern "C" void kernel_launch(void* const* d_in, const int* in_sizes, int n_in,
                              void* d_out, int out_size)
{
    const float* x  = (const float*)d_in[0];
    const float* Wq = (const float*)d_in[1];
    const float* Wk = (const float*)d_in[2];
    const float* Wv = (const float*)d_in[3];
    const float* Wo = (const float*)d_in[4];
    const float* bo = (const float*)d_in[5];
    float* out = (float*)d_out;

    bf16 *Xh, *Xl, *Qh, *Ql, *Kh, *Kl, *Vh, *Vl, *Chp, *Clp, *Whp, *Wlp;
    cudaGetSymbolAddress((void**)&Xh, g_Xh);  cudaGetSymbolAddress((void**)&Xl, g_Xl);
    cudaGetSymbolAddress((void**)&Qh, g_Qh);  cudaGetSymbolAddress((void**)&Ql, g_Ql);
    cudaGetSymbolAddress((void**)&Kh, g_Kh);  cudaGetSymbolAddress((void**)&Kl, g_Kl);
    cudaGetSymbolAddress((void**)&Vh, g_Vh);  cudaGetSymbolAddress((void**)&Vl, g_Vl);
    cudaGetSymbolAddress((void**)&Chp, g_Ch); cudaGetSymbolAddress((void**)&Clp, g_Cl);
    cudaGetSymbolAddress((void**)&Whp, g_Wh); cudaGetSymbolAddress((void**)&Wlp, g_Wl);

    cudaFuncSetAttribute(gemm_mma<0>, cudaFuncAttributeMaxDynamicSharedMemorySize, G_SZ);
    cudaFuncSetAttribute(gemm_mma<2>, cudaFuncAttributeMaxDynamicSharedMemorySize, G_SZ);
    cudaFuncSetAttribute(attn_mma, cudaFuncAttributeMaxDynamicSharedMemorySize, ASZ);

    // prep
    prep_x<<<(BM_ * HD_ / 4) / 512, 512>>>((const float4*)x, Xh, Xl);
    dim3 wblk(32, 8), wgrd(16, 16, 4);
    prep_w4<<<wgrd, wblk>>>(Wq, Wk, Wv, Wo, Whp, Wlp);

    // fused QKV projections -> [b,h,m,d] hi/lo
    gemm_mma<0><<<dim3(12, 128), 256, G_SZ>>>(Xh, Xl, Whp, Wlp,
                                              nullptr, nullptr,
                                              Qh, Ql, Kh, Kl, Vh, Vl);

    // attention
    attn_mma<<<dim3(16, 64), 256, ASZ>>>(Qh, Ql, Kh, Kl, Vh, Vl, Chp, Clp);

    // output projection + bias
    gemm_mma<2><<<dim3(4, 128), 256, G_SZ>>>(Chp, Clp, Whp + 3 * 262144, Wlp + 3 * 262144,
                                             bo, out, nullptr, nullptr,
                                             nullptr, nullptr, nullptr, nullptr);
}

// round 9
// speedup vs baseline: 1.6812x; 1.0002x over previous
#include <cuda_runtime.h>
#include <cuda_bf16.h>
#include <stdint.h>
#include <math.h>

#define B_ 8
#define M_ 2048
#define HD_ 512
#define BM_ (B_*M_)
#define SCALE_ 22.62741699796952f   // reference divides by HEAD_DIM**-0.5

typedef __nv_bfloat16 bf16;
typedef __nv_bfloat162 bf162;

// ---------------- device scratch (allocation-free rule) ----------------
__device__ __align__(16) bf16 g_Xh[(size_t)BM_*HD_], g_Xl[(size_t)BM_*HD_];
__device__ __align__(16) bf16 g_Qh[(size_t)BM_*HD_], g_Ql[(size_t)BM_*HD_];
__device__ __align__(16) bf16 g_Kh[(size_t)BM_*HD_], g_Kl[(size_t)BM_*HD_];
__device__ __align__(16) bf16 g_Vh[(size_t)BM_*HD_], g_Vl[(size_t)BM_*HD_];
__device__ __align__(16) bf16 g_Ch[(size_t)BM_*HD_], g_Cl[(size_t)BM_*HD_];
__device__ __align__(16) bf16 g_Wh[4][512*512], g_Wl[4][512*512];   // W^T: [n][k]

// ---------------- helpers ----------------
__device__ __forceinline__ uint32_t smem_u32(const void* p) {
    uint32_t a;
    asm("{ .reg .u64 t; cvta.to.shared.u64 t, %1; cvt.u32.u64 %0, t; }" : "=r"(a) : "l"(p));
    return a;
}
#define SWZ(x) ((uint32_t)(x) ^ ((((uint32_t)(x)) >> 3) & 0x70))

__device__ __forceinline__ void ldm4(uint32_t (&r)[4], uint32_t a) {
    asm volatile("ldmatrix.sync.aligned.m8n8.x4.shared.b16 {%0,%1,%2,%3}, [%4];"
                 : "=r"(r[0]), "=r"(r[1]), "=r"(r[2]), "=r"(r[3]) : "r"(a));
}
__device__ __forceinline__ void ldm4t(uint32_t (&r)[4], uint32_t a) {
    asm volatile("ldmatrix.sync.aligned.m8n8.x4.trans.shared.b16 {%0,%1,%2,%3}, [%4];"
                 : "=r"(r[0]), "=r"(r[1]), "=r"(r[2]), "=r"(r[3]) : "r"(a));
}
__device__ __forceinline__ void mma_bf(float (&d)[4], const uint32_t (&a)[4],
                                       uint32_t b0, uint32_t b1) {
    asm volatile("mma.sync.aligned.m16n8k16.row.col.f32.bf16.bf16.f32 "
                 "{%0,%1,%2,%3}, {%4,%5,%6,%7}, {%8,%9}, {%0,%1,%2,%3};"
                 : "+f"(d[0]), "+f"(d[1]), "+f"(d[2]), "+f"(d[3])
                 : "r"(a[0]), "r"(a[1]), "r"(a[2]), "r"(a[3]), "r"(b0), "r"(b1));
}
__device__ __forceinline__ void splitf(float x, bf16& h, bf16& l) {
    h = __float2bfloat16(x);
    l = __float2bfloat16(x - __bfloat162float(h));
}
__device__ __forceinline__ uint32_t packbf(float a, float b) {
    bf162 t; t.x = __float2bfloat16(a); t.y = __float2bfloat16(b);
    return *(uint32_t*)&t;
}
__device__ __forceinline__ void cpa16(uint32_t dst, const void* src) {
    asm volatile("cp.async.cg.shared.global [%0], [%1], 16;" :: "r"(dst), "l"(src));
}
#define CP_COMMIT() asm volatile("cp.async.commit_group;" ::: "memory")
#define CP_WAIT0()  asm volatile("cp.async.wait_group 0;" ::: "memory")

// ---------------- prep kernels ----------------
__global__ void __launch_bounds__(512) prep_x(const float4* __restrict__ x,
                                              bf16* __restrict__ xh, bf16* __restrict__ xl) {
    size_t i = (size_t)blockIdx.x * 512 + threadIdx.x;
    float4 v = x[i];
    bf16 h0, l0, h1, l1, h2, l2, h3, l3;
    splitf(v.x, h0, l0); splitf(v.y, h1, l1);
    splitf(v.z, h2, l2); splitf(v.w, h3, l3);
    bf162 a, b, c, d;
    a.x = h0; a.y = h1; b.x = h2; b.y = h3;
    c.x = l0; c.y = l1; d.x = l2; d.y = l3;
    *(bf162*)(xh + i * 4) = a; *(bf162*)(xh + i * 4 + 2) = b;
    *(bf162*)(xl + i * 4) = c; *(bf162*)(xl + i * 4 + 2) = d;
}

// coalesced tile-transpose for all 4 weights: W[k][n] -> W^T[n][k] hi/lo
__global__ void __launch_bounds__(256) prep_w4(
    const float* __restrict__ W0, const float* __restrict__ W1,
    const float* __restrict__ W2, const float* __restrict__ W3,
    bf16* __restrict__ th, bf16* __restrict__ tl) {
    __shared__ float t[32][33];
    const int w = blockIdx.z;
    const float* W = (w == 0) ? W0 : (w == 1) ? W1 : (w == 2) ? W2 : W3;
    bf16* thw = th + (size_t)w * 262144;
    bf16* tlw = tl + (size_t)w * 262144;
    const int bx = blockIdx.x * 32;   // n-block
    const int by = blockIdx.y * 32;   // k-block
    const int tx = threadIdx.x, ty = threadIdx.y;
#pragma unroll
    for (int j = ty; j < 32; j += 8)
        t[j][tx] = W[(size_t)(by + j) * 512 + bx + tx];
    __syncthreads();
#pragma unroll
    for (int j = ty; j < 32; j += 8) {
        float v = t[tx][j];
        bf16 h, l; splitf(v, h, l);
        thw[(size_t)(bx + j) * 512 + by + tx] = h;
        tlw[(size_t)(bx + j) * 512 + by + tx] = l;
    }
}

// ===========================================================================
// GEMM via mma.sync, cp.async double-buffered.
// CTA 128x128, 8 warps (2x4), warp tile 64x32, split-bf16 3-pass.
// MODE 0 (fused QKV): blockIdx.x selects W/output. MODE 2: fp32 + bias.
// ===========================================================================
#define GS(c)   ((c) * 65536)
#define G_AH(c) (GS(c) + 0)
#define G_AL(c) (GS(c) + 16384)
#define G_BH(c) (GS(c) + 32768)
#define G_BL(c) (GS(c) + 49152)
#define G_SZ    131072

template <int MODE>
__global__ void __launch_bounds__(256, 1) gemm_mma(
    const bf16* __restrict__ Ah_, const bf16* __restrict__ Al_,
    const bf16* __restrict__ WhB, const bf16* __restrict__ WlB,
    const float* __restrict__ bias, float* __restrict__ out32,
    bf16* __restrict__ oh0, bf16* __restrict__ ol0,
    bf16* __restrict__ oh1, bf16* __restrict__ ol1,
    bf16* __restrict__ oh2, bf16* __restrict__ ol2)
{
    extern __shared__ char sm[];
    const uint32_t sb = smem_u32(sm);
    const int tid = threadIdx.x, warp = tid >> 5, lane = tid & 31;
    const int wm = warp >> 2, wn = warp & 3;
    const int lr = lane & 7, g = lane >> 3;
    const int offAr = (g & 1) * 8 + lr, offAc = (g >> 1) * 8;
    const int offBr = (g >> 1) * 8 + lr, offBc = (g & 1) * 8;

    const int widx = (MODE == 0) ? (blockIdx.x >> 2) : 0;    // which W / output
    const int n0 = (MODE == 0) ? ((blockIdx.x & 3) * 128) : (blockIdx.x * 128);
    const int m0 = blockIdx.y * 128;
    const bf16* Bh_ = WhB + (size_t)widx * 262144;
    const bf16* Bl_ = WlB + (size_t)widx * 262144;

    // prologue: chunk 0
#pragma unroll
    for (int i = 0; i < 4; i++) {
        int t = i * 256 + tid, row = t >> 3, cb = (t & 7) * 16;
        uint32_t dsw = SWZ(row * 128 + cb);
        size_t abyte = ((size_t)(m0 + row) * 512) * 2 + cb;
        size_t bbyte = ((size_t)(n0 + row) * 512) * 2 + cb;
        cpa16(sb + G_AH(0) + dsw, (const char*)Ah_ + abyte);
        cpa16(sb + G_AL(0) + dsw, (const char*)Al_ + abyte);
        cpa16(sb + G_BH(0) + dsw, (const char*)Bh_ + bbyte);
        cpa16(sb + G_BL(0) + dsw, (const char*)Bl_ + bbyte);
    }
    CP_COMMIT();

    float acc[4][4][4];
#pragma unroll
    for (int a = 0; a < 4; a++)
#pragma unroll
        for (int b = 0; b < 4; b++)
#pragma unroll
            for (int c = 0; c < 4; c++) acc[a][b][c] = 0.0f;

    for (int ch = 0; ch < 8; ch++) {
        const int c = ch & 1;
        CP_WAIT0();
        __syncthreads();          // buf c ready; all warps done with buf c^1

        if (ch < 7) {             // prefetch ch+1 into buf c^1
#pragma unroll
            for (int i = 0; i < 4; i++) {
                int t = i * 256 + tid, row = t >> 3, cb = (t & 7) * 16;
                uint32_t dsw = SWZ(row * 128 + cb);
                size_t abyte = ((size_t)(m0 + row) * 512 + (ch + 1) * 64) * 2 + cb;
                size_t bbyte = ((size_t)(n0 + row) * 512 + (ch + 1) * 64) * 2 + cb;
                cpa16(sb + G_AH(c ^ 1) + dsw, (const char*)Ah_ + abyte);
                cpa16(sb + G_AL(c ^ 1) + dsw, (const char*)Al_ + abyte);
                cpa16(sb + G_BH(c ^ 1) + dsw, (const char*)Bh_ + bbyte);
                cpa16(sb + G_BL(c ^ 1) + dsw, (const char*)Bl_ + bbyte);
            }
            CP_COMMIT();
        }

#pragma unroll
        for (int ks = 0; ks < 4; ks++) {
            uint32_t bhF[2][4], blF[2][4];
#pragma unroll
            for (int np = 0; np < 2; np++) {
                uint32_t boff = SWZ((wn * 32 + np * 16 + offBr) * 128 + (ks * 16 + offBc) * 2);
                ldm4(bhF[np], sb + G_BH(c) + boff);
                ldm4(blF[np], sb + G_BL(c) + boff);
            }
#pragma unroll
            for (int mf = 0; mf < 4; mf++) {
                uint32_t aoff = SWZ((wm * 64 + mf * 16 + offAr) * 128 + (ks * 16 + offAc) * 2);
                uint32_t ah2[4], al2[4];
                ldm4(ah2, sb + G_AH(c) + aoff);
                ldm4(al2, sb + G_AL(c) + aoff);
#pragma unroll
                for (int nf = 0; nf < 4; nf++) {
                    int np = nf >> 1, hh = nf & 1;
                    uint32_t b0h = bhF[np][hh * 2], b1h = bhF[np][hh * 2 + 1];
                    uint32_t b0l = blF[np][hh * 2], b1l = blF[np][hh * 2 + 1];
                    mma_bf(acc[mf][nf], ah2, b0h, b1h);
                    mma_bf(acc[mf][nf], ah2, b0l, b1l);
                    mma_bf(acc[mf][nf], al2, b0h, b1h);
                }
            }
        }
    }

    bf16* oh = (MODE == 0) ? ((widx == 0) ? oh0 : (widx == 1) ? oh1 : oh2) : oh0;
    bf16* ol = (MODE == 0) ? ((widx == 0) ? ol0 : (widx == 1) ? ol1 : ol2) : ol0;

#pragma unroll
    for (int mf = 0; mf < 4; mf++) {
        int rlo = m0 + wm * 64 + mf * 16 + (lane >> 2);
        int rhi = rlo + 8;
#pragma unroll
        for (int nf = 0; nf < 4; nf++) {
            int n = n0 + wn * 32 + nf * 8 + (lane & 3) * 2;
            if (MODE == 2) {
                float2 v0, v1;
                v0.x = acc[mf][nf][0] + bias[n]; v0.y = acc[mf][nf][1] + bias[n + 1];
                v1.x = acc[mf][nf][2] + bias[n]; v1.y = acc[mf][nf][3] + bias[n + 1];
                *(float2*)(out32 + (size_t)rlo * 512 + n) = v0;
                *(float2*)(out32 + (size_t)rhi * 512 + n) = v1;
            } else {
                int h = n >> 6, d = n & 63;
                {
                    int b = rlo >> 11, mm = rlo & 2047;
                    size_t base = ((size_t)(b * 8 + h) * 2048 + mm) * 64 + d;
                    bf16 h0, l0, h1, l1;
                    splitf(acc[mf][nf][0], h0, l0); splitf(acc[mf][nf][1], h1, l1);
                    bf162 t, u; t.x = h0; t.y = h1; u.x = l0; u.y = l1;
                    *(bf162*)(oh + base) = t; *(bf162*)(ol + base) = u;
                }
                {
                    int b = rhi >> 11, mm = rhi & 2047;
                    size_t base = ((size_t)(b * 8 + h) * 2048 + mm) * 64 + d;
                    bf16 h0, l0, h1, l1;
                    splitf(acc[mf][nf][2], h0, l0); splitf(acc[mf][nf][3], h1, l1);
                    bf162 t, u; t.x = h0; t.y = h1; u.x = l0; u.y = l1;
                    *(bf162*)(oh + base) = t; *(bf162*)(ol + base) = u;
                }
            }
        }
    }
}

// ===========================================================================
// Flash attention, FA2 register-P + split-k softmax (no mid-iter barrier).
// 256 threads, 8 warps: wm = warp>>1 (4 row-groups), wn = warp&1 (2 key-chunks).
// Each wn warp keeps private running max/l over its 1024 keys; merged ONCE
// after the loop (flash-decode style). One barrier per iter (double buffer).
// Near-one-hot tile skip: if a 16-row x 32-key tile is uniformly 25 below the
// running max, its exp+PV contribution (< e^-25) is skipped.
// ===========================================================================
#define AQH 0
#define AQL 16384
#define AKH(c) (32768 + (c)*32768)
#define AKL(c) (32768 + (c)*32768 + 8192)
#define AVH(c) (32768 + (c)*32768 + 16384)
#define AVL(c) (32768 + (c)*32768 + 24576)
#define AOB  32768              // aliases KV buffers (used only post-loop)
#define AML  98304              // [2][128] m, then [2][128] l  (2 KB)
#define ASZ  100352

__global__ void __launch_bounds__(256, 1) attn_mma(
    const bf16* __restrict__ Qh, const bf16* __restrict__ Ql,
    const bf16* __restrict__ Kh, const bf16* __restrict__ Kl,
    const bf16* __restrict__ Vh, const bf16* __restrict__ Vl,
    bf16* __restrict__ Ch, bf16* __restrict__ Cl)
{
    extern __shared__ char sm[];
    const uint32_t sb = smem_u32(sm);
    float* mbuf = (float*)(sm + AML);        // [2][128]
    float* lbuf = mbuf + 256;                // [2][128]
    float* obuf = (float*)(sm + AOB);        // [128][66], post-loop only

    const int tid = threadIdx.x, warp = tid >> 5, lane = tid & 31;
    const int wm = warp >> 1, wn = warp & 1;
    const int lr = lane & 7, g = lane >> 3;
    const int offAr = (g & 1) * 8 + lr, offAc = (g >> 1) * 8;
    const int offBr = (g >> 1) * 8 + lr, offBc = (g & 1) * 8;
    const int bh = blockIdx.y, q0 = blockIdx.x * 128;

    const char* khb = (const char*)Kh + ((size_t)bh * 2048) * 128;
    const char* klb = (const char*)Kl + ((size_t)bh * 2048) * 128;
    const char* vhb = (const char*)Vh + ((size_t)bh * 2048) * 128;
    const char* vlb = (const char*)Vl + ((size_t)bh * 2048) * 128;

    // Q tiles (hi/lo), 128x64 into smem
    {
        const char* qhp = (const char*)Qh + ((size_t)bh * 2048 + q0) * 128;
        const char* qlp = (const char*)Ql + ((size_t)bh * 2048 + q0) * 128;
#pragma unroll
        for (int i = 0; i < 4; i++) {
            int t = i * 256 + tid, row = t >> 3, cb = (t & 7) * 16;
            uint32_t dsw = SWZ(row * 128 + cb);
            *(uint4*)(sm + AQH + dsw) = *(const uint4*)(qhp + row * 128 + cb);
            *(uint4*)(sm + AQL + dsw) = *(const uint4*)(qlp + row * 128 + cb);
        }
    }

    // prologue: kt=0 loads into buf 0
#pragma unroll
    for (int i = 0; i < 2; i++) {
        int t = i * 256 + tid, row = t >> 3, cb = (t & 7) * 16;
        uint32_t dsw = SWZ(row * 128 + cb);
        size_t go = (size_t)row * 128 + cb;
        cpa16(sb + AKH(0) + dsw, khb + go);
        cpa16(sb + AKL(0) + dsw, klb + go);
        cpa16(sb + AVH(0) + dsw, vhb + go);
        cpa16(sb + AVL(0) + dsw, vlb + go);
    }
    CP_COMMIT();
    __syncthreads();   // Q smem visible

    // hoist Q-hi fragments (loop-invariant)
    uint32_t qfh[4][2][4];
#pragma unroll
    for (int ks = 0; ks < 4; ks++)
#pragma unroll
        for (int mf = 0; mf < 2; mf++) {
            uint32_t aoff = SWZ((wm * 32 + mf * 16 + offAr) * 128 + (ks * 16 + offAc) * 2);
            ldm4(qfh[ks][mf], sb + AQH + aoff);
        }

    float oacc[2][8][4];
#pragma unroll
    for (int a = 0; a < 2; a++)
#pragma unroll
        for (int b = 0; b < 8; b++)
#pragma unroll
            for (int c = 0; c < 4; c++) oacc[a][b][c] = 0.0f;
    float m_prev[4], l_part[4];
#pragma unroll
    for (int r = 0; r < 4; r++) { m_prev[r] = -INFINITY; l_part[r] = 0.0f; }

    for (int kt = 0; kt < 32; kt++) {
        const int c = kt & 1;
        CP_WAIT0();
        __syncthreads();   // buf c ready + all warps done reading buf c

        if (kt < 31) {     // prefetch kt+1 into buf c^1
            size_t tb = (size_t)(kt + 1) * 64 * 128;
#pragma unroll
            for (int i = 0; i < 2; i++) {
                int t = i * 256 + tid, row = t >> 3, cb = (t & 7) * 16;
                uint32_t dsw = SWZ(row * 128 + cb);
                size_t go = tb + (size_t)row * 128 + cb;
                cpa16(sb + AKH(c ^ 1) + dsw, khb + go);
                cpa16(sb + AKL(c ^ 1) + dsw, klb + go);
                cpa16(sb + AVH(c ^ 1) + dsw, vhb + go);
                cpa16(sb + AVL(c ^ 1) + dsw, vlb + go);
            }
            CP_COMMIT();
        }

        // ---- S = Q K^T : warp computes S[32 rows x 32 own keys] ----
        float sacc[2][4][4];
#pragma unroll
        for (int a = 0; a < 2; a++)
#pragma unroll
            for (int b = 0; b < 4; b++)
#pragma unroll
                for (int e = 0; e < 4; e++) sacc[a][b][e] = 0.0f;

#pragma unroll
        for (int ks = 0; ks < 4; ks++) {
            uint32_t kh2[2][4], kl2[2][4];
#pragma unroll
            for (int kg = 0; kg < 2; kg++) {
                uint32_t boff = SWZ((wn * 32 + kg * 16 + offBr) * 128 + (ks * 16 + offBc) * 2);
                ldm4(kh2[kg], sb + AKH(c) + boff);
                ldm4(kl2[kg], sb + AKL(c) + boff);
            }
#pragma unroll
            for (int mf = 0; mf < 2; mf++) {
                uint32_t aoff = SWZ((wm * 32 + mf * 16 + offAr) * 128 + (ks * 16 + offAc) * 2);
                uint32_t ql2[4];
                ldm4(ql2, sb + AQL + aoff);
#pragma unroll
                for (int nf = 0; nf < 4; nf++) {
                    int kg = nf >> 1, hh = nf & 1;
                    mma_bf(sacc[mf][nf], qfh[ks][mf], kh2[kg][hh * 2], kh2[kg][hh * 2 + 1]);
                    mma_bf(sacc[mf][nf], qfh[ks][mf], kl2[kg][hh * 2], kl2[kg][hh * 2 + 1]);
                    mma_bf(sacc[mf][nf], ql2,         kh2[kg][hh * 2], kh2[kg][hh * 2 + 1]);
                }
            }
        }

        // ---- warp-local softmax (no barrier): scale, max, skip-vote, exp ----
        bool dopv[2];
        uint32_t pa[2][2][4];
#pragma unroll
        for (int mf = 0; mf < 2; mf++) {
            float mlo = -INFINITY, mhi = -INFINITY;
#pragma unroll
            for (int nf = 0; nf < 4; nf++) {
#pragma unroll
                for (int e = 0; e < 4; e++) sacc[mf][nf][e] *= SCALE_;
                mlo = fmaxf(mlo, fmaxf(sacc[mf][nf][0], sacc[mf][nf][1]));
                mhi = fmaxf(mhi, fmaxf(sacc[mf][nf][2], sacc[mf][nf][3]));
            }
            mlo = fmaxf(mlo, __shfl_xor_sync(0xffffffffu, mlo, 1));
            mlo = fmaxf(mlo, __shfl_xor_sync(0xffffffffu, mlo, 2));
            mhi = fmaxf(mhi, __shfl_xor_sync(0xffffffffu, mhi, 1));
            mhi = fmaxf(mhi, __shfl_xor_sync(0xffffffffu, mhi, 2));

            bool skipL = (mlo < m_prev[mf * 2] - 25.0f) &&
                         (mhi < m_prev[mf * 2 + 1] - 25.0f);
            dopv[mf] = (__ballot_sync(0xffffffffu, skipL) != 0xffffffffu);
            if (!dopv[mf]) continue;    // tile < e^-25: contribution negligible

            float ml = fmaxf(m_prev[mf * 2], mlo);
            float mh2 = fmaxf(m_prev[mf * 2 + 1], mhi);
            float slo = 0.0f, shi = 0.0f;
            float pv[4][4];
#pragma unroll
            for (int nf = 0; nf < 4; nf++) {
                pv[nf][0] = __expf(sacc[mf][nf][0] - ml);
                pv[nf][1] = __expf(sacc[mf][nf][1] - ml);
                pv[nf][2] = __expf(sacc[mf][nf][2] - mh2);
                pv[nf][3] = __expf(sacc[mf][nf][3] - mh2);
                slo += pv[nf][0] + pv[nf][1];
                shi += pv[nf][2] + pv[nf][3];
            }
#pragma unroll
            for (int k2 = 0; k2 < 2; k2++) {
                pa[mf][k2][0] = packbf(pv[2 * k2][0], pv[2 * k2][1]);
                pa[mf][k2][1] = packbf(pv[2 * k2][2], pv[2 * k2][3]);
                pa[mf][k2][2] = packbf(pv[2 * k2 + 1][0], pv[2 * k2 + 1][1]);
                pa[mf][k2][3] = packbf(pv[2 * k2 + 1][2], pv[2 * k2 + 1][3]);
            }
            float cl_ = __expf(m_prev[mf * 2] - ml);
            float ch_ = __expf(m_prev[mf * 2 + 1] - mh2);
            l_part[mf * 2]     = l_part[mf * 2] * cl_ + slo;
            l_part[mf * 2 + 1] = l_part[mf * 2 + 1] * ch_ + shi;
            m_prev[mf * 2] = ml; m_prev[mf * 2 + 1] = mh2;
#pragma unroll
            for (int nj = 0; nj < 8; nj++) {
                oacc[mf][nj][0] *= cl_; oacc[mf][nj][1] *= cl_;
                oacc[mf][nj][2] *= ch_; oacc[mf][nj][3] *= ch_;
            }
        }

        // ---- PV: O_partial[32x64] += P(regs) * V(own 32 keys) ----
        if (dopv[0] || dopv[1]) {
#pragma unroll
            for (int k2 = 0; k2 < 2; k2++) {
                uint32_t vh[4][4], vl[4][4];
#pragma unroll
                for (int j = 0; j < 4; j++) {
                    uint32_t voff = SWZ((wn * 32 + k2 * 16 + offAr) * 128 + (j * 16 + offAc) * 2);
                    ldm4t(vh[j], sb + AVH(c) + voff);
                    ldm4t(vl[j], sb + AVL(c) + voff);
                }
#pragma unroll
                for (int mf = 0; mf < 2; mf++) {
                    if (!dopv[mf]) continue;
#pragma unroll
                    for (int j = 0; j < 4; j++) {
#pragma unroll
                        for (int hh = 0; hh < 2; hh++) {
                            int nj = j * 2 + hh;
                            mma_bf(oacc[mf][nj], pa[mf][k2], vh[j][hh * 2], vh[j][hh * 2 + 1]);
                            mma_bf(oacc[mf][nj], pa[mf][k2], vl[j][hh * 2], vl[j][hh * 2 + 1]);
                        }
                    }
                }
            }
        }
    }

    // ---- split-k merge: wn partials -> final O ----
    __syncthreads();   // all PV reads done; KV smem now reusable as obuf

    // per-warp l reduce (quad) + stage m/l; wn==1 stages its O partial
#pragma unroll
    for (int mf = 0; mf < 2; mf++) {
        float slo = l_part[mf * 2], shi = l_part[mf * 2 + 1];
        slo += __shfl_xor_sync(0xffffffffu, slo, 1);
        slo += __shfl_xor_sync(0xffffffffu, slo, 2);
        shi += __shfl_xor_sync(0xffffffffu, shi, 1);
        shi += __shfl_xor_sync(0xffffffffu, shi, 2);
        l_part[mf * 2] = slo; l_part[mf * 2 + 1] = shi;
        if ((lane & 3) == 0) {
            int rl = wm * 32 + mf * 16 + (lane >> 2);
            mbuf[wn * 128 + rl] = m_prev[mf * 2];
            mbuf[wn * 128 + rl + 8] = m_prev[mf * 2 + 1];
            lbuf[wn * 128 + rl] = slo;
            lbuf[wn * 128 + rl + 8] = shi;
        }
    }
    if (wn == 1) {
#pragma unroll
        for (int mf = 0; mf < 2; mf++) {
            int rl = wm * 32 + mf * 16 + (lane >> 2), rh = rl + 8;
#pragma unroll
            for (int nj = 0; nj < 8; nj++) {
                int col = nj * 8 + (lane & 3) * 2;
                *(float2*)(obuf + rl * 66 + col) = make_float2(oacc[mf][nj][0], oacc[mf][nj][1]);
                *(float2*)(obuf + rh * 66 + col) = make_float2(oacc[mf][nj][2], oacc[mf][nj][3]);
            }
        }
    }
    __syncthreads();

    // ---- epilogue (wn==0): O = w0*O0 + w1*O1, /= l, write hi/lo ----
    if (wn == 0) {
        const int b = bh >> 3, h = bh & 7;
#pragma unroll
        for (int mf = 0; mf < 2; mf++) {
            int rl = wm * 32 + mf * 16 + (lane >> 2), rh = rl + 8;
            float m0l = m_prev[mf * 2],     m1l = mbuf[128 + rl];
            float m0h = m_prev[mf * 2 + 1], m1h = mbuf[128 + rh];
            float mL = fmaxf(m0l, m1l), mH = fmaxf(m0h, m1h);
            float w0l = __expf(m0l - mL), w1l = __expf(m1l - mL);
            float w0h = __expf(m0h - mH), w1h = __expf(m1h - mH);
            float il = 1.0f / (l_part[mf * 2] * w0l + lbuf[128 + rl] * w1l);
            float ih = 1.0f / (l_part[mf * 2 + 1] * w0h + lbuf[128 + rh] * w1h);
#pragma unroll
            for (int nj = 0; nj < 8; nj++) {
                int col = nj * 8 + (lane & 3) * 2;
                float2 s0 = *(float2*)(obuf + rl * 66 + col);
                float2 s1 = *(float2*)(obuf + rh * 66 + col);
                float v0 = (oacc[mf][nj][0] * w0l + s0.x * w1l) * il;
                float v1 = (oacc[mf][nj][1] * w0l + s0.y * w1l) * il;
                float v2 = (oacc[mf][nj][2] * w0h + s1.x * w1h) * ih;
                float v3 = (oacc[mf][nj][3] * w0h + s1.y * w1h) * ih;
                size_t blo = ((size_t)b * 2048 + q0 + rl) * 512 + h * 64 + col;
                size_t bhi = ((size_t)b * 2048 + q0 + rh) * 512 + h * 64 + col;
                bf16 x0, y0, x1, y1;
                splitf(v0, x0, y0); splitf(v1, x1, y1);
                bf162 t, u; t.x = x0; t.y = x1; u.x = y0; u.y = y1;
                *(bf162*)(Ch + blo) = t; *(bf162*)(Cl + blo) = u;
                splitf(v2, x0, y0); splitf(v3, x1, y1);
                t.x = x0; t.y = x1; u.x = y0; u.y = y1;
                *(bf162*)(Ch + bhi) = t; *(bf162*)(Cl + bhi) = u;
            }
        }
    }
}

// ---------------------------------------------------------------------------
extern "C" void kernel_launch(void* const* d_in, const int* in_sizes, int n_in,
                              void* d_out, int out_size)
{
    const float* x  = (const float*)d_in[0];
    const float* Wq = (const float*)d_in[1];
    const float* Wk = (const float*)d_in[2];
    const float* Wv = (const float*)d_in[3];
    const float* Wo = (const float*)d_in[4];
    const float* bo = (const float*)d_in[5];
    float* out = (float*)d_out;

    bf16 *Xh, *Xl, *Qh, *Ql, *Kh, *Kl, *Vh, *Vl, *Chp, *Clp, *Whp, *Wlp;
    cudaGetSymbolAddress((void**)&Xh, g_Xh);  cudaGetSymbolAddress((void**)&Xl, g_Xl);
    cudaGetSymbolAddress((void**)&Qh, g_Qh);  cudaGetSymbolAddress((void**)&Ql, g_Ql);
    cudaGetSymbolAddress((void**)&Kh, g_Kh);  cudaGetSymbolAddress((void**)&Kl, g_Kl);
    cudaGetSymbolAddress((void**)&Vh, g_Vh);  cudaGetSymbolAddress((void**)&Vl, g_Vl);
    cudaGetSymbolAddress((void**)&Chp, g_Ch); cudaGetSymbolAddress((void**)&Clp, g_Cl);
    cudaGetSymbolAddress((void**)&Whp, g_Wh); cudaGetSymbolAddress((void**)&Wlp, g_Wl);

    cudaFuncSetAttribute(gemm_mma<0>, cudaFuncAttributeMaxDynamicSharedMemorySize, G_SZ);
    cudaFuncSetAttribute(gemm_mma<2>, cudaFuncAttributeMaxDynamicSharedMemorySize, G_SZ);
    cudaFuncSetAttribute(attn_mma, cudaFuncAttributeMaxDynamicSharedMemorySize, ASZ);

    // prep
    prep_x<<<(BM_ * HD_ / 4) / 512, 512>>>((const float4*)x, Xh, Xl);
    dim3 wblk(32, 8), wgrd(16, 16, 4);
    prep_w4<<<wgrd, wblk>>>(Wq, Wk, Wv, Wo, Whp, Wlp);

    // fused QKV projections -> [b,h,m,d] hi/lo
    gemm_mma<0><<<dim3(12, 128), 256, G_SZ>>>(Xh, Xl, Whp, Wlp,
                                              nullptr, nullptr,
                                              Qh, Ql, Kh, Kl, Vh, Vl);

    // attention
    attn_mma<<<dim3(16, 64), 256, ASZ>>>(Qh, Ql, Kh, Kl, Vh, Vl, Chp, Clp);

    // output projection + bias
    gemm_mma<2><<<dim3(4, 128), 256, G_SZ>>>(Chp, Clp, Whp + 3 * 262144, Wlp + 3 * 262144,
                                             bo, out, nullptr, nullptr,
                                             nullptr, nullptr, nullptr, nullptr);
}

// round 10
// speedup vs baseline: 1.7552x; 1.0440x over previous
#include <cuda_runtime.h>
#include <cuda_bf16.h>
#include <stdint.h>
#include <math.h>

#define B_ 8
#define M_ 2048
#define HD_ 512
#define BM_ (B_*M_)
#define SCALE_ 22.62741699796952f   // reference divides by HEAD_DIM**-0.5

typedef __nv_bfloat16 bf16;
typedef __nv_bfloat162 bf162;

// ---------------- device scratch (allocation-free rule) ----------------
__device__ __align__(16) bf16 g_Xh[(size_t)BM_*HD_], g_Xl[(size_t)BM_*HD_];
__device__ __align__(16) bf16 g_Qh[(size_t)BM_*HD_], g_Ql[(size_t)BM_*HD_];
__device__ __align__(16) bf16 g_Kh[(size_t)BM_*HD_], g_Kl[(size_t)BM_*HD_];
__device__ __align__(16) bf16 g_Vh[(size_t)BM_*HD_], g_Vl[(size_t)BM_*HD_];
__device__ __align__(16) bf16 g_Ch[(size_t)BM_*HD_], g_Cl[(size_t)BM_*HD_];
__device__ __align__(16) bf16 g_Wh[4][512*512], g_Wl[4][512*512];   // W^T: [n][k]

// ---------------- helpers ----------------
__device__ __forceinline__ uint32_t smem_u32(const void* p) {
    uint32_t a;
    asm("{ .reg .u64 t; cvta.to.shared.u64 t, %1; cvt.u32.u64 %0, t; }" : "=r"(a) : "l"(p));
    return a;
}
#define SWZ(x) ((uint32_t)(x) ^ ((((uint32_t)(x)) >> 3) & 0x70))

__device__ __forceinline__ void ldm4(uint32_t (&r)[4], uint32_t a) {
    asm volatile("ldmatrix.sync.aligned.m8n8.x4.shared.b16 {%0,%1,%2,%3}, [%4];"
                 : "=r"(r[0]), "=r"(r[1]), "=r"(r[2]), "=r"(r[3]) : "r"(a));
}
__device__ __forceinline__ void ldm4t(uint32_t (&r)[4], uint32_t a) {
    asm volatile("ldmatrix.sync.aligned.m8n8.x4.trans.shared.b16 {%0,%1,%2,%3}, [%4];"
                 : "=r"(r[0]), "=r"(r[1]), "=r"(r[2]), "=r"(r[3]) : "r"(a));
}
__device__ __forceinline__ void mma_bf(float (&d)[4], const uint32_t (&a)[4],
                                       uint32_t b0, uint32_t b1) {
    asm volatile("mma.sync.aligned.m16n8k16.row.col.f32.bf16.bf16.f32 "
                 "{%0,%1,%2,%3}, {%4,%5,%6,%7}, {%8,%9}, {%0,%1,%2,%3};"
                 : "+f"(d[0]), "+f"(d[1]), "+f"(d[2]), "+f"(d[3])
                 : "r"(a[0]), "r"(a[1]), "r"(a[2]), "r"(a[3]), "r"(b0), "r"(b1));
}
__device__ __forceinline__ void splitf(float x, bf16& h, bf16& l) {
    h = __float2bfloat16(x);
    l = __float2bfloat16(x - __bfloat162float(h));
}
__device__ __forceinline__ uint32_t packbf(float a, float b) {
    bf162 t; t.x = __float2bfloat16(a); t.y = __float2bfloat16(b);
    return *(uint32_t*)&t;
}
__device__ __forceinline__ void cpa16(uint32_t dst, const void* src) {
    asm volatile("cp.async.cg.shared.global [%0], [%1], 16;" :: "r"(dst), "l"(src));
}
#define CP_COMMIT() asm volatile("cp.async.commit_group;" ::: "memory")
#define CP_WAIT0()  asm volatile("cp.async.wait_group 0;" ::: "memory")

// ---------------- prep kernels ----------------
__global__ void __launch_bounds__(512) prep_x(const float4* __restrict__ x,
                                              bf16* __restrict__ xh, bf16* __restrict__ xl) {
    size_t i = (size_t)blockIdx.x * 512 + threadIdx.x;
    float4 v = x[i];
    bf16 h0, l0, h1, l1, h2, l2, h3, l3;
    splitf(v.x, h0, l0); splitf(v.y, h1, l1);
    splitf(v.z, h2, l2); splitf(v.w, h3, l3);
    bf162 a, b, c, d;
    a.x = h0; a.y = h1; b.x = h2; b.y = h3;
    c.x = l0; c.y = l1; d.x = l2; d.y = l3;
    *(bf162*)(xh + i * 4) = a; *(bf162*)(xh + i * 4 + 2) = b;
    *(bf162*)(xl + i * 4) = c; *(bf162*)(xl + i * 4 + 2) = d;
}

// coalesced tile-transpose for all 4 weights: W[k][n] -> W^T[n][k] hi/lo
__global__ void __launch_bounds__(256) prep_w4(
    const float* __restrict__ W0, const float* __restrict__ W1,
    const float* __restrict__ W2, const float* __restrict__ W3,
    bf16* __restrict__ th, bf16* __restrict__ tl) {
    __shared__ float t[32][33];
    const int w = blockIdx.z;
    const float* W = (w == 0) ? W0 : (w == 1) ? W1 : (w == 2) ? W2 : W3;
    bf16* thw = th + (size_t)w * 262144;
    bf16* tlw = tl + (size_t)w * 262144;
    const int bx = blockIdx.x * 32;   // n-block
    const int by = blockIdx.y * 32;   // k-block
    const int tx = threadIdx.x, ty = threadIdx.y;
#pragma unroll
    for (int j = ty; j < 32; j += 8)
        t[j][tx] = W[(size_t)(by + j) * 512 + bx + tx];
    __syncthreads();
#pragma unroll
    for (int j = ty; j < 32; j += 8) {
        float v = t[tx][j];
        bf16 h, l; splitf(v, h, l);
        thw[(size_t)(bx + j) * 512 + by + tx] = h;
        tlw[(size_t)(bx + j) * 512 + by + tx] = l;
    }
}

// ===========================================================================
// GEMM via mma.sync, cp.async double-buffered.
// CTA 128x128, 8 warps (2x4), warp tile 64x32, split-bf16 3-pass.
// MODE 0 (fused QKV): blockIdx.x selects W/output. MODE 2: fp32 + bias.
// ===========================================================================
#define GS(c)   ((c) * 65536)
#define G_AH(c) (GS(c) + 0)
#define G_AL(c) (GS(c) + 16384)
#define G_BH(c) (GS(c) + 32768)
#define G_BL(c) (GS(c) + 49152)
#define G_SZ    131072

template <int MODE>
__global__ void __launch_bounds__(256, 1) gemm_mma(
    const bf16* __restrict__ Ah_, const bf16* __restrict__ Al_,
    const bf16* __restrict__ WhB, const bf16* __restrict__ WlB,
    const float* __restrict__ bias, float* __restrict__ out32,
    bf16* __restrict__ oh0, bf16* __restrict__ ol0,
    bf16* __restrict__ oh1, bf16* __restrict__ ol1,
    bf16* __restrict__ oh2, bf16* __restrict__ ol2)
{
    extern __shared__ char sm[];
    const uint32_t sb = smem_u32(sm);
    const int tid = threadIdx.x, warp = tid >> 5, lane = tid & 31;
    const int wm = warp >> 2, wn = warp & 3;
    const int lr = lane & 7, g = lane >> 3;
    const int offAr = (g & 1) * 8 + lr, offAc = (g >> 1) * 8;
    const int offBr = (g >> 1) * 8 + lr, offBc = (g & 1) * 8;

    const int widx = (MODE == 0) ? (blockIdx.x >> 2) : 0;    // which W / output
    const int n0 = (MODE == 0) ? ((blockIdx.x & 3) * 128) : (blockIdx.x * 128);
    const int m0 = blockIdx.y * 128;
    const bf16* Bh_ = WhB + (size_t)widx * 262144;
    const bf16* Bl_ = WlB + (size_t)widx * 262144;

    // prologue: chunk 0
#pragma unroll
    for (int i = 0; i < 4; i++) {
        int t = i * 256 + tid, row = t >> 3, cb = (t & 7) * 16;
        uint32_t dsw = SWZ(row * 128 + cb);
        size_t abyte = ((size_t)(m0 + row) * 512) * 2 + cb;
        size_t bbyte = ((size_t)(n0 + row) * 512) * 2 + cb;
        cpa16(sb + G_AH(0) + dsw, (const char*)Ah_ + abyte);
        cpa16(sb + G_AL(0) + dsw, (const char*)Al_ + abyte);
        cpa16(sb + G_BH(0) + dsw, (const char*)Bh_ + bbyte);
        cpa16(sb + G_BL(0) + dsw, (const char*)Bl_ + bbyte);
    }
    CP_COMMIT();

    float acc[4][4][4];
#pragma unroll
    for (int a = 0; a < 4; a++)
#pragma unroll
        for (int b = 0; b < 4; b++)
#pragma unroll
            for (int c = 0; c < 4; c++) acc[a][b][c] = 0.0f;

    for (int ch = 0; ch < 8; ch++) {
        const int c = ch & 1;
        CP_WAIT0();
        __syncthreads();          // buf c ready; all warps done with buf c^1

        if (ch < 7) {             // prefetch ch+1 into buf c^1
#pragma unroll
            for (int i = 0; i < 4; i++) {
                int t = i * 256 + tid, row = t >> 3, cb = (t & 7) * 16;
                uint32_t dsw = SWZ(row * 128 + cb);
                size_t abyte = ((size_t)(m0 + row) * 512 + (ch + 1) * 64) * 2 + cb;
                size_t bbyte = ((size_t)(n0 + row) * 512 + (ch + 1) * 64) * 2 + cb;
                cpa16(sb + G_AH(c ^ 1) + dsw, (const char*)Ah_ + abyte);
                cpa16(sb + G_AL(c ^ 1) + dsw, (const char*)Al_ + abyte);
                cpa16(sb + G_BH(c ^ 1) + dsw, (const char*)Bh_ + bbyte);
                cpa16(sb + G_BL(c ^ 1) + dsw, (const char*)Bl_ + bbyte);
            }
            CP_COMMIT();
        }

#pragma unroll
        for (int ks = 0; ks < 4; ks++) {
            uint32_t bhF[2][4], blF[2][4];
#pragma unroll
            for (int np = 0; np < 2; np++) {
                uint32_t boff = SWZ((wn * 32 + np * 16 + offBr) * 128 + (ks * 16 + offBc) * 2);
                ldm4(bhF[np], sb + G_BH(c) + boff);
                ldm4(blF[np], sb + G_BL(c) + boff);
            }
#pragma unroll
            for (int mf = 0; mf < 4; mf++) {
                uint32_t aoff = SWZ((wm * 64 + mf * 16 + offAr) * 128 + (ks * 16 + offAc) * 2);
                uint32_t ah2[4], al2[4];
                ldm4(ah2, sb + G_AH(c) + aoff);
                ldm4(al2, sb + G_AL(c) + aoff);
#pragma unroll
                for (int nf = 0; nf < 4; nf++) {
                    int np = nf >> 1, hh = nf & 1;
                    uint32_t b0h = bhF[np][hh * 2], b1h = bhF[np][hh * 2 + 1];
                    uint32_t b0l = blF[np][hh * 2], b1l = blF[np][hh * 2 + 1];
                    mma_bf(acc[mf][nf], ah2, b0h, b1h);
                    mma_bf(acc[mf][nf], ah2, b0l, b1l);
                    mma_bf(acc[mf][nf], al2, b0h, b1h);
                }
            }
        }
    }

    bf16* oh = (MODE == 0) ? ((widx == 0) ? oh0 : (widx == 1) ? oh1 : oh2) : oh0;
    bf16* ol = (MODE == 0) ? ((widx == 0) ? ol0 : (widx == 1) ? ol1 : ol2) : ol0;

#pragma unroll
    for (int mf = 0; mf < 4; mf++) {
        int rlo = m0 + wm * 64 + mf * 16 + (lane >> 2);
        int rhi = rlo + 8;
#pragma unroll
        for (int nf = 0; nf < 4; nf++) {
            int n = n0 + wn * 32 + nf * 8 + (lane & 3) * 2;
            if (MODE == 2) {
                float2 v0, v1;
                v0.x = acc[mf][nf][0] + bias[n]; v0.y = acc[mf][nf][1] + bias[n + 1];
                v1.x = acc[mf][nf][2] + bias[n]; v1.y = acc[mf][nf][3] + bias[n + 1];
                *(float2*)(out32 + (size_t)rlo * 512 + n) = v0;
                *(float2*)(out32 + (size_t)rhi * 512 + n) = v1;
            } else {
                int h = n >> 6, d = n & 63;
                {
                    int b = rlo >> 11, mm = rlo & 2047;
                    size_t base = ((size_t)(b * 8 + h) * 2048 + mm) * 64 + d;
                    bf16 h0, l0, h1, l1;
                    splitf(acc[mf][nf][0], h0, l0); splitf(acc[mf][nf][1], h1, l1);
                    bf162 t, u; t.x = h0; t.y = h1; u.x = l0; u.y = l1;
                    *(bf162*)(oh + base) = t; *(bf162*)(ol + base) = u;
                }
                {
                    int b = rhi >> 11, mm = rhi & 2047;
                    size_t base = ((size_t)(b * 8 + h) * 2048 + mm) * 64 + d;
                    bf16 h0, l0, h1, l1;
                    splitf(acc[mf][nf][2], h0, l0); splitf(acc[mf][nf][3], h1, l1);
                    bf162 t, u; t.x = h0; t.y = h1; u.x = l0; u.y = l1;
                    *(bf162*)(oh + base) = t; *(bf162*)(ol + base) = u;
                }
            }
        }
    }
}

// ===========================================================================
// Flash attention, FA2 register-P + split-k softmax, 64-row q-tile,
// 2 CTAs/SM (phase overlap across independent CTAs).
// 256 threads, 8 warps: wq = warp>>1 (4 row-groups of 16), wn = warp&1
// (2 key-chunks of 32). Private running max/l per wn warp, merged once at end.
// PV 2-pass, near-one-hot tile skip (e^-25), one barrier per iter.
// ===========================================================================
#define AQH 0
#define AQL 8192
#define AKH(c) (16384 + (c)*32768)
#define AKL(c) (16384 + (c)*32768 + 8192)
#define AVH(c) (16384 + (c)*32768 + 16384)
#define AVL(c) (16384 + (c)*32768 + 24576)
#define AOB  16384              // aliases KV buffers (post-loop only)
#define AML  81920              // [2][64] m, [2][64] l
#define ASZ  83968

__global__ void __launch_bounds__(256, 2) attn_mma(
    const bf16* __restrict__ Qh, const bf16* __restrict__ Ql,
    const bf16* __restrict__ Kh, const bf16* __restrict__ Kl,
    const bf16* __restrict__ Vh, const bf16* __restrict__ Vl,
    bf16* __restrict__ Ch, bf16* __restrict__ Cl)
{
    extern __shared__ char sm[];
    const uint32_t sb = smem_u32(sm);
    float* mbuf = (float*)(sm + AML);        // [2][64]
    float* lbuf = mbuf + 128;                // [2][64]
    float* obuf = (float*)(sm + AOB);        // [64][66], post-loop only

    const int tid = threadIdx.x, warp = tid >> 5, lane = tid & 31;
    const int wq = warp >> 1, wn = warp & 1;
    const int lr = lane & 7, g = lane >> 3;
    const int offAr = (g & 1) * 8 + lr, offAc = (g >> 1) * 8;
    const int offBr = (g >> 1) * 8 + lr, offBc = (g & 1) * 8;
    const int bh = blockIdx.y, q0 = blockIdx.x * 64;

    const char* khb = (const char*)Kh + ((size_t)bh * 2048) * 128;
    const char* klb = (const char*)Kl + ((size_t)bh * 2048) * 128;
    const char* vhb = (const char*)Vh + ((size_t)bh * 2048) * 128;
    const char* vlb = (const char*)Vl + ((size_t)bh * 2048) * 128;

    // Q tiles (hi/lo), 64x64 into smem (8KB each)
    {
        const char* qhp = (const char*)Qh + ((size_t)bh * 2048 + q0) * 128;
        const char* qlp = (const char*)Ql + ((size_t)bh * 2048 + q0) * 128;
#pragma unroll
        for (int i = 0; i < 2; i++) {
            int t = i * 256 + tid, row = t >> 3, cb = (t & 7) * 16;
            uint32_t dsw = SWZ(row * 128 + cb);
            *(uint4*)(sm + AQH + dsw) = *(const uint4*)(qhp + row * 128 + cb);
            *(uint4*)(sm + AQL + dsw) = *(const uint4*)(qlp + row * 128 + cb);
        }
    }

    // prologue: kt=0 loads into buf 0
#pragma unroll
    for (int i = 0; i < 2; i++) {
        int t = i * 256 + tid, row = t >> 3, cb = (t & 7) * 16;
        uint32_t dsw = SWZ(row * 128 + cb);
        size_t go = (size_t)row * 128 + cb;
        cpa16(sb + AKH(0) + dsw, khb + go);
        cpa16(sb + AKL(0) + dsw, klb + go);
        cpa16(sb + AVH(0) + dsw, vhb + go);
        cpa16(sb + AVL(0) + dsw, vlb + go);
    }
    CP_COMMIT();
    __syncthreads();   // Q smem visible

    // hoist Q-hi fragments (loop-invariant): 16 regs
    uint32_t qfh[4][4];
#pragma unroll
    for (int ks = 0; ks < 4; ks++) {
        uint32_t aoff = SWZ((wq * 16 + offAr) * 128 + (ks * 16 + offAc) * 2);
        ldm4(qfh[ks], sb + AQH + aoff);
    }

    float oacc[8][4];
#pragma unroll
    for (int b = 0; b < 8; b++)
#pragma unroll
        for (int c = 0; c < 4; c++) oacc[b][c] = 0.0f;
    float m_prev[2], l_part[2];
    m_prev[0] = m_prev[1] = -INFINITY;
    l_part[0] = l_part[1] = 0.0f;

    for (int kt = 0; kt < 32; kt++) {
        const int c = kt & 1;
        CP_WAIT0();
        __syncthreads();   // buf c ready + all warps done reading buf c

        if (kt < 31) {     // prefetch kt+1 into buf c^1
            size_t tb = (size_t)(kt + 1) * 64 * 128;
#pragma unroll
            for (int i = 0; i < 2; i++) {
                int t = i * 256 + tid, row = t >> 3, cb = (t & 7) * 16;
                uint32_t dsw = SWZ(row * 128 + cb);
                size_t go = tb + (size_t)row * 128 + cb;
                cpa16(sb + AKH(c ^ 1) + dsw, khb + go);
                cpa16(sb + AKL(c ^ 1) + dsw, klb + go);
                cpa16(sb + AVH(c ^ 1) + dsw, vhb + go);
                cpa16(sb + AVL(c ^ 1) + dsw, vlb + go);
            }
            CP_COMMIT();
        }

        // ---- S = Q K^T : warp computes S[16 rows x 32 own keys] ----
        float sacc[4][4];
#pragma unroll
        for (int b = 0; b < 4; b++)
#pragma unroll
            for (int e = 0; e < 4; e++) sacc[b][e] = 0.0f;

#pragma unroll
        for (int ks = 0; ks < 4; ks++) {
            uint32_t kh2[2][4], kl2[2][4];
#pragma unroll
            for (int kg = 0; kg < 2; kg++) {
                uint32_t boff = SWZ((wn * 32 + kg * 16 + offBr) * 128 + (ks * 16 + offBc) * 2);
                ldm4(kh2[kg], sb + AKH(c) + boff);
                ldm4(kl2[kg], sb + AKL(c) + boff);
            }
            uint32_t aoff = SWZ((wq * 16 + offAr) * 128 + (ks * 16 + offAc) * 2);
            uint32_t ql2[4];
            ldm4(ql2, sb + AQL + aoff);
#pragma unroll
            for (int nf = 0; nf < 4; nf++) {
                int kg = nf >> 1, hh = nf & 1;
                mma_bf(sacc[nf], qfh[ks], kh2[kg][hh * 2], kh2[kg][hh * 2 + 1]);
                mma_bf(sacc[nf], qfh[ks], kl2[kg][hh * 2], kl2[kg][hh * 2 + 1]);
                mma_bf(sacc[nf], ql2,     kh2[kg][hh * 2], kh2[kg][hh * 2 + 1]);
            }
        }

        // ---- warp-local softmax (no barrier) ----
        float mlo = -INFINITY, mhi = -INFINITY;
#pragma unroll
        for (int nf = 0; nf < 4; nf++) {
#pragma unroll
            for (int e = 0; e < 4; e++) sacc[nf][e] *= SCALE_;
            mlo = fmaxf(mlo, fmaxf(sacc[nf][0], sacc[nf][1]));
            mhi = fmaxf(mhi, fmaxf(sacc[nf][2], sacc[nf][3]));
        }
        mlo = fmaxf(mlo, __shfl_xor_sync(0xffffffffu, mlo, 1));
        mlo = fmaxf(mlo, __shfl_xor_sync(0xffffffffu, mlo, 2));
        mhi = fmaxf(mhi, __shfl_xor_sync(0xffffffffu, mhi, 1));
        mhi = fmaxf(mhi, __shfl_xor_sync(0xffffffffu, mhi, 2));

        bool skipL = (mlo < m_prev[0] - 25.0f) && (mhi < m_prev[1] - 25.0f);
        bool dopv = (__ballot_sync(0xffffffffu, skipL) != 0xffffffffu);

        if (dopv) {
            float ml = fmaxf(m_prev[0], mlo);
            float mh2 = fmaxf(m_prev[1], mhi);
            float slo = 0.0f, shi = 0.0f;
            float pv[4][4];
#pragma unroll
            for (int nf = 0; nf < 4; nf++) {
                pv[nf][0] = __expf(sacc[nf][0] - ml);
                pv[nf][1] = __expf(sacc[nf][1] - ml);
                pv[nf][2] = __expf(sacc[nf][2] - mh2);
                pv[nf][3] = __expf(sacc[nf][3] - mh2);
                slo += pv[nf][0] + pv[nf][1];
                shi += pv[nf][2] + pv[nf][3];
            }
            uint32_t pa[2][4];
#pragma unroll
            for (int k2 = 0; k2 < 2; k2++) {
                pa[k2][0] = packbf(pv[2 * k2][0], pv[2 * k2][1]);
                pa[k2][1] = packbf(pv[2 * k2][2], pv[2 * k2][3]);
                pa[k2][2] = packbf(pv[2 * k2 + 1][0], pv[2 * k2 + 1][1]);
                pa[k2][3] = packbf(pv[2 * k2 + 1][2], pv[2 * k2 + 1][3]);
            }
            float cl_ = __expf(m_prev[0] - ml);
            float ch_ = __expf(m_prev[1] - mh2);
            l_part[0] = l_part[0] * cl_ + slo;
            l_part[1] = l_part[1] * ch_ + shi;
            m_prev[0] = ml; m_prev[1] = mh2;
#pragma unroll
            for (int nj = 0; nj < 8; nj++) {
                oacc[nj][0] *= cl_; oacc[nj][1] *= cl_;
                oacc[nj][2] *= ch_; oacc[nj][3] *= ch_;
            }

            // ---- PV: O_partial[16x64] += P(regs) * V(own 32 keys) ----
#pragma unroll
            for (int k2 = 0; k2 < 2; k2++) {
                uint32_t vh[4][4], vl[4][4];
#pragma unroll
                for (int j = 0; j < 4; j++) {
                    uint32_t voff = SWZ((wn * 32 + k2 * 16 + offAr) * 128 + (j * 16 + offAc) * 2);
                    ldm4t(vh[j], sb + AVH(c) + voff);
                    ldm4t(vl[j], sb + AVL(c) + voff);
                }
#pragma unroll
                for (int j = 0; j < 4; j++) {
#pragma unroll
                    for (int hh = 0; hh < 2; hh++) {
                        int nj = j * 2 + hh;
                        mma_bf(oacc[nj], pa[k2], vh[j][hh * 2], vh[j][hh * 2 + 1]);
                        mma_bf(oacc[nj], pa[k2], vl[j][hh * 2], vl[j][hh * 2 + 1]);
                    }
                }
            }
        }
    }

    // ---- split-k merge: wn partials -> final O ----
    __syncthreads();   // all PV reads done; KV smem now reusable as obuf

    {
        float slo = l_part[0], shi = l_part[1];
        slo += __shfl_xor_sync(0xffffffffu, slo, 1);
        slo += __shfl_xor_sync(0xffffffffu, slo, 2);
        shi += __shfl_xor_sync(0xffffffffu, shi, 1);
        shi += __shfl_xor_sync(0xffffffffu, shi, 2);
        l_part[0] = slo; l_part[1] = shi;
        if ((lane & 3) == 0) {
            int rl = wq * 16 + (lane >> 2);
            mbuf[wn * 64 + rl] = m_prev[0];
            mbuf[wn * 64 + rl + 8] = m_prev[1];
            lbuf[wn * 64 + rl] = slo;
            lbuf[wn * 64 + rl + 8] = shi;
        }
    }
    if (wn == 1) {
        int rl = wq * 16 + (lane >> 2), rh = rl + 8;
#pragma unroll
        for (int nj = 0; nj < 8; nj++) {
            int col = nj * 8 + (lane & 3) * 2;
            *(float2*)(obuf + rl * 66 + col) = make_float2(oacc[nj][0], oacc[nj][1]);
            *(float2*)(obuf + rh * 66 + col) = make_float2(oacc[nj][2], oacc[nj][3]);
        }
    }
    __syncthreads();

    // ---- epilogue (wn==0): O = w0*O0 + w1*O1, /= l, write hi/lo ----
    if (wn == 0) {
        const int b = bh >> 3, h = bh & 7;
        int rl = wq * 16 + (lane >> 2), rh = rl + 8;
        float m0l = m_prev[0], m1l = mbuf[64 + rl];
        float m0h = m_prev[1], m1h = mbuf[64 + rh];
        float mL = fmaxf(m0l, m1l), mH = fmaxf(m0h, m1h);
        float w0l = __expf(m0l - mL), w1l = __expf(m1l - mL);
        float w0h = __expf(m0h - mH), w1h = __expf(m1h - mH);
        float il = 1.0f / (l_part[0] * w0l + lbuf[64 + rl] * w1l);
        float ih = 1.0f / (l_part[1] * w0h + lbuf[64 + rh] * w1h);
#pragma unroll
        for (int nj = 0; nj < 8; nj++) {
            int col = nj * 8 + (lane & 3) * 2;
            float2 s0 = *(float2*)(obuf + rl * 66 + col);
            float2 s1 = *(float2*)(obuf + rh * 66 + col);
            float v0 = (oacc[nj][0] * w0l + s0.x * w1l) * il;
            float v1 = (oacc[nj][1] * w0l + s0.y * w1l) * il;
            float v2 = (oacc[nj][2] * w0h + s1.x * w1h) * ih;
            float v3 = (oacc[nj][3] * w0h + s1.y * w1h) * ih;
            size_t blo = ((size_t)b * 2048 + q0 + rl) * 512 + h * 64 + col;
            size_t bhi = ((size_t)b * 2048 + q0 + rh) * 512 + h * 64 + col;
            bf16 x0, y0, x1, y1;
            splitf(v0, x0, y0); splitf(v1, x1, y1);
            bf162 t, u; t.x = x0; t.y = x1; u.x = y0; u.y = y1;
            *(bf162*)(Ch + blo) = t; *(bf162*)(Cl + blo) = u;
            splitf(v2, x0, y0); splitf(v3, x1, y1);
            t.x = x0; t.y = x1; u.x = y0; u.y = y1;
            *(bf162*)(Ch + bhi) = t; *(bf162*)(Cl + bhi) = u;
        }
    }
}

// ---------------------------------------------------------------------------
extern "C" void kernel_launch(void* const* d_in, const int* in_sizes, int n_in,
                              void* d_out, int out_size)
{
    const float* x  = (const float*)d_in[0];
    const float* Wq = (const float*)d_in[1];
    const float* Wk = (const float*)d_in[2];
    const float* Wv = (const float*)d_in[3];
    const float* Wo = (const float*)d_in[4];
    const float* bo = (const float*)d_in[5];
    float* out = (float*)d_out;

    bf16 *Xh, *Xl, *Qh, *Ql, *Kh, *Kl, *Vh, *Vl, *Chp, *Clp, *Whp, *Wlp;
    cudaGetSymbolAddress((void**)&Xh, g_Xh);  cudaGetSymbolAddress((void**)&Xl, g_Xl);
    cudaGetSymbolAddress((void**)&Qh, g_Qh);  cudaGetSymbolAddress((void**)&Ql, g_Ql);
    cudaGetSymbolAddress((void**)&Kh, g_Kh);  cudaGetSymbolAddress((void**)&Kl, g_Kl);
    cudaGetSymbolAddress((void**)&Vh, g_Vh);  cudaGetSymbolAddress((void**)&Vl, g_Vl);
    cudaGetSymbolAddress((void**)&Chp, g_Ch); cudaGetSymbolAddress((void**)&Clp, g_Cl);
    cudaGetSymbolAddress((void**)&Whp, g_Wh); cudaGetSymbolAddress((void**)&Wlp, g_Wl);

    cudaFuncSetAttribute(gemm_mma<0>, cudaFuncAttributeMaxDynamicSharedMemorySize, G_SZ);
    cudaFuncSetAttribute(gemm_mma<2>, cudaFuncAttributeMaxDynamicSharedMemorySize, G_SZ);
    cudaFuncSetAttribute(attn_mma, cudaFuncAttributeMaxDynamicSharedMemorySize, ASZ);

    // prep
    prep_x<<<(BM_ * HD_ / 4) / 512, 512>>>((const float4*)x, Xh, Xl);
    dim3 wblk(32, 8), wgrd(16, 16, 4);
    prep_w4<<<wgrd, wblk>>>(Wq, Wk, Wv, Wo, Whp, Wlp);

    // fused QKV projections -> [b,h,m,d] hi/lo
    gemm_mma<0><<<dim3(12, 128), 256, G_SZ>>>(Xh, Xl, Whp, Wlp,
                                              nullptr, nullptr,
                                              Qh, Ql, Kh, Kl, Vh, Vl);

    // attention: 64-row q-tiles, 2 CTAs/SM
    attn_mma<<<dim3(32, 64), 256, ASZ>>>(Qh, Ql, Kh, Kl, Vh, Vl, Chp, Clp);

    // output projection + bias
    gemm_mma<2><<<dim3(4, 128), 256, G_SZ>>>(Chp, Clp, Whp + 3 * 262144, Wlp + 3 * 262144,
                                             bo, out, nullptr, nullptr,
                                             nullptr, nullptr, nullptr, nullptr);
}

// round 11
// speedup vs baseline: 2.0197x; 1.1506x over previous
#include <cuda_runtime.h>
#include <cuda_fp16.h>
#include <stdint.h>
#include <math.h>

#define B_ 8
#define M_ 2048
#define HD_ 512
#define BM_ (B_*M_)
#define SCALE_ 22.62741699796952f   // reference divides by HEAD_DIM**-0.5

typedef __half hf;
typedef __half2 hf2;

// ---------------- device scratch (allocation-free rule) ----------------
__device__ __align__(16) hf g_Xh[(size_t)BM_*HD_], g_Xl[(size_t)BM_*HD_];
__device__ __align__(16) hf g_Qh[(size_t)BM_*HD_], g_Ql[(size_t)BM_*HD_];
__device__ __align__(16) hf g_Kh[(size_t)BM_*HD_], g_Kl[(size_t)BM_*HD_];
__device__ __align__(16) hf g_Vh[(size_t)BM_*HD_], g_Vl[(size_t)BM_*HD_];
__device__ __align__(16) hf g_Ch[(size_t)BM_*HD_], g_Cl[(size_t)BM_*HD_];
__device__ __align__(16) hf g_Wh[4][512*512], g_Wl[4][512*512];   // W^T: [n][k]

// ---------------- helpers ----------------
__device__ __forceinline__ uint32_t smem_u32(const void* p) {
    uint32_t a;
    asm("{ .reg .u64 t; cvta.to.shared.u64 t, %1; cvt.u32.u64 %0, t; }" : "=r"(a) : "l"(p));
    return a;
}
#define SWZ(x) ((uint32_t)(x) ^ ((((uint32_t)(x)) >> 3) & 0x70))

__device__ __forceinline__ void ldm4(uint32_t (&r)[4], uint32_t a) {
    asm volatile("ldmatrix.sync.aligned.m8n8.x4.shared.b16 {%0,%1,%2,%3}, [%4];"
                 : "=r"(r[0]), "=r"(r[1]), "=r"(r[2]), "=r"(r[3]) : "r"(a));
}
__device__ __forceinline__ void ldm4t(uint32_t (&r)[4], uint32_t a) {
    asm volatile("ldmatrix.sync.aligned.m8n8.x4.trans.shared.b16 {%0,%1,%2,%3}, [%4];"
                 : "=r"(r[0]), "=r"(r[1]), "=r"(r[2]), "=r"(r[3]) : "r"(a));
}
__device__ __forceinline__ void mma_hf(float (&d)[4], const uint32_t (&a)[4],
                                       uint32_t b0, uint32_t b1) {
    asm volatile("mma.sync.aligned.m16n8k16.row.col.f32.f16.f16.f32 "
                 "{%0,%1,%2,%3}, {%4,%5,%6,%7}, {%8,%9}, {%0,%1,%2,%3};"
                 : "+f"(d[0]), "+f"(d[1]), "+f"(d[2]), "+f"(d[3])
                 : "r"(a[0]), "r"(a[1]), "r"(a[2]), "r"(a[3]), "r"(b0), "r"(b1));
}
__device__ __forceinline__ void splith(float x, hf& h, hf& l) {
    h = __float2half_rn(x);
    l = __float2half_rn(x - __half2float(h));
}
__device__ __forceinline__ uint32_t packh(float a, float b) {
    hf2 t; t.x = __float2half_rn(a); t.y = __float2half_rn(b);
    return *(uint32_t*)&t;
}
__device__ __forceinline__ void cpa16(uint32_t dst, const void* src) {
    asm volatile("cp.async.cg.shared.global [%0], [%1], 16;" :: "r"(dst), "l"(src));
}
#define CP_COMMIT() asm volatile("cp.async.commit_group;" ::: "memory")
#define CP_WAIT0()  asm volatile("cp.async.wait_group 0;" ::: "memory")

// ---------------- prep kernels ----------------
__global__ void __launch_bounds__(512) prep_x(const float4* __restrict__ x,
                                              hf* __restrict__ xh, hf* __restrict__ xl) {
    size_t i = (size_t)blockIdx.x * 512 + threadIdx.x;
    float4 v = x[i];
    hf h0, l0, h1, l1, h2, l2, h3, l3;
    splith(v.x, h0, l0); splith(v.y, h1, l1);
    splith(v.z, h2, l2); splith(v.w, h3, l3);
    hf2 a, b, c, d;
    a.x = h0; a.y = h1; b.x = h2; b.y = h3;
    c.x = l0; c.y = l1; d.x = l2; d.y = l3;
    *(hf2*)(xh + i * 4) = a; *(hf2*)(xh + i * 4 + 2) = b;
    *(hf2*)(xl + i * 4) = c; *(hf2*)(xl + i * 4 + 2) = d;
}

// coalesced tile-transpose for all 4 weights: W[k][n] -> W^T[n][k] hi/lo
__global__ void __launch_bounds__(256) prep_w4(
    const float* __restrict__ W0, const float* __restrict__ W1,
    const float* __restrict__ W2, const float* __restrict__ W3,
    hf* __restrict__ th, hf* __restrict__ tl) {
    __shared__ float t[32][33];
    const int w = blockIdx.z;
    const float* W = (w == 0) ? W0 : (w == 1) ? W1 : (w == 2) ? W2 : W3;
    hf* thw = th + (size_t)w * 262144;
    hf* tlw = tl + (size_t)w * 262144;
    const int bx = blockIdx.x * 32;   // n-block
    const int by = blockIdx.y * 32;   // k-block
    const int tx = threadIdx.x, ty = threadIdx.y;
#pragma unroll
    for (int j = ty; j < 32; j += 8)
        t[j][tx] = W[(size_t)(by + j) * 512 + bx + tx];
    __syncthreads();
#pragma unroll
    for (int j = ty; j < 32; j += 8) {
        float v = t[tx][j];
        hf h, l; splith(v, h, l);
        thw[(size_t)(bx + j) * 512 + by + tx] = h;
        tlw[(size_t)(bx + j) * 512 + by + tx] = l;
    }
}

// ===========================================================================
// GEMM via mma.sync (fp16 split 3-pass), cp.async double-buffered, 2 CTAs/SM.
// CTA tile 128m x 64n, K-chunks of 64. 8 warps (wm 2 x wn 4), warp tile 64x16.
// MODE 0 (fused QKV): blockIdx.x = widx*8 + ntile. MODE 2: fp32 + bias.
// ===========================================================================
#define GSTG 49152
#define G_AH(c) ((c)*GSTG + 0)
#define G_AL(c) ((c)*GSTG + 16384)
#define G_BH(c) ((c)*GSTG + 32768)
#define G_BL(c) ((c)*GSTG + 40960)
#define G_SZ    98304

template <int MODE>
__global__ void __launch_bounds__(256, 2) gemm_mma(
    const hf* __restrict__ Ah_, const hf* __restrict__ Al_,
    const hf* __restrict__ WhB, const hf* __restrict__ WlB,
    const float* __restrict__ bias, float* __restrict__ out32,
    hf* __restrict__ oh0, hf* __restrict__ ol0,
    hf* __restrict__ oh1, hf* __restrict__ ol1,
    hf* __restrict__ oh2, hf* __restrict__ ol2)
{
    extern __shared__ char sm[];
    const uint32_t sb = smem_u32(sm);
    const int tid = threadIdx.x, warp = tid >> 5, lane = tid & 31;
    const int wm = warp >> 2, wn = warp & 3;
    const int lr = lane & 7, g = lane >> 3;
    const int offAr = (g & 1) * 8 + lr, offAc = (g >> 1) * 8;
    const int offBr = (g >> 1) * 8 + lr, offBc = (g & 1) * 8;

    const int widx = (MODE == 0) ? (blockIdx.x >> 3) : 0;
    const int n0 = (MODE == 0) ? ((blockIdx.x & 7) * 64) : (blockIdx.x * 64);
    const int m0 = blockIdx.y * 128;
    const hf* Bh_ = WhB + (size_t)widx * 262144;
    const hf* Bl_ = WlB + (size_t)widx * 262144;

    // prologue: chunk 0
#pragma unroll
    for (int i = 0; i < 4; i++) {
        int t = i * 256 + tid, row = t >> 3, cb = (t & 7) * 16;
        uint32_t dsw = SWZ(row * 128 + cb);
        size_t abyte = ((size_t)(m0 + row) * 512) * 2 + cb;
        cpa16(sb + G_AH(0) + dsw, (const char*)Ah_ + abyte);
        cpa16(sb + G_AL(0) + dsw, (const char*)Al_ + abyte);
    }
#pragma unroll
    for (int i = 0; i < 2; i++) {
        int t = i * 256 + tid, row = t >> 3, cb = (t & 7) * 16;
        uint32_t dsw = SWZ(row * 128 + cb);
        size_t bbyte = ((size_t)(n0 + row) * 512) * 2 + cb;
        cpa16(sb + G_BH(0) + dsw, (const char*)Bh_ + bbyte);
        cpa16(sb + G_BL(0) + dsw, (const char*)Bl_ + bbyte);
    }
    CP_COMMIT();

    float acc[4][2][4];
#pragma unroll
    for (int a = 0; a < 4; a++)
#pragma unroll
        for (int b = 0; b < 2; b++)
#pragma unroll
            for (int c = 0; c < 4; c++) acc[a][b][c] = 0.0f;

    for (int ch = 0; ch < 8; ch++) {
        const int c = ch & 1;
        CP_WAIT0();
        __syncthreads();

        if (ch < 7) {
#pragma unroll
            for (int i = 0; i < 4; i++) {
                int t = i * 256 + tid, row = t >> 3, cb = (t & 7) * 16;
                uint32_t dsw = SWZ(row * 128 + cb);
                size_t abyte = ((size_t)(m0 + row) * 512 + (ch + 1) * 64) * 2 + cb;
                cpa16(sb + G_AH(c ^ 1) + dsw, (const char*)Ah_ + abyte);
                cpa16(sb + G_AL(c ^ 1) + dsw, (const char*)Al_ + abyte);
            }
#pragma unroll
            for (int i = 0; i < 2; i++) {
                int t = i * 256 + tid, row = t >> 3, cb = (t & 7) * 16;
                uint32_t dsw = SWZ(row * 128 + cb);
                size_t bbyte = ((size_t)(n0 + row) * 512 + (ch + 1) * 64) * 2 + cb;
                cpa16(sb + G_BH(c ^ 1) + dsw, (const char*)Bh_ + bbyte);
                cpa16(sb + G_BL(c ^ 1) + dsw, (const char*)Bl_ + bbyte);
            }
            CP_COMMIT();
        }

#pragma unroll
        for (int ks = 0; ks < 4; ks++) {
            uint32_t bhF[4], blF[4];
            uint32_t boff = SWZ((wn * 16 + offBr) * 128 + (ks * 16 + offBc) * 2);
            ldm4(bhF, sb + G_BH(c) + boff);
            ldm4(blF, sb + G_BL(c) + boff);
#pragma unroll
            for (int mf = 0; mf < 4; mf++) {
                uint32_t aoff = SWZ((wm * 64 + mf * 16 + offAr) * 128 + (ks * 16 + offAc) * 2);
                uint32_t ah2[4], al2[4];
                ldm4(ah2, sb + G_AH(c) + aoff);
                ldm4(al2, sb + G_AL(c) + aoff);
#pragma unroll
                for (int nf = 0; nf < 2; nf++) {
                    uint32_t b0h = bhF[nf * 2], b1h = bhF[nf * 2 + 1];
                    uint32_t b0l = blF[nf * 2], b1l = blF[nf * 2 + 1];
                    mma_hf(acc[mf][nf], ah2, b0h, b1h);
                    mma_hf(acc[mf][nf], ah2, b0l, b1l);
                    mma_hf(acc[mf][nf], al2, b0h, b1h);
                }
            }
        }
    }

    hf* oh = (MODE == 0) ? ((widx == 0) ? oh0 : (widx == 1) ? oh1 : oh2) : oh0;
    hf* ol = (MODE == 0) ? ((widx == 0) ? ol0 : (widx == 1) ? ol1 : ol2) : ol0;

#pragma unroll
    for (int mf = 0; mf < 4; mf++) {
        int rlo = m0 + wm * 64 + mf * 16 + (lane >> 2);
        int rhi = rlo + 8;
#pragma unroll
        for (int nf = 0; nf < 2; nf++) {
            int n = n0 + wn * 16 + nf * 8 + (lane & 3) * 2;
            if (MODE == 2) {
                float2 v0, v1;
                v0.x = acc[mf][nf][0] + bias[n]; v0.y = acc[mf][nf][1] + bias[n + 1];
                v1.x = acc[mf][nf][2] + bias[n]; v1.y = acc[mf][nf][3] + bias[n + 1];
                *(float2*)(out32 + (size_t)rlo * 512 + n) = v0;
                *(float2*)(out32 + (size_t)rhi * 512 + n) = v1;
            } else {
                int h = n >> 6, d = n & 63;
                {
                    int b = rlo >> 11, mm = rlo & 2047;
                    size_t base = ((size_t)(b * 8 + h) * 2048 + mm) * 64 + d;
                    hf h0, l0, h1, l1;
                    splith(acc[mf][nf][0], h0, l0); splith(acc[mf][nf][1], h1, l1);
                    hf2 t, u; t.x = h0; t.y = h1; u.x = l0; u.y = l1;
                    *(hf2*)(oh + base) = t; *(hf2*)(ol + base) = u;
                }
                {
                    int b = rhi >> 11, mm = rhi & 2047;
                    size_t base = ((size_t)(b * 8 + h) * 2048 + mm) * 64 + d;
                    hf h0, l0, h1, l1;
                    splith(acc[mf][nf][2], h0, l0); splith(acc[mf][nf][3], h1, l1);
                    hf2 t, u; t.x = h0; t.y = h1; u.x = l0; u.y = l1;
                    *(hf2*)(oh + base) = t; *(hf2*)(ol + base) = u;
                }
            }
        }
    }
}

// ===========================================================================
// Flash attention (fp16): FA2 register-P + split-k softmax, 64-row q-tile,
// 2 CTAs/SM. S = 3-pass fp16 split; P fp16; PV SINGLE-pass (V hi fp16 only:
// fp16 mantissa 2^-11 keeps O error ~3e-4, vs gate 1e-3).
// 8 warps: wq = warp>>1 (4 row-groups of 16), wn = warp&1 (2 key-chunks of 32).
// ===========================================================================
#define AQH 0
#define AQL 8192
#define ASTG 24576
#define AKH(c) (16384 + (c)*ASTG)
#define AKL(c) (16384 + (c)*ASTG + 8192)
#define AVH(c) (16384 + (c)*ASTG + 16384)
#define AOB  16384              // aliases KV buffers (post-loop only)
#define AML  65536              // [2][64] m, [2][64] l
#define ASZ  67584

__global__ void __launch_bounds__(256, 2) attn_mma(
    const hf* __restrict__ Qh, const hf* __restrict__ Ql,
    const hf* __restrict__ Kh, const hf* __restrict__ Kl,
    const hf* __restrict__ Vh,
    hf* __restrict__ Ch, hf* __restrict__ Cl)
{
    extern __shared__ char sm[];
    const uint32_t sb = smem_u32(sm);
    float* mbuf = (float*)(sm + AML);        // [2][64]
    float* lbuf = mbuf + 128;                // [2][64]
    float* obuf = (float*)(sm + AOB);        // [64][66], post-loop only

    const int tid = threadIdx.x, warp = tid >> 5, lane = tid & 31;
    const int wq = warp >> 1, wn = warp & 1;
    const int lr = lane & 7, g = lane >> 3;
    const int offAr = (g & 1) * 8 + lr, offAc = (g >> 1) * 8;
    const int offBr = (g >> 1) * 8 + lr, offBc = (g & 1) * 8;
    const int bh = blockIdx.y, q0 = blockIdx.x * 64;

    const char* khb = (const char*)Kh + ((size_t)bh * 2048) * 128;
    const char* klb = (const char*)Kl + ((size_t)bh * 2048) * 128;
    const char* vhb = (const char*)Vh + ((size_t)bh * 2048) * 128;

    // Q tiles (hi/lo), 64x64 into smem (8KB each)
    {
        const char* qhp = (const char*)Qh + ((size_t)bh * 2048 + q0) * 128;
        const char* qlp = (const char*)Ql + ((size_t)bh * 2048 + q0) * 128;
#pragma unroll
        for (int i = 0; i < 2; i++) {
            int t = i * 256 + tid, row = t >> 3, cb = (t & 7) * 16;
            uint32_t dsw = SWZ(row * 128 + cb);
            *(uint4*)(sm + AQH + dsw) = *(const uint4*)(qhp + row * 128 + cb);
            *(uint4*)(sm + AQL + dsw) = *(const uint4*)(qlp + row * 128 + cb);
        }
    }

    // prologue: kt=0 loads into buf 0
#pragma unroll
    for (int i = 0; i < 2; i++) {
        int t = i * 256 + tid, row = t >> 3, cb = (t & 7) * 16;
        uint32_t dsw = SWZ(row * 128 + cb);
        size_t go = (size_t)row * 128 + cb;
        cpa16(sb + AKH(0) + dsw, khb + go);
        cpa16(sb + AKL(0) + dsw, klb + go);
        cpa16(sb + AVH(0) + dsw, vhb + go);
    }
    CP_COMMIT();
    __syncthreads();   // Q smem visible

    // hoist Q-hi fragments (loop-invariant): 16 regs
    uint32_t qfh[4][4];
#pragma unroll
    for (int ks = 0; ks < 4; ks++) {
        uint32_t aoff = SWZ((wq * 16 + offAr) * 128 + (ks * 16 + offAc) * 2);
        ldm4(qfh[ks], sb + AQH + aoff);
    }

    float oacc[8][4];
#pragma unroll
    for (int b = 0; b < 8; b++)
#pragma unroll
        for (int c = 0; c < 4; c++) oacc[b][c] = 0.0f;
    float m_prev[2], l_part[2];
    m_prev[0] = m_prev[1] = -INFINITY;
    l_part[0] = l_part[1] = 0.0f;

    for (int kt = 0; kt < 32; kt++) {
        const int c = kt & 1;
        CP_WAIT0();
        __syncthreads();

        if (kt < 31) {
            size_t tb = (size_t)(kt + 1) * 64 * 128;
#pragma unroll
            for (int i = 0; i < 2; i++) {
                int t = i * 256 + tid, row = t >> 3, cb = (t & 7) * 16;
                uint32_t dsw = SWZ(row * 128 + cb);
                size_t go = tb + (size_t)row * 128 + cb;
                cpa16(sb + AKH(c ^ 1) + dsw, khb + go);
                cpa16(sb + AKL(c ^ 1) + dsw, klb + go);
                cpa16(sb + AVH(c ^ 1) + dsw, vhb + go);
            }
            CP_COMMIT();
        }

        // ---- S = Q K^T : warp computes S[16 rows x 32 own keys] ----
        float sacc[4][4];
#pragma unroll
        for (int b = 0; b < 4; b++)
#pragma unroll
            for (int e = 0; e < 4; e++) sacc[b][e] = 0.0f;

#pragma unroll
        for (int ks = 0; ks < 4; ks++) {
            uint32_t kh2[2][4], kl2[2][4];
#pragma unroll
            for (int kg = 0; kg < 2; kg++) {
                uint32_t boff = SWZ((wn * 32 + kg * 16 + offBr) * 128 + (ks * 16 + offBc) * 2);
                ldm4(kh2[kg], sb + AKH(c) + boff);
                ldm4(kl2[kg], sb + AKL(c) + boff);
            }
            uint32_t aoff = SWZ((wq * 16 + offAr) * 128 + (ks * 16 + offAc) * 2);
            uint32_t ql2[4];
            ldm4(ql2, sb + AQL + aoff);
#pragma unroll
            for (int nf = 0; nf < 4; nf++) {
                int kg = nf >> 1, hh = nf & 1;
                mma_hf(sacc[nf], qfh[ks], kh2[kg][hh * 2], kh2[kg][hh * 2 + 1]);
                mma_hf(sacc[nf], qfh[ks], kl2[kg][hh * 2], kl2[kg][hh * 2 + 1]);
                mma_hf(sacc[nf], ql2,     kh2[kg][hh * 2], kh2[kg][hh * 2 + 1]);
            }
        }

        // ---- warp-local softmax (no barrier) ----
        float mlo = -INFINITY, mhi = -INFINITY;
#pragma unroll
        for (int nf = 0; nf < 4; nf++) {
#pragma unroll
            for (int e = 0; e < 4; e++) sacc[nf][e] *= SCALE_;
            mlo = fmaxf(mlo, fmaxf(sacc[nf][0], sacc[nf][1]));
            mhi = fmaxf(mhi, fmaxf(sacc[nf][2], sacc[nf][3]));
        }
        mlo = fmaxf(mlo, __shfl_xor_sync(0xffffffffu, mlo, 1));
        mlo = fmaxf(mlo, __shfl_xor_sync(0xffffffffu, mlo, 2));
        mhi = fmaxf(mhi, __shfl_xor_sync(0xffffffffu, mhi, 1));
        mhi = fmaxf(mhi, __shfl_xor_sync(0xffffffffu, mhi, 2));

        bool skipL = (mlo < m_prev[0] - 25.0f) && (mhi < m_prev[1] - 25.0f);
        bool dopv = (__ballot_sync(0xffffffffu, skipL) != 0xffffffffu);

        if (dopv) {
            float ml = fmaxf(m_prev[0], mlo);
            float mh2 = fmaxf(m_prev[1], mhi);
            float slo = 0.0f, shi = 0.0f;
            float pv[4][4];
#pragma unroll
            for (int nf = 0; nf < 4; nf++) {
                pv[nf][0] = __expf(sacc[nf][0] - ml);
                pv[nf][1] = __expf(sacc[nf][1] - ml);
                pv[nf][2] = __expf(sacc[nf][2] - mh2);
                pv[nf][3] = __expf(sacc[nf][3] - mh2);
                slo += pv[nf][0] + pv[nf][1];
                shi += pv[nf][2] + pv[nf][3];
            }
            uint32_t pa[2][4];
#pragma unroll
            for (int k2 = 0; k2 < 2; k2++) {
                pa[k2][0] = packh(pv[2 * k2][0], pv[2 * k2][1]);
                pa[k2][1] = packh(pv[2 * k2][2], pv[2 * k2][3]);
                pa[k2][2] = packh(pv[2 * k2 + 1][0], pv[2 * k2 + 1][1]);
                pa[k2][3] = packh(pv[2 * k2 + 1][2], pv[2 * k2 + 1][3]);
            }
            float cl_ = __expf(m_prev[0] - ml);
            float ch_ = __expf(m_prev[1] - mh2);
            l_part[0] = l_part[0] * cl_ + slo;
            l_part[1] = l_part[1] * ch_ + shi;
            m_prev[0] = ml; m_prev[1] = mh2;
#pragma unroll
            for (int nj = 0; nj < 8; nj++) {
                oacc[nj][0] *= cl_; oacc[nj][1] *= cl_;
                oacc[nj][2] *= ch_; oacc[nj][3] *= ch_;
            }

            // ---- PV single-pass: O_partial[16x64] += P * Vh ----
#pragma unroll
            for (int k2 = 0; k2 < 2; k2++) {
                uint32_t vh[4][4];
#pragma unroll
                for (int j = 0; j < 4; j++) {
                    uint32_t voff = SWZ((wn * 32 + k2 * 16 + offAr) * 128 + (j * 16 + offAc) * 2);
                    ldm4t(vh[j], sb + AVH(c) + voff);
                }
#pragma unroll
                for (int j = 0; j < 4; j++) {
#pragma unroll
                    for (int hh = 0; hh < 2; hh++) {
                        int nj = j * 2 + hh;
                        mma_hf(oacc[nj], pa[k2], vh[j][hh * 2], vh[j][hh * 2 + 1]);
                    }
                }
            }
        }
    }

    // ---- split-k merge: wn partials -> final O ----
    __syncthreads();   // all PV reads done; KV smem now reusable as obuf

    {
        float slo = l_part[0], shi = l_part[1];
        slo += __shfl_xor_sync(0xffffffffu, slo, 1);
        slo += __shfl_xor_sync(0xffffffffu, slo, 2);
        shi += __shfl_xor_sync(0xffffffffu, shi, 1);
        shi += __shfl_xor_sync(0xffffffffu, shi, 2);
        l_part[0] = slo; l_part[1] = shi;
        if ((lane & 3) == 0) {
            int rl = wq * 16 + (lane >> 2);
            mbuf[wn * 64 + rl] = m_prev[0];
            mbuf[wn * 64 + rl + 8] = m_prev[1];
            lbuf[wn * 64 + rl] = slo;
            lbuf[wn * 64 + rl + 8] = shi;
        }
    }
    if (wn == 1) {
        int rl = wq * 16 + (lane >> 2), rh = rl + 8;
#pragma unroll
        for (int nj = 0; nj < 8; nj++) {
            int col = nj * 8 + (lane & 3) * 2;
            *(float2*)(obuf + rl * 66 + col) = make_float2(oacc[nj][0], oacc[nj][1]);
            *(float2*)(obuf + rh * 66 + col) = make_float2(oacc[nj][2], oacc[nj][3]);
        }
    }
    __syncthreads();

    // ---- epilogue (wn==0): O = w0*O0 + w1*O1, /= l, write hi/lo ----
    if (wn == 0) {
        const int b = bh >> 3, h = bh & 7;
        int rl = wq * 16 + (lane >> 2), rh = rl + 8;
        float m0l = m_prev[0], m1l = mbuf[64 + rl];
        float m0h = m_prev[1], m1h = mbuf[64 + rh];
        float mL = fmaxf(m0l, m1l), mH = fmaxf(m0h, m1h);
        float w0l = __expf(m0l - mL), w1l = __expf(m1l - mL);
        float w0h = __expf(m0h - mH), w1h = __expf(m1h - mH);
        float il = 1.0f / (l_part[0] * w0l + lbuf[64 + rl] * w1l);
        float ih = 1.0f / (l_part[1] * w0h + lbuf[64 + rh] * w1h);
#pragma unroll
        for (int nj = 0; nj < 8; nj++) {
            int col = nj * 8 + (lane & 3) * 2;
            float2 s0 = *(float2*)(obuf + rl * 66 + col);
            float2 s1 = *(float2*)(obuf + rh * 66 + col);
            float v0 = (oacc[nj][0] * w0l + s0.x * w1l) * il;
            float v1 = (oacc[nj][1] * w0l + s0.y * w1l) * il;
            float v2 = (oacc[nj][2] * w0h + s1.x * w1h) * ih;
            float v3 = (oacc[nj][3] * w0h + s1.y * w1h) * ih;
            size_t blo = ((size_t)b * 2048 + q0 + rl) * 512 + h * 64 + col;
            size_t bhi = ((size_t)b * 2048 + q0 + rh) * 512 + h * 64 + col;
            hf x0, y0, x1, y1;
            splith(v0, x0, y0); splith(v1, x1, y1);
            hf2 t, u; t.x = x0; t.y = x1; u.x = y0; u.y = y1;
            *(hf2*)(Ch + blo) = t; *(hf2*)(Cl + blo) = u;
            splith(v2, x0, y0); splith(v3, x1, y1);
            t.x = x0; t.y = x1; u.x = y0; u.y = y1;
            *(hf2*)(Ch + bhi) = t; *(hf2*)(Cl + bhi) = u;
        }
    }
}

// ---------------------------------------------------------------------------
extern "C" void kernel_launch(void* const* d_in, const int* in_sizes, int n_in,
                              void* d_out, int out_size)
{
    const float* x  = (const float*)d_in[0];
    const float* Wq = (const float*)d_in[1];
    const float* Wk = (const float*)d_in[2];
    const float* Wv = (const float*)d_in[3];
    const float* Wo = (const float*)d_in[4];
    const float* bo = (const float*)d_in[5];
    float* out = (float*)d_out;

    hf *Xh, *Xl, *Qh, *Ql, *Kh, *Kl, *Vh, *Vl, *Chp, *Clp, *Whp, *Wlp;
    cudaGetSymbolAddress((void**)&Xh, g_Xh);  cudaGetSymbolAddress((void**)&Xl, g_Xl);
    cudaGetSymbolAddress((void**)&Qh, g_Qh);  cudaGetSymbolAddress((void**)&Ql, g_Ql);
    cudaGetSymbolAddress((void**)&Kh, g_Kh);  cudaGetSymbolAddress((void**)&Kl, g_Kl);
    cudaGetSymbolAddress((void**)&Vh, g_Vh);  cudaGetSymbolAddress((void**)&Vl, g_Vl);
    cudaGetSymbolAddress((void**)&Chp, g_Ch); cudaGetSymbolAddress((void**)&Clp, g_Cl);
    cudaGetSymbolAddress((void**)&Whp, g_Wh); cudaGetSymbolAddress((void**)&Wlp, g_Wl);

    cudaFuncSetAttribute(gemm_mma<0>, cudaFuncAttributeMaxDynamicSharedMemorySize, G_SZ);
    cudaFuncSetAttribute(gemm_mma<2>, cudaFuncAttributeMaxDynamicSharedMemorySize, G_SZ);
    cudaFuncSetAttribute(attn_mma, cudaFuncAttributeMaxDynamicSharedMemorySize, ASZ);

    // prep
    prep_x<<<(BM_ * HD_ / 4) / 512, 512>>>((const float4*)x, Xh, Xl);
    dim3 wblk(32, 8), wgrd(16, 16, 4);
    prep_w4<<<wgrd, wblk>>>(Wq, Wk, Wv, Wo, Whp, Wlp);

    // fused QKV projections -> [b,h,m,d] hi/lo  (24 = 3 weights x 8 n-tiles)
    gemm_mma<0><<<dim3(24, 128), 256, G_SZ>>>(Xh, Xl, Whp, Wlp,
                                              nullptr, nullptr,
                                              Qh, Ql, Kh, Kl, Vh, Vl);

    // attention: 64-row q-tiles, 2 CTAs/SM, V single-pass
    attn_mma<<<dim3(32, 64), 256, ASZ>>>(Qh, Ql, Kh, Kl, Vh, Chp, Clp);

    // output projection + bias
    gemm_mma<2><<<dim3(8, 128), 256, G_SZ>>>(Chp, Clp, Whp + 3 * 262144, Wlp + 3 * 262144,
                                             bo, out, nullptr, nullptr,
                                             nullptr, nullptr, nullptr, nullptr);
}

// round 13
// speedup vs baseline: 2.0899x; 1.0348x over previous
#include <cuda_runtime.h>
#include <cuda_fp16.h>
#include <stdint.h>
#include <math.h>

#define B_ 8
#define M_ 2048
#define HD_ 512
#define BM_ (B_*M_)
#define SCALE_ 22.62741699796952f   // reference divides by HEAD_DIM**-0.5

typedef __half hf;
typedef __half2 hf2;

// ---------------- device scratch (allocation-free rule) ----------------
__device__ __align__(16) hf g_Xh[(size_t)BM_*HD_], g_Xl[(size_t)BM_*HD_];
__device__ __align__(16) hf g_Qh[(size_t)BM_*HD_], g_Ql[(size_t)BM_*HD_];
__device__ __align__(16) hf g_Kh[(size_t)BM_*HD_], g_Kl[(size_t)BM_*HD_];
__device__ __align__(16) hf g_Vh[(size_t)BM_*HD_];
__device__ __align__(16) hf g_C [(size_t)BM_*HD_];
__device__ __align__(16) hf g_Wh[4][512*512], g_Wl[4][512*512];   // W^T: [n][k]

// ---------------- helpers ----------------
__device__ __forceinline__ uint32_t smem_u32(const void* p) {
    uint32_t a;
    asm("{ .reg .u64 t; cvta.to.shared.u64 t, %1; cvt.u32.u64 %0, t; }" : "=r"(a) : "l"(p));
    return a;
}
#define SWZ(x) ((uint32_t)(x) ^ ((((uint32_t)(x)) >> 3) & 0x70))

__device__ __forceinline__ void ldm4(uint32_t (&r)[4], uint32_t a) {
    asm volatile("ldmatrix.sync.aligned.m8n8.x4.shared.b16 {%0,%1,%2,%3}, [%4];"
                 : "=r"(r[0]), "=r"(r[1]), "=r"(r[2]), "=r"(r[3]) : "r"(a));
}
__device__ __forceinline__ void ldm4t(uint32_t (&r)[4], uint32_t a) {
    asm volatile("ldmatrix.sync.aligned.m8n8.x4.trans.shared.b16 {%0,%1,%2,%3}, [%4];"
                 : "=r"(r[0]), "=r"(r[1]), "=r"(r[2]), "=r"(r[3]) : "r"(a));
}
__device__ __forceinline__ void mma_hf(float (&d)[4], const uint32_t (&a)[4],
                                       uint32_t b0, uint32_t b1) {
    asm volatile("mma.sync.aligned.m16n8k16.row.col.f32.f16.f16.f32 "
                 "{%0,%1,%2,%3}, {%4,%5,%6,%7}, {%8,%9}, {%0,%1,%2,%3};"
                 : "+f"(d[0]), "+f"(d[1]), "+f"(d[2]), "+f"(d[3])
                 : "r"(a[0]), "r"(a[1]), "r"(a[2]), "r"(a[3]), "r"(b0), "r"(b1));
}
__device__ __forceinline__ void splith(float x, hf& h, hf& l) {
    h = __float2half_rn(x);
    l = __float2half_rn(x - __half2float(h));
}
__device__ __forceinline__ uint32_t packh(float a, float b) {
    hf2 t; t.x = __float2half_rn(a); t.y = __float2half_rn(b);
    return *(uint32_t*)&t;
}
__device__ __forceinline__ void cpa16(uint32_t dst, const void* src) {
    asm volatile("cp.async.cg.shared.global [%0], [%1], 16;" :: "r"(dst), "l"(src));
}
#define CP_COMMIT() asm volatile("cp.async.commit_group;" ::: "memory")
#define CP_WAIT0()  asm volatile("cp.async.wait_group 0;" ::: "memory")

// ---------------- prep kernels ----------------
__global__ void __launch_bounds__(512) prep_x(const float4* __restrict__ x,
                                              hf* __restrict__ xh, hf* __restrict__ xl) {
    size_t i = (size_t)blockIdx.x * 512 + threadIdx.x;
    float4 v = x[i];
    hf h0, l0, h1, l1, h2, l2, h3, l3;
    splith(v.x, h0, l0); splith(v.y, h1, l1);
    splith(v.z, h2, l2); splith(v.w, h3, l3);
    hf2 a, b, c, d;
    a.x = h0; a.y = h1; b.x = h2; b.y = h3;
    c.x = l0; c.y = l1; d.x = l2; d.y = l3;
    *(hf2*)(xh + i * 4) = a; *(hf2*)(xh + i * 4 + 2) = b;
    *(hf2*)(xl + i * 4) = c; *(hf2*)(xl + i * 4 + 2) = d;
}

__global__ void __launch_bounds__(256) prep_w4(
    const float* __restrict__ W0, const float* __restrict__ W1,
    const float* __restrict__ W2, const float* __restrict__ W3,
    hf* __restrict__ th, hf* __restrict__ tl) {
    __shared__ float t[32][33];
    const int w = blockIdx.z;
    const float* W = (w == 0) ? W0 : (w == 1) ? W1 : (w == 2) ? W2 : W3;
    hf* thw = th + (size_t)w * 262144;
    hf* tlw = tl + (size_t)w * 262144;
    const int bx = blockIdx.x * 32;
    const int by = blockIdx.y * 32;
    const int tx = threadIdx.x, ty = threadIdx.y;
#pragma unroll
    for (int j = ty; j < 32; j += 8)
        t[j][tx] = W[(size_t)(by + j) * 512 + bx + tx];
    __syncthreads();
#pragma unroll
    for (int j = ty; j < 32; j += 8) {
        float v = t[tx][j];
        hf h, l; splith(v, h, l);
        thw[(size_t)(bx + j) * 512 + by + tx] = h;
        tlw[(size_t)(bx + j) * 512 + by + tx] = l;
    }
}

// ===========================================================================
// GEMM via mma.sync (fp16), cp.async double-buffered, 2 CTAs/SM.
// CTA tile 128m x 64n, K-chunks of 64. MODE 0 (QKV, 3-pass split): widx from
// blockIdx.x; Q/K write hi+lo, V writes hi only. MODE 2 (out-proj, 2-pass:
// A is single fp16): fp32 + bias output.
// ===========================================================================
#define GSTG 49152
#define G_AH(c) ((c)*GSTG + 0)
#define G_AL(c) ((c)*GSTG + 16384)
#define G_BH(c) ((c)*GSTG + 32768)
#define G_BL(c) ((c)*GSTG + 40960)
#define G_SZ    98304

template <int MODE>
__global__ void __launch_bounds__(256, 2) gemm_mma(
    const hf* __restrict__ Ah_, const hf* __restrict__ Al_,
    const hf* __restrict__ WhB, const hf* __restrict__ WlB,
    const float* __restrict__ bias, float* __restrict__ out32,
    hf* __restrict__ oh0, hf* __restrict__ ol0,
    hf* __restrict__ oh1, hf* __restrict__ ol1,
    hf* __restrict__ oh2)
{
    extern __shared__ char sm[];
    const uint32_t sb = smem_u32(sm);
    const int tid = threadIdx.x, warp = tid >> 5, lane = tid & 31;
    const int wm = warp >> 2, wn = warp & 3;
    const int lr = lane & 7, g = lane >> 3;
    const int offAr = (g & 1) * 8 + lr, offAc = (g >> 1) * 8;
    const int offBr = (g >> 1) * 8 + lr, offBc = (g & 1) * 8;

    const int widx = (MODE == 0) ? (blockIdx.x >> 3) : 0;
    const int n0 = (MODE == 0) ? ((blockIdx.x & 7) * 64) : (blockIdx.x * 64);
    const int m0 = blockIdx.y * 128;
    const hf* Bh_ = WhB + (size_t)widx * 262144;
    const hf* Bl_ = WlB + (size_t)widx * 262144;

    // prologue: chunk 0
#pragma unroll
    for (int i = 0; i < 4; i++) {
        int t = i * 256 + tid, row = t >> 3, cb = (t & 7) * 16;
        uint32_t dsw = SWZ(row * 128 + cb);
        size_t abyte = ((size_t)(m0 + row) * 512) * 2 + cb;
        cpa16(sb + G_AH(0) + dsw, (const char*)Ah_ + abyte);
        if (MODE != 2) cpa16(sb + G_AL(0) + dsw, (const char*)Al_ + abyte);
    }
#pragma unroll
    for (int i = 0; i < 2; i++) {
        int t = i * 256 + tid, row = t >> 3, cb = (t & 7) * 16;
        uint32_t dsw = SWZ(row * 128 + cb);
        size_t bbyte = ((size_t)(n0 + row) * 512) * 2 + cb;
        cpa16(sb + G_BH(0) + dsw, (const char*)Bh_ + bbyte);
        cpa16(sb + G_BL(0) + dsw, (const char*)Bl_ + bbyte);
    }
    CP_COMMIT();

    float acc[4][2][4];
#pragma unroll
    for (int a = 0; a < 4; a++)
#pragma unroll
        for (int b = 0; b < 2; b++)
#pragma unroll
            for (int c = 0; c < 4; c++) acc[a][b][c] = 0.0f;

    for (int ch = 0; ch < 8; ch++) {
        const int c = ch & 1;
        CP_WAIT0();
        __syncthreads();

        if (ch < 7) {
#pragma unroll
            for (int i = 0; i < 4; i++) {
                int t = i * 256 + tid, row = t >> 3, cb = (t & 7) * 16;
                uint32_t dsw = SWZ(row * 128 + cb);
                size_t abyte = ((size_t)(m0 + row) * 512 + (ch + 1) * 64) * 2 + cb;
                cpa16(sb + G_AH(c ^ 1) + dsw, (const char*)Ah_ + abyte);
                if (MODE != 2) cpa16(sb + G_AL(c ^ 1) + dsw, (const char*)Al_ + abyte);
            }
#pragma unroll
            for (int i = 0; i < 2; i++) {
                int t = i * 256 + tid, row = t >> 3, cb = (t & 7) * 16;
                uint32_t dsw = SWZ(row * 128 + cb);
                size_t bbyte = ((size_t)(n0 + row) * 512 + (ch + 1) * 64) * 2 + cb;
                cpa16(sb + G_BH(c ^ 1) + dsw, (const char*)Bh_ + bbyte);
                cpa16(sb + G_BL(c ^ 1) + dsw, (const char*)Bl_ + bbyte);
            }
            CP_COMMIT();
        }

#pragma unroll
        for (int ks = 0; ks < 4; ks++) {
            uint32_t bhF[4], blF[4];
            uint32_t boff = SWZ((wn * 16 + offBr) * 128 + (ks * 16 + offBc) * 2);
            ldm4(bhF, sb + G_BH(c) + boff);
            ldm4(blF, sb + G_BL(c) + boff);
#pragma unroll
            for (int mf = 0; mf < 4; mf++) {
                uint32_t aoff = SWZ((wm * 64 + mf * 16 + offAr) * 128 + (ks * 16 + offAc) * 2);
                uint32_t ah2[4];
                ldm4(ah2, sb + G_AH(c) + aoff);
                uint32_t al2[4];
                if (MODE != 2) ldm4(al2, sb + G_AL(c) + aoff);
#pragma unroll
                for (int nf = 0; nf < 2; nf++) {
                    uint32_t b0h = bhF[nf * 2], b1h = bhF[nf * 2 + 1];
                    uint32_t b0l = blF[nf * 2], b1l = blF[nf * 2 + 1];
                    mma_hf(acc[mf][nf], ah2, b0h, b1h);
                    mma_hf(acc[mf][nf], ah2, b0l, b1l);
                    if (MODE != 2) mma_hf(acc[mf][nf], al2, b0h, b1h);
                }
            }
        }
    }

    hf* oh = (MODE == 0) ? ((widx == 0) ? oh0 : (widx == 1) ? oh1 : oh2) : oh0;
    hf* ol = (MODE == 0) ? ((widx == 0) ? ol0 : ol1) : ol0;
    const bool wlo = (MODE == 0) && (widx != 2);   // V: hi only

#pragma unroll
    for (int mf = 0; mf < 4; mf++) {
        int rlo = m0 + wm * 64 + mf * 16 + (lane >> 2);
        int rhi = rlo + 8;
#pragma unroll
        for (int nf = 0; nf < 2; nf++) {
            int n = n0 + wn * 16 + nf * 8 + (lane & 3) * 2;
            if (MODE == 2) {
                float2 v0, v1;
                v0.x = acc[mf][nf][0] + bias[n]; v0.y = acc[mf][nf][1] + bias[n + 1];
                v1.x = acc[mf][nf][2] + bias[n]; v1.y = acc[mf][nf][3] + bias[n + 1];
                *(float2*)(out32 + (size_t)rlo * 512 + n) = v0;
                *(float2*)(out32 + (size_t)rhi * 512 + n) = v1;
            } else {
                int h = n >> 6, d = n & 63;
                {
                    int b = rlo >> 11, mm = rlo & 2047;
                    size_t base = ((size_t)(b * 8 + h) * 2048 + mm) * 64 + d;
                    hf h0, l0, h1, l1;
                    splith(acc[mf][nf][0], h0, l0); splith(acc[mf][nf][1], h1, l1);
                    hf2 t, u; t.x = h0; t.y = h1; u.x = l0; u.y = l1;
                    *(hf2*)(oh + base) = t;
                    if (wlo) *(hf2*)(ol + base) = u;
                }
                {
                    int b = rhi >> 11, mm = rhi & 2047;
                    size_t base = ((size_t)(b * 8 + h) * 2048 + mm) * 64 + d;
                    hf h0, l0, h1, l1;
                    splith(acc[mf][nf][2], h0, l0); splith(acc[mf][nf][3], h1, l1);
                    hf2 t, u; t.x = h0; t.y = h1; u.x = l0; u.y = l1;
                    *(hf2*)(oh + base) = t;
                    if (wlo) *(hf2*)(ol + base) = u;
                }
            }
        }
    }
}

// ===========================================================================
// Two-phase flash attention (softmax is near-one-hot: logit sigma ~181).
// Phase A: 1-pass S (Qh*Kh only), per-row global max + per-tile maxes.
// Phase B: only tiles with some row within 25 of its global max; kept tiles
// get full 3-pass S + exp(s - m_g) + single-pass PV. Fixed global shift =>
// no online rescale. 64-row q-tile, 2 CTAs/SM, split-k over wn; O merge =
// (O0+O1)/(l0+l1). NOTE: every tile load loop MUST cover 64 rows (i<2 x 256t).
// ===========================================================================
#define AQH 0
#define AQL 8192
#define ASTG 24576
#define AKH(c) (16384 + (c)*ASTG)
#define AKL(c) (16384 + (c)*ASTG + 8192)
#define AVH(c) (16384 + (c)*ASTG + 16384)
#define AOB  16384              // aliases stages (post-loop only)
#define ATM  65536              // tilemax [2][64][32] f32 = 16 KB
#define AMG  81920              // mgbuf [2][64] f32
#define AWMK 82432              // wmask[8] u32
#define ALST 82464              // count + list[32] int
#define ALRD 82624              // lred [2][64] f32
#define ASZ  83200

__global__ void __launch_bounds__(256, 2) attn_mma(
    const hf* __restrict__ Qh, const hf* __restrict__ Ql,
    const hf* __restrict__ Kh, const hf* __restrict__ Kl,
    const hf* __restrict__ Vh, hf* __restrict__ C)
{
    extern __shared__ char sm[];
    const uint32_t sb = smem_u32(sm);
    float* tmax_s = (float*)(sm + ATM);
    float* mgbuf  = (float*)(sm + AMG);
    uint32_t* wmaskA = (uint32_t*)(sm + AWMK);
    int* lst = (int*)(sm + ALST);
    float* lred = (float*)(sm + ALRD);
    float* obuf = (float*)(sm + AOB);

    const int tid = threadIdx.x, warp = tid >> 5, lane = tid & 31;
    const int wq = warp >> 1, wn = warp & 1;
    const int lr = lane & 7, g = lane >> 3;
    const int offAr = (g & 1) * 8 + lr, offAc = (g >> 1) * 8;
    const int offBr = (g >> 1) * 8 + lr, offBc = (g & 1) * 8;
    const int bh = blockIdx.y, q0 = blockIdx.x * 64;
    const int rl = wq * 16 + (lane >> 2), rh = rl + 8;

    const char* khb = (const char*)Kh + ((size_t)bh * 2048) * 128;
    const char* klb = (const char*)Kl + ((size_t)bh * 2048) * 128;
    const char* vhb = (const char*)Vh + ((size_t)bh * 2048) * 128;

    // Q tiles (hi/lo) into smem
    {
        const char* qhp = (const char*)Qh + ((size_t)bh * 2048 + q0) * 128;
        const char* qlp = (const char*)Ql + ((size_t)bh * 2048 + q0) * 128;
#pragma unroll
        for (int i = 0; i < 2; i++) {
            int t = i * 256 + tid, row = t >> 3, cb = (t & 7) * 16;
            uint32_t dsw = SWZ(row * 128 + cb);
            *(uint4*)(sm + AQH + dsw) = *(const uint4*)(qhp + row * 128 + cb);
            *(uint4*)(sm + AQL + dsw) = *(const uint4*)(qlp + row * 128 + cb);
        }
    }

    // Phase A prologue: Kh tile 0 (full 64 rows = 8 KB)
#pragma unroll
    for (int i = 0; i < 2; i++) {
        int t = i * 256 + tid, row = t >> 3, cb = (t & 7) * 16;
        uint32_t dsw = SWZ(row * 128 + cb);
        cpa16(sb + AKH(0) + dsw, khb + (size_t)row * 128 + cb);
    }
    CP_COMMIT();
    __syncthreads();   // Q visible

    uint32_t qfh[4][4];
#pragma unroll
    for (int ks = 0; ks < 4; ks++) {
        uint32_t aoff = SWZ((wq * 16 + offAr) * 128 + (ks * 16 + offAc) * 2);
        ldm4(qfh[ks], sb + AQH + aoff);
    }

    // ================= Phase A: max scan =================
    float mrun0 = -INFINITY, mrun1 = -INFINITY;
    for (int kt = 0; kt < 32; kt++) {
        const int c = kt & 1;
        CP_WAIT0();
        __syncthreads();
        if (kt < 31) {
#pragma unroll
            for (int i = 0; i < 2; i++) {
                int t = i * 256 + tid, row = t >> 3, cb = (t & 7) * 16;
                uint32_t dsw = SWZ(row * 128 + cb);
                size_t go = (size_t)(kt + 1) * 8192 + (size_t)row * 128 + cb;
                cpa16(sb + AKH(c ^ 1) + dsw, khb + go);
            }
            CP_COMMIT();
        }
        float sacc[4][4];
#pragma unroll
        for (int b = 0; b < 4; b++)
#pragma unroll
            for (int e = 0; e < 4; e++) sacc[b][e] = 0.0f;
#pragma unroll
        for (int ks = 0; ks < 4; ks++) {
            uint32_t kh2[2][4];
#pragma unroll
            for (int kg = 0; kg < 2; kg++) {
                uint32_t boff = SWZ((wn * 32 + kg * 16 + offBr) * 128 + (ks * 16 + offBc) * 2);
                ldm4(kh2[kg], sb + AKH(c) + boff);
            }
#pragma unroll
            for (int nf = 0; nf < 4; nf++) {
                int kg = nf >> 1, hh = nf & 1;
                mma_hf(sacc[nf], qfh[ks], kh2[kg][hh * 2], kh2[kg][hh * 2 + 1]);
            }
        }
        float t0 = -INFINITY, t1 = -INFINITY;
#pragma unroll
        for (int nf = 0; nf < 4; nf++) {
            t0 = fmaxf(t0, fmaxf(sacc[nf][0], sacc[nf][1]));
            t1 = fmaxf(t1, fmaxf(sacc[nf][2], sacc[nf][3]));
        }
        t0 *= SCALE_; t1 *= SCALE_;
        t0 = fmaxf(t0, __shfl_xor_sync(0xffffffffu, t0, 1));
        t0 = fmaxf(t0, __shfl_xor_sync(0xffffffffu, t0, 2));
        t1 = fmaxf(t1, __shfl_xor_sync(0xffffffffu, t1, 1));
        t1 = fmaxf(t1, __shfl_xor_sync(0xffffffffu, t1, 2));
        mrun0 = fmaxf(mrun0, t0); mrun1 = fmaxf(mrun1, t1);
        if ((lane & 3) == 0) {
            tmax_s[(wn * 64 + rl) * 32 + kt] = t0;
            tmax_s[(wn * 64 + rh) * 32 + kt] = t1;
        }
    }
    __syncthreads();

    // merge global max across wn
    if ((lane & 3) == 0) {
        mgbuf[wn * 64 + rl] = mrun0;
        mgbuf[wn * 64 + rh] = mrun1;
    }
    __syncthreads();
    const float mg0 = fmaxf(mgbuf[rl], mgbuf[64 + rl]);
    const float mg1 = fmaxf(mgbuf[rh], mgbuf[64 + rh]);

    // keep mask (per warp) + CTA load list
    uint32_t kmask = 0;
    {
        const float* tmw = tmax_s + wn * 64 * 32;
        for (int kt = 0; kt < 32; kt++) {
            bool f = (tmw[rl * 32 + kt] >= mg0 - 25.0f) ||
                     (tmw[rh * 32 + kt] >= mg1 - 25.0f);
            if (__ballot_sync(0xffffffffu, f)) kmask |= (1u << kt);
        }
        if (lane == 0) wmaskA[warp] = kmask;
    }
    __syncthreads();
    uint32_t loadmask = 0;
#pragma unroll
    for (int w = 0; w < 8; w++) loadmask |= wmaskA[w];
    if (tid == 0) {
        int cnt = 0;
        for (int kt = 0; kt < 32; kt++)
            if ((loadmask >> kt) & 1) lst[1 + cnt++] = kt;
        lst[0] = cnt;
    }
    __syncthreads();
    const int count = lst[0];

    // ================= Phase B: selected tiles =================
    {
        int kt0 = lst[1];
#pragma unroll
        for (int i = 0; i < 2; i++) {
            int t = i * 256 + tid, row = t >> 3, cb = (t & 7) * 16;
            uint32_t dsw = SWZ(row * 128 + cb);
            size_t go = (size_t)kt0 * 8192 + (size_t)row * 128 + cb;
            cpa16(sb + AKH(0) + dsw, khb + go);
            cpa16(sb + AKL(0) + dsw, klb + go);
            cpa16(sb + AVH(0) + dsw, vhb + go);
        }
        CP_COMMIT();
    }

    float oacc[8][4];
#pragma unroll
    for (int b = 0; b < 8; b++)
#pragma unroll
        for (int c = 0; c < 4; c++) oacc[b][c] = 0.0f;
    float l0 = 0.0f, l1 = 0.0f;

    for (int i = 0; i < count; i++) {
        const int kt = lst[1 + i];
        const int c = i & 1;
        CP_WAIT0();
        __syncthreads();
        if (i + 1 < count) {
            int ktn = lst[2 + i];
#pragma unroll
            for (int j = 0; j < 2; j++) {
                int t = j * 256 + tid, row = t >> 3, cb = (t & 7) * 16;
                uint32_t dsw = SWZ(row * 128 + cb);
                size_t go = (size_t)ktn * 8192 + (size_t)row * 128 + cb;
                cpa16(sb + AKH(c ^ 1) + dsw, khb + go);
                cpa16(sb + AKL(c ^ 1) + dsw, klb + go);
                cpa16(sb + AVH(c ^ 1) + dsw, vhb + go);
            }
            CP_COMMIT();
        }
        if (!((kmask >> kt) & 1)) continue;   // this warp has no work here

        // 3-pass S
        float sacc[4][4];
#pragma unroll
        for (int b = 0; b < 4; b++)
#pragma unroll
            for (int e = 0; e < 4; e++) sacc[b][e] = 0.0f;
#pragma unroll
        for (int ks = 0; ks < 4; ks++) {
            uint32_t kh2[2][4], kl2[2][4];
#pragma unroll
            for (int kg = 0; kg < 2; kg++) {
                uint32_t boff = SWZ((wn * 32 + kg * 16 + offBr) * 128 + (ks * 16 + offBc) * 2);
                ldm4(kh2[kg], sb + AKH(c) + boff);
                ldm4(kl2[kg], sb + AKL(c) + boff);
            }
            uint32_t aoff = SWZ((wq * 16 + offAr) * 128 + (ks * 16 + offAc) * 2);
            uint32_t ql2[4];
            ldm4(ql2, sb + AQL + aoff);
#pragma unroll
            for (int nf = 0; nf < 4; nf++) {
                int kg = nf >> 1, hh = nf & 1;
                mma_hf(sacc[nf], qfh[ks], kh2[kg][hh * 2], kh2[kg][hh * 2 + 1]);
                mma_hf(sacc[nf], qfh[ks], kl2[kg][hh * 2], kl2[kg][hh * 2 + 1]);
                mma_hf(sacc[nf], ql2,     kh2[kg][hh * 2], kh2[kg][hh * 2 + 1]);
            }
        }

        // exp with fixed global shift
        float slo = 0.0f, shi = 0.0f;
        float pv[4][4];
#pragma unroll
        for (int nf = 0; nf < 4; nf++) {
            pv[nf][0] = __expf(sacc[nf][0] * SCALE_ - mg0);
            pv[nf][1] = __expf(sacc[nf][1] * SCALE_ - mg0);
            pv[nf][2] = __expf(sacc[nf][2] * SCALE_ - mg1);
            pv[nf][3] = __expf(sacc[nf][3] * SCALE_ - mg1);
            slo += pv[nf][0] + pv[nf][1];
            shi += pv[nf][2] + pv[nf][3];
        }
        l0 += slo; l1 += shi;
        uint32_t pa[2][4];
#pragma unroll
        for (int k2 = 0; k2 < 2; k2++) {
            pa[k2][0] = packh(pv[2 * k2][0], pv[2 * k2][1]);
            pa[k2][1] = packh(pv[2 * k2][2], pv[2 * k2][3]);
            pa[k2][2] = packh(pv[2 * k2 + 1][0], pv[2 * k2 + 1][1]);
            pa[k2][3] = packh(pv[2 * k2 + 1][2], pv[2 * k2 + 1][3]);
        }
        // PV single-pass
#pragma unroll
        for (int k2 = 0; k2 < 2; k2++) {
            uint32_t vh[4][4];
#pragma unroll
            for (int j = 0; j < 4; j++) {
                uint32_t voff = SWZ((wn * 32 + k2 * 16 + offAr) * 128 + (j * 16 + offAc) * 2);
                ldm4t(vh[j], sb + AVH(c) + voff);
            }
#pragma unroll
            for (int j = 0; j < 4; j++) {
#pragma unroll
                for (int hh = 0; hh < 2; hh++) {
                    int nj = j * 2 + hh;
                    mma_hf(oacc[nj], pa[k2], vh[j][hh * 2], vh[j][hh * 2 + 1]);
                }
            }
        }
    }

    // ---- split-k merge (l only; m is global) ----
    __syncthreads();
    {
        float a = l0, b = l1;
        a += __shfl_xor_sync(0xffffffffu, a, 1);
        a += __shfl_xor_sync(0xffffffffu, a, 2);
        b += __shfl_xor_sync(0xffffffffu, b, 1);
        b += __shfl_xor_sync(0xffffffffu, b, 2);
        l0 = a; l1 = b;
        if ((lane & 3) == 0) {
            lred[wn * 64 + rl] = a;
            lred[wn * 64 + rh] = b;
        }
    }
    if (wn == 1) {
#pragma unroll
        for (int nj = 0; nj < 8; nj++) {
            int col = nj * 8 + (lane & 3) * 2;
            *(float2*)(obuf + rl * 66 + col) = make_float2(oacc[nj][0], oacc[nj][1]);
            *(float2*)(obuf + rh * 66 + col) = make_float2(oacc[nj][2], oacc[nj][3]);
        }
    }
    __syncthreads();

    if (wn == 0) {
        const int b = bh >> 3, h = bh & 7;
        float il = 1.0f / (l0 + lred[64 + rl]);
        float ih = 1.0f / (l1 + lred[64 + rh]);
#pragma unroll
        for (int nj = 0; nj < 8; nj++) {
            int col = nj * 8 + (lane & 3) * 2;
            float2 s0 = *(float2*)(obuf + rl * 66 + col);
            float2 s1 = *(float2*)(obuf + rh * 66 + col);
            size_t blo = ((size_t)b * 2048 + q0 + rl) * 512 + h * 64 + col;
            size_t bhi = ((size_t)b * 2048 + q0 + rh) * 512 + h * 64 + col;
            hf2 t;
            t.x = __float2half_rn((oacc[nj][0] + s0.x) * il);
            t.y = __float2half_rn((oacc[nj][1] + s0.y) * il);
            *(hf2*)(C + blo) = t;
            t.x = __float2half_rn((oacc[nj][2] + s1.x) * ih);
            t.y = __float2half_rn((oacc[nj][3] + s1.y) * ih);
            *(hf2*)(C + bhi) = t;
        }
    }
}

// ---------------------------------------------------------------------------
extern "C" void kernel_launch(void* const* d_in, const int* in_sizes, int n_in,
                              void* d_out, int out_size)
{
    const float* x  = (const float*)d_in[0];
    const float* Wq = (const float*)d_in[1];
    const float* Wk = (const float*)d_in[2];
    const float* Wv = (const float*)d_in[3];
    const float* Wo = (const float*)d_in[4];
    const float* bo = (const float*)d_in[5];
    float* out = (float*)d_out;

    hf *Xh, *Xl, *Qh, *Ql, *Kh, *Kl, *Vh, *Cp, *Whp, *Wlp;
    cudaGetSymbolAddress((void**)&Xh, g_Xh);  cudaGetSymbolAddress((void**)&Xl, g_Xl);
    cudaGetSymbolAddress((void**)&Qh, g_Qh);  cudaGetSymbolAddress((void**)&Ql, g_Ql);
    cudaGetSymbolAddress((void**)&Kh, g_Kh);  cudaGetSymbolAddress((void**)&Kl, g_Kl);
    cudaGetSymbolAddress((void**)&Vh, g_Vh);
    cudaGetSymbolAddress((void**)&Cp, g_C);
    cudaGetSymbolAddress((void**)&Whp, g_Wh); cudaGetSymbolAddress((void**)&Wlp, g_Wl);

    cudaFuncSetAttribute(gemm_mma<0>, cudaFuncAttributeMaxDynamicSharedMemorySize, G_SZ);
    cudaFuncSetAttribute(gemm_mma<2>, cudaFuncAttributeMaxDynamicSharedMemorySize, G_SZ);
    cudaFuncSetAttribute(attn_mma, cudaFuncAttributeMaxDynamicSharedMemorySize, ASZ);

    // prep
    prep_x<<<(BM_ * HD_ / 4) / 512, 512>>>((const float4*)x, Xh, Xl);
    dim3 wblk(32, 8), wgrd(16, 16, 4);
    prep_w4<<<wgrd, wblk>>>(Wq, Wk, Wv, Wo, Whp, Wlp);

    // fused QKV projections (24 = 3 weights x 8 n-tiles); V writes hi only
    gemm_mma<0><<<dim3(24, 128), 256, G_SZ>>>(Xh, Xl, Whp, Wlp,
                                              nullptr, nullptr,
                                              Qh, Ql, Kh, Kl, Vh);

    // attention: two-phase global-max, 64-row q-tiles, 2 CTAs/SM
    attn_mma<<<dim3(32, 64), 256, ASZ>>>(Qh, Ql, Kh, Kl, Vh, Cp);

    // output projection + bias (2-pass, C single fp16)
    gemm_mma<2><<<dim3(8, 128), 256, G_SZ>>>(Cp, nullptr, Whp + 3 * 262144, Wlp + 3 * 262144,
                                             bo, out, nullptr, nullptr,
                                             nullptr, nullptr, nullptr);
}

// round 14
// speedup vs baseline: 2.1365x; 1.0223x over previous
#include <cuda_runtime.h>
#include <cuda_fp16.h>
#include <stdint.h>
#include <math.h>

#define B_ 8
#define M_ 2048
#define HD_ 512
#define BM_ (B_*M_)
#define SCALE_ 22.62741699796952f   // reference divides by HEAD_DIM**-0.5

typedef __half hf;
typedef __half2 hf2;

// ---------------- device scratch (allocation-free rule) ----------------
__device__ __align__(16) hf g_Xh[(size_t)BM_*HD_], g_Xl[(size_t)BM_*HD_];
__device__ __align__(16) hf g_Qh[(size_t)BM_*HD_], g_Ql[(size_t)BM_*HD_];
__device__ __align__(16) hf g_Kh[(size_t)BM_*HD_], g_Kl[(size_t)BM_*HD_];
__device__ __align__(16) hf g_Vh[(size_t)BM_*HD_];
__device__ __align__(16) hf g_C [(size_t)BM_*HD_];
__device__ __align__(16) hf g_Wh[4][512*512], g_Wl[4][512*512];   // W^T: [n][k]

// ---------------- helpers ----------------
__device__ __forceinline__ uint32_t smem_u32(const void* p) {
    uint32_t a;
    asm("{ .reg .u64 t; cvta.to.shared.u64 t, %1; cvt.u32.u64 %0, t; }" : "=r"(a) : "l"(p));
    return a;
}
#define SWZ(x) ((uint32_t)(x) ^ ((((uint32_t)(x)) >> 3) & 0x70))

__device__ __forceinline__ void ldm4(uint32_t (&r)[4], uint32_t a) {
    asm volatile("ldmatrix.sync.aligned.m8n8.x4.shared.b16 {%0,%1,%2,%3}, [%4];"
                 : "=r"(r[0]), "=r"(r[1]), "=r"(r[2]), "=r"(r[3]) : "r"(a));
}
__device__ __forceinline__ void ldm4t(uint32_t (&r)[4], uint32_t a) {
    asm volatile("ldmatrix.sync.aligned.m8n8.x4.trans.shared.b16 {%0,%1,%2,%3}, [%4];"
                 : "=r"(r[0]), "=r"(r[1]), "=r"(r[2]), "=r"(r[3]) : "r"(a));
}
__device__ __forceinline__ void mma_hf(float (&d)[4], const uint32_t (&a)[4],
                                       uint32_t b0, uint32_t b1) {
    asm volatile("mma.sync.aligned.m16n8k16.row.col.f32.f16.f16.f32 "
                 "{%0,%1,%2,%3}, {%4,%5,%6,%7}, {%8,%9}, {%0,%1,%2,%3};"
                 : "+f"(d[0]), "+f"(d[1]), "+f"(d[2]), "+f"(d[3])
                 : "r"(a[0]), "r"(a[1]), "r"(a[2]), "r"(a[3]), "r"(b0), "r"(b1));
}
__device__ __forceinline__ void splith(float x, hf& h, hf& l) {
    h = __float2half_rn(x);
    l = __float2half_rn(x - __half2float(h));
}
__device__ __forceinline__ uint32_t packh(float a, float b) {
    hf2 t; t.x = __float2half_rn(a); t.y = __float2half_rn(b);
    return *(uint32_t*)&t;
}
__device__ __forceinline__ void cpa16(uint32_t dst, const void* src) {
    asm volatile("cp.async.cg.shared.global [%0], [%1], 16;" :: "r"(dst), "l"(src));
}
#define CP_COMMIT() asm volatile("cp.async.commit_group;" ::: "memory")
#define CP_WAIT0()  asm volatile("cp.async.wait_group 0;" ::: "memory")
#define CP_WAIT1()  asm volatile("cp.async.wait_group 1;" ::: "memory")

// ---------------- prep kernels ----------------
__global__ void __launch_bounds__(512) prep_x(const float4* __restrict__ x,
                                              hf* __restrict__ xh, hf* __restrict__ xl) {
    size_t i = (size_t)blockIdx.x * 512 + threadIdx.x;
    float4 v = x[i];
    hf h0, l0, h1, l1, h2, l2, h3, l3;
    splith(v.x, h0, l0); splith(v.y, h1, l1);
    splith(v.z, h2, l2); splith(v.w, h3, l3);
    hf2 a, b, c, d;
    a.x = h0; a.y = h1; b.x = h2; b.y = h3;
    c.x = l0; c.y = l1; d.x = l2; d.y = l3;
    *(hf2*)(xh + i * 4) = a; *(hf2*)(xh + i * 4 + 2) = b;
    *(hf2*)(xl + i * 4) = c; *(hf2*)(xl + i * 4 + 2) = d;
}

__global__ void __launch_bounds__(256) prep_w4(
    const float* __restrict__ W0, const float* __restrict__ W1,
    const float* __restrict__ W2, const float* __restrict__ W3,
    hf* __restrict__ th, hf* __restrict__ tl) {
    __shared__ float t[32][33];
    const int w = blockIdx.z;
    const float* W = (w == 0) ? W0 : (w == 1) ? W1 : (w == 2) ? W2 : W3;
    hf* thw = th + (size_t)w * 262144;
    hf* tlw = tl + (size_t)w * 262144;
    const int bx = blockIdx.x * 32;
    const int by = blockIdx.y * 32;
    const int tx = threadIdx.x, ty = threadIdx.y;
#pragma unroll
    for (int j = ty; j < 32; j += 8)
        t[j][tx] = W[(size_t)(by + j) * 512 + bx + tx];
    __syncthreads();
#pragma unroll
    for (int j = ty; j < 32; j += 8) {
        float v = t[tx][j];
        hf h, l; splith(v, h, l);
        thw[(size_t)(bx + j) * 512 + by + tx] = h;
        tlw[(size_t)(bx + j) * 512 + by + tx] = l;
    }
}

// ===========================================================================
// GEMM via mma.sync (fp16), cp.async double-buffered, 2 CTAs/SM.
// CTA tile 128m x 64n, K-chunks of 64. MODE 0 (QKV, 3-pass split): widx from
// blockIdx.x; Q/K write hi+lo, V writes hi only. MODE 2 (out-proj, 2-pass).
// ===========================================================================
#define GSTG 49152
#define G_AH(c) ((c)*GSTG + 0)
#define G_AL(c) ((c)*GSTG + 16384)
#define G_BH(c) ((c)*GSTG + 32768)
#define G_BL(c) ((c)*GSTG + 40960)
#define G_SZ    98304

template <int MODE>
__global__ void __launch_bounds__(256, 2) gemm_mma(
    const hf* __restrict__ Ah_, const hf* __restrict__ Al_,
    const hf* __restrict__ WhB, const hf* __restrict__ WlB,
    const float* __restrict__ bias, float* __restrict__ out32,
    hf* __restrict__ oh0, hf* __restrict__ ol0,
    hf* __restrict__ oh1, hf* __restrict__ ol1,
    hf* __restrict__ oh2)
{
    extern __shared__ char sm[];
    const uint32_t sb = smem_u32(sm);
    const int tid = threadIdx.x, warp = tid >> 5, lane = tid & 31;
    const int wm = warp >> 2, wn = warp & 3;
    const int lr = lane & 7, g = lane >> 3;
    const int offAr = (g & 1) * 8 + lr, offAc = (g >> 1) * 8;
    const int offBr = (g >> 1) * 8 + lr, offBc = (g & 1) * 8;

    const int widx = (MODE == 0) ? (blockIdx.x >> 3) : 0;
    const int n0 = (MODE == 0) ? ((blockIdx.x & 7) * 64) : (blockIdx.x * 64);
    const int m0 = blockIdx.y * 128;
    const hf* Bh_ = WhB + (size_t)widx * 262144;
    const hf* Bl_ = WlB + (size_t)widx * 262144;

#pragma unroll
    for (int i = 0; i < 4; i++) {
        int t = i * 256 + tid, row = t >> 3, cb = (t & 7) * 16;
        uint32_t dsw = SWZ(row * 128 + cb);
        size_t abyte = ((size_t)(m0 + row) * 512) * 2 + cb;
        cpa16(sb + G_AH(0) + dsw, (const char*)Ah_ + abyte);
        if (MODE != 2) cpa16(sb + G_AL(0) + dsw, (const char*)Al_ + abyte);
    }
#pragma unroll
    for (int i = 0; i < 2; i++) {
        int t = i * 256 + tid, row = t >> 3, cb = (t & 7) * 16;
        uint32_t dsw = SWZ(row * 128 + cb);
        size_t bbyte = ((size_t)(n0 + row) * 512) * 2 + cb;
        cpa16(sb + G_BH(0) + dsw, (const char*)Bh_ + bbyte);
        cpa16(sb + G_BL(0) + dsw, (const char*)Bl_ + bbyte);
    }
    CP_COMMIT();

    float acc[4][2][4];
#pragma unroll
    for (int a = 0; a < 4; a++)
#pragma unroll
        for (int b = 0; b < 2; b++)
#pragma unroll
            for (int c = 0; c < 4; c++) acc[a][b][c] = 0.0f;

    for (int ch = 0; ch < 8; ch++) {
        const int c = ch & 1;
        CP_WAIT0();
        __syncthreads();

        if (ch < 7) {
#pragma unroll
            for (int i = 0; i < 4; i++) {
                int t = i * 256 + tid, row = t >> 3, cb = (t & 7) * 16;
                uint32_t dsw = SWZ(row * 128 + cb);
                size_t abyte = ((size_t)(m0 + row) * 512 + (ch + 1) * 64) * 2 + cb;
                cpa16(sb + G_AH(c ^ 1) + dsw, (const char*)Ah_ + abyte);
                if (MODE != 2) cpa16(sb + G_AL(c ^ 1) + dsw, (const char*)Al_ + abyte);
            }
#pragma unroll
            for (int i = 0; i < 2; i++) {
                int t = i * 256 + tid, row = t >> 3, cb = (t & 7) * 16;
                uint32_t dsw = SWZ(row * 128 + cb);
                size_t bbyte = ((size_t)(n0 + row) * 512 + (ch + 1) * 64) * 2 + cb;
                cpa16(sb + G_BH(c ^ 1) + dsw, (const char*)Bh_ + bbyte);
                cpa16(sb + G_BL(c ^ 1) + dsw, (const char*)Bl_ + bbyte);
            }
            CP_COMMIT();
        }

#pragma unroll
        for (int ks = 0; ks < 4; ks++) {
            uint32_t bhF[4], blF[4];
            uint32_t boff = SWZ((wn * 16 + offBr) * 128 + (ks * 16 + offBc) * 2);
            ldm4(bhF, sb + G_BH(c) + boff);
            ldm4(blF, sb + G_BL(c) + boff);
#pragma unroll
            for (int mf = 0; mf < 4; mf++) {
                uint32_t aoff = SWZ((wm * 64 + mf * 16 + offAr) * 128 + (ks * 16 + offAc) * 2);
                uint32_t ah2[4];
                ldm4(ah2, sb + G_AH(c) + aoff);
                uint32_t al2[4];
                if (MODE != 2) ldm4(al2, sb + G_AL(c) + aoff);
#pragma unroll
                for (int nf = 0; nf < 2; nf++) {
                    uint32_t b0h = bhF[nf * 2], b1h = bhF[nf * 2 + 1];
                    uint32_t b0l = blF[nf * 2], b1l = blF[nf * 2 + 1];
                    mma_hf(acc[mf][nf], ah2, b0h, b1h);
                    mma_hf(acc[mf][nf], ah2, b0l, b1l);
                    if (MODE != 2) mma_hf(acc[mf][nf], al2, b0h, b1h);
                }
            }
        }
    }

    hf* oh = (MODE == 0) ? ((widx == 0) ? oh0 : (widx == 1) ? oh1 : oh2) : oh0;
    hf* ol = (MODE == 0) ? ((widx == 0) ? ol0 : ol1) : ol0;
    const bool wlo = (MODE == 0) && (widx != 2);

#pragma unroll
    for (int mf = 0; mf < 4; mf++) {
        int rlo = m0 + wm * 64 + mf * 16 + (lane >> 2);
        int rhi = rlo + 8;
#pragma unroll
        for (int nf = 0; nf < 2; nf++) {
            int n = n0 + wn * 16 + nf * 8 + (lane & 3) * 2;
            if (MODE == 2) {
                float2 v0, v1;
                v0.x = acc[mf][nf][0] + bias[n]; v0.y = acc[mf][nf][1] + bias[n + 1];
                v1.x = acc[mf][nf][2] + bias[n]; v1.y = acc[mf][nf][3] + bias[n + 1];
                *(float2*)(out32 + (size_t)rlo * 512 + n) = v0;
                *(float2*)(out32 + (size_t)rhi * 512 + n) = v1;
            } else {
                int h = n >> 6, d = n & 63;
                {
                    int b = rlo >> 11, mm = rlo & 2047;
                    size_t base = ((size_t)(b * 8 + h) * 2048 + mm) * 64 + d;
                    hf h0, l0, h1, l1;
                    splith(acc[mf][nf][0], h0, l0); splith(acc[mf][nf][1], h1, l1);
                    hf2 t, u; t.x = h0; t.y = h1; u.x = l0; u.y = l1;
                    *(hf2*)(oh + base) = t;
                    if (wlo) *(hf2*)(ol + base) = u;
                }
                {
                    int b = rhi >> 11, mm = rhi & 2047;
                    size_t base = ((size_t)(b * 8 + h) * 2048 + mm) * 64 + d;
                    hf h0, l0, h1, l1;
                    splith(acc[mf][nf][2], h0, l0); splith(acc[mf][nf][3], h1, l1);
                    hf2 t, u; t.x = h0; t.y = h1; u.x = l0; u.y = l1;
                    *(hf2*)(oh + base) = t;
                    if (wlo) *(hf2*)(ol + base) = u;
                }
            }
        }
    }
}

// ===========================================================================
// Two-phase flash attention, latency-optimized iteration skeleton.
// Phase A: 1-pass max scan, TWO 64-key tiles per iteration (16 iters),
//          3-stage cp.async pipeline (wait_group 1, one commit per iter).
// Phase B: selected tiles (>= mg-25), 3-pass S + fixed-shift exp + 1-pass PV,
//          3-stage pipeline. No online rescale. 2 CTAs/SM.
// ===========================================================================
#define AQH 0
#define AQL 8192
#define PA(s)  (16384 + (s)*16384)              // Phase A: 3 x 16KB (2 tiles)
#define PBK(s) (16384 + (s)*24576)              // Phase B: 3 x 24KB
#define PBL(s) (16384 + (s)*24576 + 8192)
#define PBV(s) (16384 + (s)*24576 + 16384)
#define AOB  16384                               // post-loop alias
#define ATM  90112                               // tilemax fp16 [2][64][32] = 8KB
#define AMG  98304                               // mgbuf [2][64] f32
#define AWMK 98816
#define ALST 98848
#define ALRD 99008
#define ASZ  99584

__global__ void __launch_bounds__(256, 2) attn_mma(
    const hf* __restrict__ Qh, const hf* __restrict__ Ql,
    const hf* __restrict__ Kh, const hf* __restrict__ Kl,
    const hf* __restrict__ Vh, hf* __restrict__ C)
{
    extern __shared__ char sm[];
    const uint32_t sb = smem_u32(sm);
    hf* tmax_s = (hf*)(sm + ATM);
    float* mgbuf  = (float*)(sm + AMG);
    uint32_t* wmaskA = (uint32_t*)(sm + AWMK);
    int* lst = (int*)(sm + ALST);
    float* lred = (float*)(sm + ALRD);
    float* obuf = (float*)(sm + AOB);

    const int tid = threadIdx.x, warp = tid >> 5, lane = tid & 31;
    const int wq = warp >> 1, wn = warp & 1;
    const int lr = lane & 7, g = lane >> 3;
    const int offAr = (g & 1) * 8 + lr, offAc = (g >> 1) * 8;
    const int offBr = (g >> 1) * 8 + lr, offBc = (g & 1) * 8;
    const int bh = blockIdx.y, q0 = blockIdx.x * 64;
    const int rl = wq * 16 + (lane >> 2), rh = rl + 8;

    const char* khb = (const char*)Kh + ((size_t)bh * 2048) * 128;
    const char* klb = (const char*)Kl + ((size_t)bh * 2048) * 128;
    const char* vhb = (const char*)Vh + ((size_t)bh * 2048) * 128;

    // Q tiles (hi/lo)
    {
        const char* qhp = (const char*)Qh + ((size_t)bh * 2048 + q0) * 128;
        const char* qlp = (const char*)Ql + ((size_t)bh * 2048 + q0) * 128;
#pragma unroll
        for (int i = 0; i < 2; i++) {
            int t = i * 256 + tid, row = t >> 3, cb = (t & 7) * 16;
            uint32_t dsw = SWZ(row * 128 + cb);
            *(uint4*)(sm + AQH + dsw) = *(const uint4*)(qhp + row * 128 + cb);
            *(uint4*)(sm + AQL + dsw) = *(const uint4*)(qlp + row * 128 + cb);
        }
    }

    // Phase A prologue: pair 0 -> stage 0, pair 1 -> stage 1 (one commit each)
#pragma unroll
    for (int s = 0; s < 2; s++) {
#pragma unroll
        for (int i = 0; i < 4; i++) {
            int t = i * 256 + tid, row = t >> 3, cb = (t & 7) * 16;
            uint32_t dsw = SWZ(row * 128 + cb);
            cpa16(sb + PA(s) + dsw, khb + (size_t)s * 16384 + (size_t)row * 128 + cb);
        }
        CP_COMMIT();
    }
    __syncthreads();   // Q visible

    uint32_t qfh[4][4];
#pragma unroll
    for (int ks = 0; ks < 4; ks++) {
        uint32_t aoff = SWZ((wq * 16 + offAr) * 128 + (ks * 16 + offAc) * 2);
        ldm4(qfh[ks], sb + AQH + aoff);
    }

    // ================= Phase A: max scan (pairs) =================
    float mrun0 = -INFINITY, mrun1 = -INFINITY;
    for (int k2 = 0; k2 < 16; k2++) {
        const int s = k2 % 3;
        CP_WAIT1();          // stage s (group k2) complete
        __syncthreads();     // all warps done with stage (k2+2)%3 from iter k2-1

        // one commit per iter: prefetch pair k2+2 or empty group
        if (k2 + 2 < 16) {
            const int sn = (k2 + 2) % 3;
#pragma unroll
            for (int i = 0; i < 4; i++) {
                int t = i * 256 + tid, row = t >> 3, cb = (t & 7) * 16;
                uint32_t dsw = SWZ(row * 128 + cb);
                cpa16(sb + PA(sn) + dsw,
                      khb + (size_t)(k2 + 2) * 16384 + (size_t)row * 128 + cb);
            }
        }
        CP_COMMIT();

#pragma unroll
        for (int sub = 0; sub < 2; sub++) {
            const uint32_t kbase = sb + PA(s) + sub * 8192;
            float sacc[4][4];
#pragma unroll
            for (int b = 0; b < 4; b++)
#pragma unroll
                for (int e = 0; e < 4; e++) sacc[b][e] = 0.0f;
#pragma unroll
            for (int ks = 0; ks < 4; ks++) {
                uint32_t kh2[2][4];
#pragma unroll
                for (int kg = 0; kg < 2; kg++) {
                    uint32_t boff = SWZ((wn * 32 + kg * 16 + offBr) * 128 + (ks * 16 + offBc) * 2);
                    ldm4(kh2[kg], kbase + boff);
                }
#pragma unroll
                for (int nf = 0; nf < 4; nf++) {
                    int kg = nf >> 1, hh = nf & 1;
                    mma_hf(sacc[nf], qfh[ks], kh2[kg][hh * 2], kh2[kg][hh * 2 + 1]);
                }
            }
            float t0 = -INFINITY, t1 = -INFINITY;
#pragma unroll
            for (int nf = 0; nf < 4; nf++) {
                t0 = fmaxf(t0, fmaxf(sacc[nf][0], sacc[nf][1]));
                t1 = fmaxf(t1, fmaxf(sacc[nf][2], sacc[nf][3]));
            }
            t0 *= SCALE_; t1 *= SCALE_;
            t0 = fmaxf(t0, __shfl_xor_sync(0xffffffffu, t0, 1));
            t0 = fmaxf(t0, __shfl_xor_sync(0xffffffffu, t0, 2));
            t1 = fmaxf(t1, __shfl_xor_sync(0xffffffffu, t1, 1));
            t1 = fmaxf(t1, __shfl_xor_sync(0xffffffffu, t1, 2));
            mrun0 = fmaxf(mrun0, t0); mrun1 = fmaxf(mrun1, t1);
            if ((lane & 3) == 0) {
                int kt = k2 * 2 + sub;
                tmax_s[(wn * 64 + rl) * 32 + kt] = __float2half_rn(t0);
                tmax_s[(wn * 64 + rh) * 32 + kt] = __float2half_rn(t1);
            }
        }
    }
    CP_WAIT0();
    __syncthreads();

    // merge global max across wn
    if ((lane & 3) == 0) {
        mgbuf[wn * 64 + rl] = mrun0;
        mgbuf[wn * 64 + rh] = mrun1;
    }
    __syncthreads();
    const float mg0 = fmaxf(mgbuf[rl], mgbuf[64 + rl]);
    const float mg1 = fmaxf(mgbuf[rh], mgbuf[64 + rh]);

    // keep mask per warp + CTA load list
    uint32_t kmask = 0;
    {
        const hf* tmw = tmax_s + wn * 64 * 32;
        for (int kt = 0; kt < 32; kt++) {
            bool f = (__half2float(tmw[rl * 32 + kt]) >= mg0 - 25.0f) ||
                     (__half2float(tmw[rh * 32 + kt]) >= mg1 - 25.0f);
            if (__ballot_sync(0xffffffffu, f)) kmask |= (1u << kt);
        }
        if (lane == 0) wmaskA[warp] = kmask;
    }
    __syncthreads();
    uint32_t loadmask = 0;
#pragma unroll
    for (int w = 0; w < 8; w++) loadmask |= wmaskA[w];
    if (tid == 0) {
        int cnt = 0;
        for (int kt = 0; kt < 32; kt++)
            if ((loadmask >> kt) & 1) lst[1 + cnt++] = kt;
        lst[0] = cnt;
    }
    __syncthreads();
    const int count = lst[0];   // >= 1 always (max tile is kept)

    // ================= Phase B prologue: stages 0,1 =================
#pragma unroll
    for (int s = 0; s < 2; s++) {
        if (s < count) {
            int kt0 = lst[1 + s];
#pragma unroll
            for (int i = 0; i < 2; i++) {
                int t = i * 256 + tid, row = t >> 3, cb = (t & 7) * 16;
                uint32_t dsw = SWZ(row * 128 + cb);
                size_t go = (size_t)kt0 * 8192 + (size_t)row * 128 + cb;
                cpa16(sb + PBK(s) + dsw, khb + go);
                cpa16(sb + PBL(s) + dsw, klb + go);
                cpa16(sb + PBV(s) + dsw, vhb + go);
            }
        }
        CP_COMMIT();
    }

    float oacc[8][4];
#pragma unroll
    for (int b = 0; b < 8; b++)
#pragma unroll
        for (int c = 0; c < 4; c++) oacc[b][c] = 0.0f;
    float l0 = 0.0f, l1 = 0.0f;

    for (int i = 0; i < count; i++) {
        const int kt = lst[1 + i];
        const int s = i % 3;
        CP_WAIT1();
        __syncthreads();

        if (i + 2 < count) {
            int ktn = lst[3 + i];
            const int sn = (i + 2) % 3;
#pragma unroll
            for (int j = 0; j < 2; j++) {
                int t = j * 256 + tid, row = t >> 3, cb = (t & 7) * 16;
                uint32_t dsw = SWZ(row * 128 + cb);
                size_t go = (size_t)ktn * 8192 + (size_t)row * 128 + cb;
                cpa16(sb + PBK(sn) + dsw, khb + go);
                cpa16(sb + PBL(sn) + dsw, klb + go);
                cpa16(sb + PBV(sn) + dsw, vhb + go);
            }
        }
        CP_COMMIT();

        if (!((kmask >> kt) & 1)) continue;

        // 3-pass S
        float sacc[4][4];
#pragma unroll
        for (int b = 0; b < 4; b++)
#pragma unroll
            for (int e = 0; e < 4; e++) sacc[b][e] = 0.0f;
#pragma unroll
        for (int ks = 0; ks < 4; ks++) {
            uint32_t kh2[2][4], kl2[2][4];
#pragma unroll
            for (int kg = 0; kg < 2; kg++) {
                uint32_t boff = SWZ((wn * 32 + kg * 16 + offBr) * 128 + (ks * 16 + offBc) * 2);
                ldm4(kh2[kg], sb + PBK(s) + boff);
                ldm4(kl2[kg], sb + PBL(s) + boff);
            }
            uint32_t aoff = SWZ((wq * 16 + offAr) * 128 + (ks * 16 + offAc) * 2);
            uint32_t ql2[4];
            ldm4(ql2, sb + AQL + aoff);
#pragma unroll
            for (int nf = 0; nf < 4; nf++) {
                int kg = nf >> 1, hh = nf & 1;
                mma_hf(sacc[nf], qfh[ks], kh2[kg][hh * 2], kh2[kg][hh * 2 + 1]);
                mma_hf(sacc[nf], qfh[ks], kl2[kg][hh * 2], kl2[kg][hh * 2 + 1]);
                mma_hf(sacc[nf], ql2,     kh2[kg][hh * 2], kh2[kg][hh * 2 + 1]);
            }
        }

        // exp with fixed global shift
        float slo = 0.0f, shi = 0.0f;
        float pv[4][4];
#pragma unroll
        for (int nf = 0; nf < 4; nf++) {
            pv[nf][0] = __expf(sacc[nf][0] * SCALE_ - mg0);
            pv[nf][1] = __expf(sacc[nf][1] * SCALE_ - mg0);
            pv[nf][2] = __expf(sacc[nf][2] * SCALE_ - mg1);
            pv[nf][3] = __expf(sacc[nf][3] * SCALE_ - mg1);
            slo += pv[nf][0] + pv[nf][1];
            shi += pv[nf][2] + pv[nf][3];
        }
        l0 += slo; l1 += shi;
        uint32_t pa[2][4];
#pragma unroll
        for (int k2 = 0; k2 < 2; k2++) {
            pa[k2][0] = packh(pv[2 * k2][0], pv[2 * k2][1]);
            pa[k2][1] = packh(pv[2 * k2][2], pv[2 * k2][3]);
            pa[k2][2] = packh(pv[2 * k2 + 1][0], pv[2 * k2 + 1][1]);
            pa[k2][3] = packh(pv[2 * k2 + 1][2], pv[2 * k2 + 1][3]);
        }
        // PV single-pass
#pragma unroll
        for (int k2 = 0; k2 < 2; k2++) {
            uint32_t vh[4][4];
#pragma unroll
            for (int j = 0; j < 4; j++) {
                uint32_t voff = SWZ((wn * 32 + k2 * 16 + offAr) * 128 + (j * 16 + offAc) * 2);
                ldm4t(vh[j], sb + PBV(s) + voff);
            }
#pragma unroll
            for (int j = 0; j < 4; j++) {
#pragma unroll
                for (int hh = 0; hh < 2; hh++) {
                    int nj = j * 2 + hh;
                    mma_hf(oacc[nj], pa[k2], vh[j][hh * 2], vh[j][hh * 2 + 1]);
                }
            }
        }
    }

    // ---- split-k merge (l only; m is global) ----
    CP_WAIT0();
    __syncthreads();
    {
        float a = l0, b = l1;
        a += __shfl_xor_sync(0xffffffffu, a, 1);
        a += __shfl_xor_sync(0xffffffffu, a, 2);
        b += __shfl_xor_sync(0xffffffffu, b, 1);
        b += __shfl_xor_sync(0xffffffffu, b, 2);
        l0 = a; l1 = b;
        if ((lane & 3) == 0) {
            lred[wn * 64 + rl] = a;
            lred[wn * 64 + rh] = b;
        }
    }
    if (wn == 1) {
#pragma unroll
        for (int nj = 0; nj < 8; nj++) {
            int col = nj * 8 + (lane & 3) * 2;
            *(float2*)(obuf + rl * 66 + col) = make_float2(oacc[nj][0], oacc[nj][1]);
            *(float2*)(obuf + rh * 66 + col) = make_float2(oacc[nj][2], oacc[nj][3]);
        }
    }
    __syncthreads();

    if (wn == 0) {
        const int b = bh >> 3, h = bh & 7;
        float il = 1.0f / (l0 + lred[64 + rl]);
        float ih = 1.0f / (l1 + lred[64 + rh]);
#pragma unroll
        for (int nj = 0; nj < 8; nj++) {
            int col = nj * 8 + (lane & 3) * 2;
            float2 s0 = *(float2*)(obuf + rl * 66 + col);
            float2 s1 = *(float2*)(obuf + rh * 66 + col);
            size_t blo = ((size_t)b * 2048 + q0 + rl) * 512 + h * 64 + col;
            size_t bhi = ((size_t)b * 2048 + q0 + rh) * 512 + h * 64 + col;
            hf2 t;
            t.x = __float2half_rn((oacc[nj][0] + s0.x) * il);
            t.y = __float2half_rn((oacc[nj][1] + s0.y) * il);
            *(hf2*)(C + blo) = t;
            t.x = __float2half_rn((oacc[nj][2] + s1.x) * ih);
            t.y = __float2half_rn((oacc[nj][3] + s1.y) * ih);
            *(hf2*)(C + bhi) = t;
        }
    }
}

// ---------------------------------------------------------------------------
extern "C" void kernel_launch(void* const* d_in, const int* in_sizes, int n_in,
                              void* d_out, int out_size)
{
    const float* x  = (const float*)d_in[0];
    const float* Wq = (const float*)d_in[1];
    const float* Wk = (const float*)d_in[2];
    const float* Wv = (const float*)d_in[3];
    const float* Wo = (const float*)d_in[4];
    const float* bo = (const float*)d_in[5];
    float* out = (float*)d_out;

    hf *Xh, *Xl, *Qh, *Ql, *Kh, *Kl, *Vh, *Cp, *Whp, *Wlp;
    cudaGetSymbolAddress((void**)&Xh, g_Xh);  cudaGetSymbolAddress((void**)&Xl, g_Xl);
    cudaGetSymbolAddress((void**)&Qh, g_Qh);  cudaGetSymbolAddress((void**)&Ql, g_Ql);
    cudaGetSymbolAddress((void**)&Kh, g_Kh);  cudaGetSymbolAddress((void**)&Kl, g_Kl);
    cudaGetSymbolAddress((void**)&Vh, g_Vh);
    cudaGetSymbolAddress((void**)&Cp, g_C);
    cudaGetSymbolAddress((void**)&Whp, g_Wh); cudaGetSymbolAddress((void**)&Wlp, g_Wl);

    cudaFuncSetAttribute(gemm_mma<0>, cudaFuncAttributeMaxDynamicSharedMemorySize, G_SZ);
    cudaFuncSetAttribute(gemm_mma<2>, cudaFuncAttributeMaxDynamicSharedMemorySize, G_SZ);
    cudaFuncSetAttribute(attn_mma, cudaFuncAttributeMaxDynamicSharedMemorySize, ASZ);

    // prep
    prep_x<<<(BM_ * HD_ / 4) / 512, 512>>>((const float4*)x, Xh, Xl);
    dim3 wblk(32, 8), wgrd(16, 16, 4);
    prep_w4<<<wgrd, wblk>>>(Wq, Wk, Wv, Wo, Whp, Wlp);

    // fused QKV projections (24 = 3 weights x 8 n-tiles); V writes hi only
    gemm_mma<0><<<dim3(24, 128), 256, G_SZ>>>(Xh, Xl, Whp, Wlp,
                                              nullptr, nullptr,
                                              Qh, Ql, Kh, Kl, Vh);

    // attention: two-phase global-max, latency-optimized, 2 CTAs/SM
    attn_mma<<<dim3(32, 64), 256, ASZ>>>(Qh, Ql, Kh, Kl, Vh, Cp);

    // output projection + bias (2-pass, C single fp16)
    gemm_mma<2><<<dim3(8, 128), 256, G_SZ>>>(Cp, nullptr, Whp + 3 * 262144, Wlp + 3 * 262144,
                                             bo, out, nullptr, nullptr,
                                             nullptr, nullptr, nullptr);
}